// round 1
// baseline (speedup 1.0000x reference)
#include <cuda_runtime.h>

// ---------------- problem constants ----------------
constexpr int Cdim = 768;
constexpr int Bn   = 8;
constexpr int Nn   = 1024;
constexpr int Hn   = 4;
constexpr int HDn  = 192;            // head dim
constexpr int Sn   = Bn * Nn;        // 8192 rows
constexpr int BHn  = Bn * Hn;        // 32
constexpr int CEN  = 20;
constexpr float EPSv = 1e-5f;

// ---------------- scratch (device globals; no allocation allowed) ----------------
__device__ float g_h   [Sn * Cdim];
__device__ float g_qkv [Sn * 3 * Cdim];
__device__ float g_Qg  [BHn * Nn * HDn];
__device__ float g_Kg  [BHn * Nn * HDn];
__device__ float g_Vg  [BHn * Nn * HDn];
__device__ float g_QM  [BHn * Nn * HDn];
__device__ float g_KM  [BHn * Nn * HDn];
__device__ float g_MT  [HDn * HDn];
__device__ float g_kb  [BHn * Nn];
__device__ float g_y   [Sn * Cdim];
__device__ float g_x1  [Sn * Cdim];
__device__ float g_h2  [Sn * Cdim];
__device__ float g_rbf [Sn * CEN];

// ---------------- helpers ----------------
__device__ __forceinline__ float warpsum32(float v) {
#pragma unroll
    for (int o = 16; o >= 1; o >>= 1) v += __shfl_xor_sync(0xffffffffu, v, o);
    return v;
}
__device__ __forceinline__ float grpsum16(float v) {
#pragma unroll
    for (int o = 8; o >= 1; o >>= 1) v += __shfl_xor_sync(0xffffffffu, v, o);
    return v;
}
__device__ __forceinline__ float grpmax16(float v) {
#pragma unroll
    for (int o = 8; o >= 1; o >>= 1) v = fmaxf(v, __shfl_xor_sync(0xffffffffu, v, o));
    return v;
}

// ---------------- LayerNorm: one block per row ----------------
__global__ __launch_bounds__(256) void ln_kernel(
    const float* __restrict__ x, const float* __restrict__ w,
    const float* __restrict__ b, float* __restrict__ out)
{
    const int row = blockIdx.x;
    const float* xr = x + (size_t)row * Cdim;
    float s = 0.f, s2 = 0.f;
    for (int i = threadIdx.x; i < Cdim; i += 256) {
        float v = xr[i];
        s += v; s2 += v * v;
    }
    s = warpsum32(s); s2 = warpsum32(s2);
    __shared__ float sh[16];
    const int wid = threadIdx.x >> 5, lane = threadIdx.x & 31;
    if (lane == 0) { sh[wid] = s; sh[8 + wid] = s2; }
    __syncthreads();
    if (threadIdx.x == 0) {
        float a = 0.f, c = 0.f;
#pragma unroll
        for (int i = 0; i < 8; i++) { a += sh[i]; c += sh[8 + i]; }
        sh[0] = a; sh[8] = c;
    }
    __syncthreads();
    const float mu  = sh[0] * (1.0f / Cdim);
    const float var = sh[8] * (1.0f / Cdim) - mu * mu;
    const float rs  = rsqrtf(var + EPSv);
    for (int i = threadIdx.x; i < Cdim; i += 256)
        out[(size_t)row * Cdim + i] = (xr[i] - mu) * rs * w[i] + b[i];
}

// ---------------- generic NT GEMM: C[M,N] = A[M,K] * B[N,K]^T (+bias +resid) ----
// M%64==0, N%64==0, K%16==0 required.
__global__ __launch_bounds__(256) void gemm_nt_kernel(
    const float* __restrict__ A, const float* __restrict__ B, float* __restrict__ Cc,
    int Md, int Nd, int Kd,
    const float* __restrict__ bias, const float* __restrict__ resid)
{
    __shared__ __align__(16) float As[16][64];
    __shared__ __align__(16) float Bs[16][64];
    const int t  = threadIdx.x;
    const int ty = t >> 4, tx = t & 15;
    const int m0 = blockIdx.y << 6;
    const int n0 = blockIdx.x << 6;
    const int lr = t >> 2;
    const int lk = (t & 3) << 2;
    const float* Ap = A + (size_t)(m0 + lr) * Kd + lk;
    const float* Bp = B + (size_t)(n0 + lr) * Kd + lk;
    float acc[4][4];
#pragma unroll
    for (int i = 0; i < 4; i++)
#pragma unroll
        for (int j = 0; j < 4; j++) acc[i][j] = 0.f;

    for (int k0 = 0; k0 < Kd; k0 += 16) {
        float4 a4 = *(const float4*)(Ap + k0);
        float4 b4 = *(const float4*)(Bp + k0);
        As[lk + 0][lr] = a4.x; As[lk + 1][lr] = a4.y; As[lk + 2][lr] = a4.z; As[lk + 3][lr] = a4.w;
        Bs[lk + 0][lr] = b4.x; Bs[lk + 1][lr] = b4.y; Bs[lk + 2][lr] = b4.z; Bs[lk + 3][lr] = b4.w;
        __syncthreads();
#pragma unroll
        for (int k = 0; k < 16; k++) {
            float4 av = *(const float4*)&As[k][ty << 2];
            float4 bv = *(const float4*)&Bs[k][tx << 2];
            float a[4] = {av.x, av.y, av.z, av.w};
            float b2[4] = {bv.x, bv.y, bv.z, bv.w};
#pragma unroll
            for (int i = 0; i < 4; i++)
#pragma unroll
                for (int j = 0; j < 4; j++) acc[i][j] += a[i] * b2[j];
        }
        __syncthreads();
    }
#pragma unroll
    for (int i = 0; i < 4; i++) {
        const int m = m0 + (ty << 2) + i;
#pragma unroll
        for (int j = 0; j < 4; j++) {
            const int n = n0 + (tx << 2) + j;
            float v = acc[i][j];
            if (bias)  v += bias[n];
            const size_t idx = (size_t)m * Nd + n;
            if (resid) v += resid[idx];
            Cc[idx] = v;
        }
    }
}

// ---------------- gather qkv -> Q,K,V in [BH, N, HD] layout ----------------
__global__ __launch_bounds__(256) void gather_qkv_kernel(
    const float* __restrict__ qkv, float* __restrict__ Qg,
    float* __restrict__ Kg, float* __restrict__ Vg)
{
    const int i = blockIdx.x * 256 + threadIdx.x;
    if (i >= BHn * Nn * HDn) return;
    const int d  = i % HDn;
    const int r  = i / HDn;
    const int n  = r % Nn;
    const int bh = r / Nn;
    const int b  = bh >> 2, h = bh & 3;
    const size_t src = (size_t)(b * Nn + n) * (3 * Cdim) + h * HDn + d;
    Qg[i] = qkv[src];
    Kg[i] = qkv[src + Cdim];
    Vg[i] = qkv[src + 2 * Cdim];
}

// ---------------- transpose M (192x192) ----------------
__global__ __launch_bounds__(256) void transpose_m_kernel(
    const float* __restrict__ M, float* __restrict__ MT)
{
    const int i = blockIdx.x * 256 + threadIdx.x;
    if (i >= HDn * HDn) return;
    const int r = i / HDn, c = i % HDn;
    MT[c * HDn + r] = M[r * HDn + c];
}

// ---------------- per-key bias: kb[r] = -scale * dot(K[r], KM[r]) ----------------
__global__ __launch_bounds__(256) void kbias_kernel(
    const float* __restrict__ Kg, const float* __restrict__ KM,
    const float* __restrict__ scale_p, float* __restrict__ kb)
{
    const int gw = (blockIdx.x * 256 + threadIdx.x) >> 5;
    const int lane = threadIdx.x & 31;
    if (gw >= BHn * Nn) return;
    const float* kr  = Kg + (size_t)gw * HDn;
    const float* kmr = KM + (size_t)gw * HDn;
    float s = 0.f;
#pragma unroll
    for (int i = lane; i < HDn; i += 32) s += kr[i] * kmr[i];
    s = warpsum32(s);
    if (lane == 0) kb[gw] = -scale_p[0] * s;
}

// ---------------- fused flash attention ----------------
// logits S_ij = 2*scale*(qM_i . k_j) + kb_j   (qMq term cancels in softmax)
constexpr int ATT_SMEM_BYTES = (3 * 64 * HDn + 64 * 64 + 64) * 4;  // 164096

__global__ __launch_bounds__(256) void attn_kernel(
    const float* __restrict__ QM, const float* __restrict__ Kg,
    const float* __restrict__ Vg, const float* __restrict__ kbias,
    const float* __restrict__ scale_p, float* __restrict__ y)
{
    extern __shared__ __align__(16) float sm[];
    float* qs = sm;
    float* ks = sm + 64 * HDn;
    float* vs = sm + 2 * 64 * HDn;
    float* ps = sm + 3 * 64 * HDn;
    float* kb = ps + 64 * 64;

    const int bh = blockIdx.x;     // 0..31
    const int qt = blockIdx.y;     // 0..15
    const int b  = bh >> 2, h = bh & 3;
    const int t  = threadIdx.x;
    const int ty = t >> 4, tx = t & 15;
    const float twoscale = 2.0f * scale_p[0];

    {   // load q-tile (qM rows) once
        const float4* qbase = (const float4*)(QM + ((size_t)bh * Nn + qt * 64) * HDn);
        for (int i = t; i < 64 * HDn / 4; i += 256) ((float4*)qs)[i] = qbase[i];
    }

    float O[4][12];
#pragma unroll
    for (int i = 0; i < 4; i++)
#pragma unroll
        for (int c = 0; c < 12; c++) O[i][c] = 0.f;
    float mrow[4], lrow[4];
#pragma unroll
    for (int i = 0; i < 4; i++) { mrow[i] = -1e30f; lrow[i] = 0.f; }

    for (int kt = 0; kt < Nn / 64; kt++) {
        __syncthreads();   // protect ks/vs/ps from previous iteration's readers
        {
            const float4* kbase = (const float4*)(Kg + ((size_t)bh * Nn + kt * 64) * HDn);
            const float4* vbase = (const float4*)(Vg + ((size_t)bh * Nn + kt * 64) * HDn);
            for (int i = t; i < 64 * HDn / 4; i += 256) {
                ((float4*)ks)[i] = kbase[i];
                ((float4*)vs)[i] = vbase[i];
            }
            if (t < 64) kb[t] = kbias[bh * Nn + kt * 64 + t];
        }
        __syncthreads();

        // ---- scores: S[4][4] = qM_tile @ k_tile^T ----
        float s[4][4];
#pragma unroll
        for (int i = 0; i < 4; i++)
#pragma unroll
            for (int j = 0; j < 4; j++) s[i][j] = 0.f;

#pragma unroll 4
        for (int k4 = 0; k4 < HDn / 4; k4++) {
            float4 qa[4], ka[4];
#pragma unroll
            for (int i = 0; i < 4; i++)
                qa[i] = *(const float4*)&qs[(ty * 4 + i) * HDn + k4 * 4];
#pragma unroll
            for (int j = 0; j < 4; j++)
                ka[j] = *(const float4*)&ks[(tx * 4 + j) * HDn + k4 * 4];
#pragma unroll
            for (int i = 0; i < 4; i++)
#pragma unroll
                for (int j = 0; j < 4; j++)
                    s[i][j] += qa[i].x * ka[j].x + qa[i].y * ka[j].y
                             + qa[i].z * ka[j].z + qa[i].w * ka[j].w;
        }
        float kbj[4];
#pragma unroll
        for (int j = 0; j < 4; j++) kbj[j] = kb[tx * 4 + j];
#pragma unroll
        for (int i = 0; i < 4; i++)
#pragma unroll
            for (int j = 0; j < 4; j++) s[i][j] = twoscale * s[i][j] + kbj[j];

        // ---- online softmax ----
#pragma unroll
        for (int i = 0; i < 4; i++) {
            float mx = fmaxf(fmaxf(s[i][0], s[i][1]), fmaxf(s[i][2], s[i][3]));
            mx = grpmax16(mx);
            const float mnew = fmaxf(mrow[i], mx);
            const float corr = __expf(mrow[i] - mnew);
            mrow[i] = mnew;
            float rs = 0.f;
#pragma unroll
            for (int j = 0; j < 4; j++) {
                const float p = __expf(s[i][j] - mnew);
                s[i][j] = p;
                rs += p;
            }
            rs = grpsum16(rs);
            lrow[i] = lrow[i] * corr + rs;
#pragma unroll
            for (int c = 0; c < 12; c++) O[i][c] *= corr;
#pragma unroll
            for (int j = 0; j < 4; j++) ps[(ty * 4 + i) * 64 + tx * 4 + j] = s[i][j];
        }
        __syncthreads();

        // ---- O += P @ V ----
#pragma unroll 4
        for (int j = 0; j < 64; j++) {
            float p[4];
#pragma unroll
            for (int i = 0; i < 4; i++) p[i] = ps[(ty * 4 + i) * 64 + j];
            const float* vrow = &vs[j * HDn + tx * 12];
            float4 v0 = *(const float4*)(vrow);
            float4 v1 = *(const float4*)(vrow + 4);
            float4 v2 = *(const float4*)(vrow + 8);
            float vv[12] = {v0.x, v0.y, v0.z, v0.w, v1.x, v1.y, v1.z, v1.w,
                            v2.x, v2.y, v2.z, v2.w};
#pragma unroll
            for (int i = 0; i < 4; i++)
#pragma unroll
                for (int c = 0; c < 12; c++) O[i][c] += p[i] * vv[c];
        }
    }

    // ---- normalize + write y in [B,N,C] layout ----
#pragma unroll
    for (int i = 0; i < 4; i++) {
        const float inv = 1.0f / lrow[i];
        const int n = qt * 64 + ty * 4 + i;
        float* yr = y + (size_t)(b * Nn + n) * Cdim + h * HDn + tx * 12;
#pragma unroll
        for (int c = 0; c < 12; c++) yr[c] = O[i][c] * inv;
    }
}

// ---------------- RBF features ----------------
constexpr int RBF_SMEM_BYTES = (CEN * Cdim + CEN) * 4;  // 61520

__global__ __launch_bounds__(256) void rbf_kernel(
    const float* __restrict__ h2, const float* __restrict__ centers,
    const float* __restrict__ beta, float* __restrict__ rbf)
{
    extern __shared__ __align__(16) float rsm[];
    float* cs = rsm;                 // [CEN*Cdim]
    float* cn = rsm + CEN * Cdim;    // [CEN]
    const int t = threadIdx.x;
    for (int i = t; i < CEN * Cdim; i += 256) cs[i] = centers[i];
    __syncthreads();
    if (t < CEN) {
        float s = 0.f;
        for (int k = 0; k < Cdim; k++) s += cs[t * Cdim + k] * cs[t * Cdim + k];
        cn[t] = s;
    }
    __syncthreads();
    const int wid = t >> 5, lane = t & 31;
    for (int rr = 0; rr < 8; rr++) {
        const int row = blockIdx.x * 64 + wid * 8 + rr;
        const float* xr = h2 + (size_t)row * Cdim;
        float xv[24];
#pragma unroll
        for (int i = 0; i < 24; i++) xv[i] = xr[lane + i * 32];
        float a = 0.f;
#pragma unroll
        for (int i = 0; i < 24; i++) a += xv[i] * xv[i];
        a = warpsum32(a);
        for (int j = 0; j < CEN; j++) {
            float d = 0.f;
#pragma unroll
            for (int i = 0; i < 24; i++) d += xv[i] * cs[j * Cdim + lane + i * 32];
            d = warpsum32(d);
            if (lane == 0)
                rbf[(size_t)row * CEN + j] = __expf(-beta[j] * (a - 2.0f * d + cn[j]));
        }
    }
}

// ---------------- final: out = x1 + rbf @ fc_w^T ----------------
__global__ __launch_bounds__(256) void final_kernel(
    const float* __restrict__ x1, const float* __restrict__ rbf,
    const float* __restrict__ fcw, float* __restrict__ out)
{
    const int i = blockIdx.x * 256 + threadIdx.x;
    if (i >= Sn * Cdim) return;
    const int c = i % Cdim;
    const int r = i / Cdim;
    const float* rb = rbf + (size_t)r * CEN;
    const float* fw = fcw + (size_t)c * CEN;
    float acc = x1[i];
#pragma unroll
    for (int j = 0; j < CEN; j++) acc += rb[j] * fw[j];
    out[i] = acc;
}

// ---------------- launcher ----------------
extern "C" void kernel_launch(void* const* d_in, const int* in_sizes, int n_in,
                              void* d_out, int out_size)
{
    (void)in_sizes; (void)n_in; (void)out_size;
    const float* x     = (const float*)d_in[0];
    const float* n1w   = (const float*)d_in[1];
    const float* n1b   = (const float*)d_in[2];
    const float* qkvw  = (const float*)d_in[3];
    const float* Mmat  = (const float*)d_in[4];
    const float* scale = (const float*)d_in[5];
    const float* projw = (const float*)d_in[6];
    const float* projb = (const float*)d_in[7];
    const float* n2w   = (const float*)d_in[8];
    const float* n2b   = (const float*)d_in[9];
    const float* cent  = (const float*)d_in[10];
    const float* beta  = (const float*)d_in[11];
    const float* fcw   = (const float*)d_in[12];
    float* out = (float*)d_out;

    float *hP, *qkvP, *QgP, *KgP, *VgP, *QMP, *KMP, *MTP, *kbP, *yP, *x1P, *h2P, *rbfP;
    cudaGetSymbolAddress((void**)&hP,   g_h);
    cudaGetSymbolAddress((void**)&qkvP, g_qkv);
    cudaGetSymbolAddress((void**)&QgP,  g_Qg);
    cudaGetSymbolAddress((void**)&KgP,  g_Kg);
    cudaGetSymbolAddress((void**)&VgP,  g_Vg);
    cudaGetSymbolAddress((void**)&QMP,  g_QM);
    cudaGetSymbolAddress((void**)&KMP,  g_KM);
    cudaGetSymbolAddress((void**)&MTP,  g_MT);
    cudaGetSymbolAddress((void**)&kbP,  g_kb);
    cudaGetSymbolAddress((void**)&yP,   g_y);
    cudaGetSymbolAddress((void**)&x1P,  g_x1);
    cudaGetSymbolAddress((void**)&h2P,  g_h2);
    cudaGetSymbolAddress((void**)&rbfP, g_rbf);

    cudaFuncSetAttribute(attn_kernel, cudaFuncAttributeMaxDynamicSharedMemorySize, ATT_SMEM_BYTES);
    cudaFuncSetAttribute(rbf_kernel,  cudaFuncAttributeMaxDynamicSharedMemorySize, RBF_SMEM_BYTES);

    // 1) LN1
    ln_kernel<<<Sn, 256>>>(x, n1w, n1b, hP);
    // 2) qkv = h @ qkv_w^T   [8192 x 2304]
    gemm_nt_kernel<<<dim3(3 * Cdim / 64, Sn / 64), 256>>>(hP, qkvw, qkvP,
                                                          Sn, 3 * Cdim, Cdim, nullptr, nullptr);
    // 3) gather into [BH,N,HD]
    gather_qkv_kernel<<<(BHn * Nn * HDn + 255) / 256, 256>>>(qkvP, QgP, KgP, VgP);
    // 4) M^T
    transpose_m_kernel<<<(HDn * HDn + 255) / 256, 256>>>(Mmat, MTP);
    // 5) qM = Q @ M, kM = K @ M  (NT gemm against M^T)
    gemm_nt_kernel<<<dim3(HDn / 64, BHn * Nn / 64), 256>>>(QgP, MTP, QMP,
                                                           BHn * Nn, HDn, HDn, nullptr, nullptr);
    gemm_nt_kernel<<<dim3(HDn / 64, BHn * Nn / 64), 256>>>(KgP, MTP, KMP,
                                                           BHn * Nn, HDn, HDn, nullptr, nullptr);
    // 6) per-key bias
    kbias_kernel<<<(BHn * Nn) * 32 / 256, 256>>>(KgP, KMP, scale, kbP);
    // 7) flash attention -> y [B,N,C]
    attn_kernel<<<dim3(BHn, Nn / 64), 256, ATT_SMEM_BYTES>>>(QMP, KgP, VgP, kbP, scale, yP);
    // 8) x1 = x + y @ proj_w^T + proj_b
    gemm_nt_kernel<<<dim3(Cdim / 64, Sn / 64), 256>>>(yP, projw, x1P,
                                                      Sn, Cdim, Cdim, projb, x);
    // 9) LN2
    ln_kernel<<<Sn, 256>>>(x1P, n2w, n2b, h2P);
    // 10) RBF features
    rbf_kernel<<<Sn / 64, 256, RBF_SMEM_BYTES>>>(h2P, cent, beta, rbfP);
    // 11) out = x1 + rbf @ fc_w^T
    final_kernel<<<(Sn * Cdim + 255) / 256, 256>>>(x1P, rbfP, fcw, out);
}

// round 2
// speedup vs baseline: 2.3986x; 2.3986x over previous
#include <cuda_runtime.h>
#include <cstdint>

// ---------------- problem constants ----------------
constexpr int Cdim = 768;
constexpr int Bn   = 8;
constexpr int Nn   = 1024;
constexpr int HDn  = 192;            // head dim
constexpr int Sn   = Bn * Nn;        // 8192 rows
constexpr int BHn  = Bn * 4;         // 32
constexpr int CEN  = 20;
constexpr float EPSv = 1e-5f;

// ---------------- scratch (device globals; no allocation allowed) ----------------
__device__ float g_h   [Sn * Cdim];
__device__ float g_qkv [Sn * 3 * Cdim];
__device__ float g_Qg  [BHn * Nn * HDn];
__device__ float g_Kg  [BHn * Nn * HDn];
__device__ float g_Vg  [BHn * Nn * HDn];
__device__ float g_QM  [BHn * Nn * HDn];
__device__ float g_KM  [BHn * Nn * HDn];
__device__ float g_MT  [HDn * HDn];
__device__ float g_kb  [BHn * Nn];
__device__ float g_y   [Sn * Cdim];
__device__ float g_x1  [Sn * Cdim];
__device__ float g_h2  [Sn * Cdim];
__device__ float g_rbf [Sn * CEN];

// ---------------- helpers ----------------
__device__ __forceinline__ float warpsum32(float v) {
#pragma unroll
    for (int o = 16; o >= 1; o >>= 1) v += __shfl_xor_sync(0xffffffffu, v, o);
    return v;
}
__device__ __forceinline__ uint32_t f2tf(float f) {
    uint32_t u;
    asm("cvt.rna.tf32.f32 %0, %1;" : "=r"(u) : "f"(f));
    return u;
}
__device__ __forceinline__ void mma8(float* c,
    uint32_t a0, uint32_t a1, uint32_t a2, uint32_t a3, uint32_t b0, uint32_t b1)
{
    asm volatile("mma.sync.aligned.m16n8k8.row.col.f32.tf32.tf32.f32 "
        "{%0,%1,%2,%3}, {%4,%5,%6,%7}, {%8,%9}, {%0,%1,%2,%3};"
        : "+f"(c[0]), "+f"(c[1]), "+f"(c[2]), "+f"(c[3])
        : "r"(a0), "r"(a1), "r"(a2), "r"(a3), "r"(b0), "r"(b1));
}

// ---------------- LayerNorm: one block per row ----------------
__global__ __launch_bounds__(256) void ln_kernel(
    const float* __restrict__ x, const float* __restrict__ w,
    const float* __restrict__ b, float* __restrict__ out)
{
    const int row = blockIdx.x;
    const float* xr = x + (size_t)row * Cdim;
    float s = 0.f, s2 = 0.f;
    for (int i = threadIdx.x; i < Cdim; i += 256) {
        float v = xr[i];
        s += v; s2 += v * v;
    }
    s = warpsum32(s); s2 = warpsum32(s2);
    __shared__ float sh[16];
    const int wid = threadIdx.x >> 5, lane = threadIdx.x & 31;
    if (lane == 0) { sh[wid] = s; sh[8 + wid] = s2; }
    __syncthreads();
    if (threadIdx.x == 0) {
        float a = 0.f, c = 0.f;
#pragma unroll
        for (int i = 0; i < 8; i++) { a += sh[i]; c += sh[8 + i]; }
        sh[0] = a; sh[8] = c;
    }
    __syncthreads();
    const float mu  = sh[0] * (1.0f / Cdim);
    const float var = sh[8] * (1.0f / Cdim) - mu * mu;
    const float rs  = rsqrtf(var + EPSv);
    for (int i = threadIdx.x; i < Cdim; i += 256)
        out[(size_t)row * Cdim + i] = (xr[i] - mu) * rs * w[i] + b[i];
}

// ---------------- tf32 3-split NT GEMM: C[M,N] = A[M,K] * B[N,K]^T ----------------
// fp32-equivalent precision via (ah+al) decomposition. M%128==0, N%BN==0, K%32==0.
template<int BN>
__global__ __launch_bounds__(256) void gemm_tf32x3_nt(
    const float* __restrict__ A, const float* __restrict__ B, float* __restrict__ Cc,
    int Md, int Nd, int Kd,
    const float* __restrict__ bias, const float* __restrict__ resid)
{
    constexpr int BM = 128, BK = 32, LDS = BK + 4;   // pad -> conflict-free frag reads
    constexpr int WM = (BN == 128) ? 2 : 4;
    constexpr int WN = 8 / WM;
    constexpr int WTM = BM / WM, WTN = BN / WN;
    constexpr int MT = WTM / 16, NT = WTN / 8;
    __shared__ float As[BM * LDS];
    __shared__ float Bs[BN * LDS];

    const int t = threadIdx.x;
    const int wid = t >> 5, lane = t & 31;
    const int wm = wid % WM, wn = wid / WM;
    const int lr4 = lane >> 2, lc4 = lane & 3;
    const int m0 = blockIdx.y * BM, n0 = blockIdx.x * BN;
    const int lrow = t >> 3;            // 0..31
    const int lcol = (t & 7) << 2;      // 0,4,...,28

    float acc[MT][NT][4];
#pragma unroll
    for (int i = 0; i < MT; i++)
#pragma unroll
        for (int j = 0; j < NT; j++)
#pragma unroll
            for (int q = 0; q < 4; q++) acc[i][j][q] = 0.f;

    for (int k0 = 0; k0 < Kd; k0 += BK) {
        __syncthreads();
#pragma unroll
        for (int p = 0; p < 4; p++) {
            const int r = lrow + p * 32;
            float4 v = *(const float4*)(A + (size_t)(m0 + r) * Kd + k0 + lcol);
            *(float4*)&As[r * LDS + lcol] = v;
        }
#pragma unroll
        for (int p = 0; p < BN / 32; p++) {
            const int r = lrow + p * 32;
            float4 v = *(const float4*)(B + (size_t)(n0 + r) * Kd + k0 + lcol);
            *(float4*)&Bs[r * LDS + lcol] = v;
        }
        __syncthreads();

#pragma unroll
        for (int k8 = 0; k8 < BK / 8; k8++) {
            const int kk = k8 * 8;
            uint32_t bh[NT][2], bl[NT][2];
#pragma unroll
            for (int nt = 0; nt < NT; nt++) {
                const int nb = wn * WTN + nt * 8 + lr4;
                const float b0 = Bs[nb * LDS + kk + lc4];
                const float b1 = Bs[nb * LDS + kk + lc4 + 4];
                bh[nt][0] = f2tf(b0); bl[nt][0] = f2tf(b0 - __uint_as_float(bh[nt][0]));
                bh[nt][1] = f2tf(b1); bl[nt][1] = f2tf(b1 - __uint_as_float(bh[nt][1]));
            }
#pragma unroll
            for (int mt = 0; mt < MT; mt++) {
                const int mb = wm * WTM + mt * 16;
                const float a0 = As[(mb + lr4)     * LDS + kk + lc4];
                const float a1 = As[(mb + lr4 + 8) * LDS + kk + lc4];
                const float a2 = As[(mb + lr4)     * LDS + kk + lc4 + 4];
                const float a3 = As[(mb + lr4 + 8) * LDS + kk + lc4 + 4];
                const uint32_t ah0 = f2tf(a0), ah1 = f2tf(a1), ah2 = f2tf(a2), ah3 = f2tf(a3);
                const uint32_t al0 = f2tf(a0 - __uint_as_float(ah0));
                const uint32_t al1 = f2tf(a1 - __uint_as_float(ah1));
                const uint32_t al2 = f2tf(a2 - __uint_as_float(ah2));
                const uint32_t al3 = f2tf(a3 - __uint_as_float(ah3));
#pragma unroll
                for (int nt = 0; nt < NT; nt++) {
                    mma8(acc[mt][nt], ah0, ah1, ah2, ah3, bh[nt][0], bh[nt][1]);
                    mma8(acc[mt][nt], al0, al1, al2, al3, bh[nt][0], bh[nt][1]);
                    mma8(acc[mt][nt], ah0, ah1, ah2, ah3, bl[nt][0], bl[nt][1]);
                }
            }
        }
    }

#pragma unroll
    for (int mt = 0; mt < MT; mt++) {
        const int mbase = m0 + wm * WTM + mt * 16 + lr4;
#pragma unroll
        for (int nt = 0; nt < NT; nt++) {
            const int n = n0 + wn * WTN + nt * 8 + 2 * lc4;
            float b0 = 0.f, b1 = 0.f;
            if (bias) { b0 = bias[n]; b1 = bias[n + 1]; }
            const size_t i0 = (size_t)mbase * Nd + n;
            const size_t i1 = (size_t)(mbase + 8) * Nd + n;
            float2 v0 = make_float2(acc[mt][nt][0] + b0, acc[mt][nt][1] + b1);
            float2 v1 = make_float2(acc[mt][nt][2] + b0, acc[mt][nt][3] + b1);
            if (resid) {
                v0.x += resid[i0]; v0.y += resid[i0 + 1];
                v1.x += resid[i1]; v1.y += resid[i1 + 1];
            }
            *(float2*)&Cc[i0] = v0;
            *(float2*)&Cc[i1] = v1;
        }
    }
}

// ---------------- gather qkv -> Q,K,V in [BH, N, HD] layout ----------------
__global__ __launch_bounds__(256) void gather_qkv_kernel(
    const float* __restrict__ qkv, float* __restrict__ Qg,
    float* __restrict__ Kg, float* __restrict__ Vg)
{
    const int i = blockIdx.x * 256 + threadIdx.x;
    if (i >= BHn * Nn * HDn) return;
    const int d  = i % HDn;
    const int r  = i / HDn;
    const int n  = r % Nn;
    const int bh = r / Nn;
    const int b  = bh >> 2, h = bh & 3;
    const size_t src = (size_t)(b * Nn + n) * (3 * Cdim) + h * HDn + d;
    Qg[i] = qkv[src];
    Kg[i] = qkv[src + Cdim];
    Vg[i] = qkv[src + 2 * Cdim];
}

// ---------------- transpose M (192x192) ----------------
__global__ __launch_bounds__(256) void transpose_m_kernel(
    const float* __restrict__ M, float* __restrict__ MT)
{
    const int i = blockIdx.x * 256 + threadIdx.x;
    if (i >= HDn * HDn) return;
    const int r = i / HDn, c = i % HDn;
    MT[c * HDn + r] = M[r * HDn + c];
}

// ---------------- per-key bias: kb[r] = -scale * dot(K[r], KM[r]) ----------------
__global__ __launch_bounds__(256) void kbias_kernel(
    const float* __restrict__ Kg, const float* __restrict__ KM,
    const float* __restrict__ scale_p, float* __restrict__ kb)
{
    const int gw = (blockIdx.x * 256 + threadIdx.x) >> 5;
    const int lane = threadIdx.x & 31;
    if (gw >= BHn * Nn) return;
    const float* kr  = Kg + (size_t)gw * HDn;
    const float* kmr = KM + (size_t)gw * HDn;
    float s = 0.f;
#pragma unroll
    for (int i = lane; i < HDn; i += 32) s += kr[i] * kmr[i];
    s = warpsum32(s);
    if (lane == 0) kb[gw] = -scale_p[0] * s;
}

// ---------------- tensor-core flash attention ----------------
// logits S_ij = 2*scale*(qM_i . k_j) + kb_j   (qMq term cancels in softmax)
constexpr int QSs = 196;   // q/k smem stride (conflict-free for A/B row-pattern frags)
constexpr int VSs = 200;   // v smem stride (conflict-free for k-major B frags)
constexpr int PSs = 68;    // p smem stride
constexpr int ATT_SMEM = (64 * QSs * 2 + 64 * VSs + 64 * PSs + 64 + 128 + 128) * 4;

__global__ __launch_bounds__(256) void attn_tc_kernel(
    const float* __restrict__ QM, const float* __restrict__ Kg,
    const float* __restrict__ Vg, const float* __restrict__ kbias,
    const float* __restrict__ scale_p, float* __restrict__ y)
{
    extern __shared__ __align__(16) float sm[];
    float* qs   = sm;
    float* ks   = qs + 64 * QSs;
    float* vs   = ks + 64 * QSs;
    float* ps   = vs + 64 * VSs;
    float* kbt  = ps + 64 * PSs;
    float* rmax = kbt + 64;
    float* rsum = rmax + 128;

    const int bh = blockIdx.x, qt = blockIdx.y;
    const int b = bh >> 2, h = bh & 3;
    const int t = threadIdx.x;
    const int wid = t >> 5, lane = t & 31;
    const int wm = wid & 3, wn = wid >> 2;   // 4 row-groups x 2 col-groups
    const int lr4 = lane >> 2, lc4 = lane & 3;
    const float twoscale = 2.0f * scale_p[0];
    const int r0 = wm * 16;

    {   // load q-tile once
        const float* qb = QM + ((size_t)bh * Nn + qt * 64) * HDn;
        for (int i = t; i < 64 * 48; i += 256) {
            const int r = i / 48, c = (i % 48) * 4;
            *(float4*)&qs[r * QSs + c] = *(const float4*)(qb + r * HDn + c);
        }
    }

    float O[12][4];
#pragma unroll
    for (int nt = 0; nt < 12; nt++)
#pragma unroll
        for (int q = 0; q < 4; q++) O[nt][q] = 0.f;
    float mr0 = -1e30f, mr1 = -1e30f, l0 = 0.f, l1 = 0.f;

    for (int kt = 0; kt < Nn / 64; kt++) {
        __syncthreads();
        {
            const float* kb_ = Kg + ((size_t)bh * Nn + kt * 64) * HDn;
            const float* vb_ = Vg + ((size_t)bh * Nn + kt * 64) * HDn;
            for (int i = t; i < 64 * 48; i += 256) {
                const int r = i / 48, c = (i % 48) * 4;
                *(float4*)&ks[r * QSs + c] = *(const float4*)(kb_ + r * HDn + c);
                *(float4*)&vs[r * VSs + c] = *(const float4*)(vb_ + r * HDn + c);
            }
            if (t < 64) kbt[t] = kbias[(size_t)bh * Nn + kt * 64 + t];
        }
        __syncthreads();

        // ---- S = qM_tile @ K_tile^T (warp: rows r0..r0+15, cols wn*32..+31) ----
        float s[4][4];
#pragma unroll
        for (int nt = 0; nt < 4; nt++)
#pragma unroll
            for (int q = 0; q < 4; q++) s[nt][q] = 0.f;
        const int cb = wn * 32;
#pragma unroll
        for (int k8 = 0; k8 < HDn / 8; k8++) {
            const int kk = k8 * 8;
            const uint32_t A0 = f2tf(qs[(r0 + lr4)     * QSs + kk + lc4]);
            const uint32_t A1 = f2tf(qs[(r0 + lr4 + 8) * QSs + kk + lc4]);
            const uint32_t A2 = f2tf(qs[(r0 + lr4)     * QSs + kk + lc4 + 4]);
            const uint32_t A3 = f2tf(qs[(r0 + lr4 + 8) * QSs + kk + lc4 + 4]);
#pragma unroll
            for (int nt = 0; nt < 4; nt++) {
                const int nb = cb + nt * 8 + lr4;
                const uint32_t B0 = f2tf(ks[nb * QSs + kk + lc4]);
                const uint32_t B1 = f2tf(ks[nb * QSs + kk + lc4 + 4]);
                mma8(s[nt], A0, A1, A2, A3, B0, B1);
            }
        }

        // ---- scale + key bias, partial rowmax ----
        float pm0 = -1e30f, pm1 = -1e30f;
#pragma unroll
        for (int nt = 0; nt < 4; nt++) {
            const int col = cb + nt * 8 + 2 * lc4;
            const float kb0 = kbt[col], kb1 = kbt[col + 1];
            s[nt][0] = fmaf(twoscale, s[nt][0], kb0);
            s[nt][1] = fmaf(twoscale, s[nt][1], kb1);
            s[nt][2] = fmaf(twoscale, s[nt][2], kb0);
            s[nt][3] = fmaf(twoscale, s[nt][3], kb1);
            pm0 = fmaxf(pm0, fmaxf(s[nt][0], s[nt][1]));
            pm1 = fmaxf(pm1, fmaxf(s[nt][2], s[nt][3]));
        }
        pm0 = fmaxf(pm0, __shfl_xor_sync(0xffffffffu, pm0, 1));
        pm0 = fmaxf(pm0, __shfl_xor_sync(0xffffffffu, pm0, 2));
        pm1 = fmaxf(pm1, __shfl_xor_sync(0xffffffffu, pm1, 1));
        pm1 = fmaxf(pm1, __shfl_xor_sync(0xffffffffu, pm1, 2));
        if (lc4 == 0) {
            rmax[wn * 64 + r0 + lr4]     = pm0;
            rmax[wn * 64 + r0 + lr4 + 8] = pm1;
        }
        __syncthreads();
        pm0 = fmaxf(pm0, rmax[(wn ^ 1) * 64 + r0 + lr4]);
        pm1 = fmaxf(pm1, rmax[(wn ^ 1) * 64 + r0 + lr4 + 8]);
        const float mn0 = fmaxf(mr0, pm0), mn1 = fmaxf(mr1, pm1);
        const float cor0 = __expf(mr0 - mn0), cor1 = __expf(mr1 - mn1);
        mr0 = mn0; mr1 = mn1;

        // ---- exp, partial rowsum, P -> smem ----
        float q0 = 0.f, q1 = 0.f;
#pragma unroll
        for (int nt = 0; nt < 4; nt++) {
            const int col = cb + nt * 8 + 2 * lc4;
            const float e0 = __expf(s[nt][0] - mn0);
            const float e1 = __expf(s[nt][1] - mn0);
            const float e2 = __expf(s[nt][2] - mn1);
            const float e3 = __expf(s[nt][3] - mn1);
            q0 += e0 + e1; q1 += e2 + e3;
            ps[(r0 + lr4)     * PSs + col]     = e0;
            ps[(r0 + lr4)     * PSs + col + 1] = e1;
            ps[(r0 + lr4 + 8) * PSs + col]     = e2;
            ps[(r0 + lr4 + 8) * PSs + col + 1] = e3;
        }
        q0 += __shfl_xor_sync(0xffffffffu, q0, 1);
        q0 += __shfl_xor_sync(0xffffffffu, q0, 2);
        q1 += __shfl_xor_sync(0xffffffffu, q1, 1);
        q1 += __shfl_xor_sync(0xffffffffu, q1, 2);
        if (lc4 == 0) {
            rsum[wn * 64 + r0 + lr4]     = q0;
            rsum[wn * 64 + r0 + lr4 + 8] = q1;
        }
#pragma unroll
        for (int nt = 0; nt < 12; nt++) {
            O[nt][0] *= cor0; O[nt][1] *= cor0;
            O[nt][2] *= cor1; O[nt][3] *= cor1;
        }
        __syncthreads();
        l0 = l0 * cor0 + q0 + rsum[(wn ^ 1) * 64 + r0 + lr4];
        l1 = l1 * cor1 + q1 + rsum[(wn ^ 1) * 64 + r0 + lr4 + 8];

        // ---- O += P @ V (warp: rows r0..r0+15, cols wn*96..+95) ----
        const int ob = wn * 96;
#pragma unroll
        for (int k8 = 0; k8 < 8; k8++) {
            const int kk = k8 * 8;
            const uint32_t A0 = f2tf(ps[(r0 + lr4)     * PSs + kk + lc4]);
            const uint32_t A1 = f2tf(ps[(r0 + lr4 + 8) * PSs + kk + lc4]);
            const uint32_t A2 = f2tf(ps[(r0 + lr4)     * PSs + kk + lc4 + 4]);
            const uint32_t A3 = f2tf(ps[(r0 + lr4 + 8) * PSs + kk + lc4 + 4]);
#pragma unroll
            for (int nt = 0; nt < 12; nt++) {
                const int nb = ob + nt * 8 + lr4;
                const uint32_t B0 = f2tf(vs[(kk + lc4)     * VSs + nb]);
                const uint32_t B1 = f2tf(vs[(kk + lc4 + 4) * VSs + nb]);
                mma8(O[nt], A0, A1, A2, A3, B0, B1);
            }
        }
    }

    // ---- normalize + write y ----
    const float i0v = 1.0f / l0, i1v = 1.0f / l1;
    const int ob = wn * 96;
    const int nrow0 = qt * 64 + r0 + lr4;
    float* y0 = y + (size_t)(b * Nn + nrow0) * Cdim + h * HDn;
    float* y1 = y0 + 8 * Cdim;
#pragma unroll
    for (int nt = 0; nt < 12; nt++) {
        const int col = ob + nt * 8 + 2 * lc4;
        *(float2*)&y0[col] = make_float2(O[nt][0] * i0v, O[nt][1] * i0v);
        *(float2*)&y1[col] = make_float2(O[nt][2] * i1v, O[nt][3] * i1v);
    }
}

// ---------------- RBF features ----------------
constexpr int RBF_SMEM_BYTES = (CEN * Cdim + CEN) * 4;  // 61520

__global__ __launch_bounds__(256) void rbf_kernel(
    const float* __restrict__ h2, const float* __restrict__ centers,
    const float* __restrict__ beta, float* __restrict__ rbf)
{
    extern __shared__ __align__(16) float rsm[];
    float* cs = rsm;
    float* cn = rsm + CEN * Cdim;
    const int t = threadIdx.x;
    for (int i = t; i < CEN * Cdim; i += 256) cs[i] = centers[i];
    __syncthreads();
    if (t < CEN) {
        float s = 0.f;
        for (int k = 0; k < Cdim; k++) s += cs[t * Cdim + k] * cs[t * Cdim + k];
        cn[t] = s;
    }
    __syncthreads();
    const int wid = t >> 5, lane = t & 31;
    for (int rr = 0; rr < 8; rr++) {
        const int row = blockIdx.x * 64 + wid * 8 + rr;
        const float* xr = h2 + (size_t)row * Cdim;
        float xv[24];
#pragma unroll
        for (int i = 0; i < 24; i++) xv[i] = xr[lane + i * 32];
        float a = 0.f;
#pragma unroll
        for (int i = 0; i < 24; i++) a += xv[i] * xv[i];
        a = warpsum32(a);
        for (int j = 0; j < CEN; j++) {
            float d = 0.f;
#pragma unroll
            for (int i = 0; i < 24; i++) d += xv[i] * cs[j * Cdim + lane + i * 32];
            d = warpsum32(d);
            if (lane == 0)
                rbf[(size_t)row * CEN + j] = __expf(-beta[j] * (a - 2.0f * d + cn[j]));
        }
    }
}

// ---------------- final: out = x1 + rbf @ fc_w^T ----------------
__global__ __launch_bounds__(256) void final_kernel(
    const float* __restrict__ x1, const float* __restrict__ rbf,
    const float* __restrict__ fcw, float* __restrict__ out)
{
    const int i = blockIdx.x * 256 + threadIdx.x;
    if (i >= Sn * Cdim) return;
    const int c = i % Cdim;
    const int r = i / Cdim;
    const float* rb = rbf + (size_t)r * CEN;
    const float* fw = fcw + (size_t)c * CEN;
    float acc = x1[i];
#pragma unroll
    for (int j = 0; j < CEN; j++) acc += rb[j] * fw[j];
    out[i] = acc;
}

// ---------------- launcher ----------------
extern "C" void kernel_launch(void* const* d_in, const int* in_sizes, int n_in,
                              void* d_out, int out_size)
{
    (void)in_sizes; (void)n_in; (void)out_size;
    const float* x     = (const float*)d_in[0];
    const float* n1w   = (const float*)d_in[1];
    const float* n1b   = (const float*)d_in[2];
    const float* qkvw  = (const float*)d_in[3];
    const float* Mmat  = (const float*)d_in[4];
    const float* scale = (const float*)d_in[5];
    const float* projw = (const float*)d_in[6];
    const float* projb = (const float*)d_in[7];
    const float* n2w   = (const float*)d_in[8];
    const float* n2b   = (const float*)d_in[9];
    const float* cent  = (const float*)d_in[10];
    const float* beta  = (const float*)d_in[11];
    const float* fcw   = (const float*)d_in[12];
    float* out = (float*)d_out;

    float *hP, *qkvP, *QgP, *KgP, *VgP, *QMP, *KMP, *MTP, *kbP, *yP, *x1P, *h2P, *rbfP;
    cudaGetSymbolAddress((void**)&hP,   g_h);
    cudaGetSymbolAddress((void**)&qkvP, g_qkv);
    cudaGetSymbolAddress((void**)&QgP,  g_Qg);
    cudaGetSymbolAddress((void**)&KgP,  g_Kg);
    cudaGetSymbolAddress((void**)&VgP,  g_Vg);
    cudaGetSymbolAddress((void**)&QMP,  g_QM);
    cudaGetSymbolAddress((void**)&KMP,  g_KM);
    cudaGetSymbolAddress((void**)&MTP,  g_MT);
    cudaGetSymbolAddress((void**)&kbP,  g_kb);
    cudaGetSymbolAddress((void**)&yP,   g_y);
    cudaGetSymbolAddress((void**)&x1P,  g_x1);
    cudaGetSymbolAddress((void**)&h2P,  g_h2);
    cudaGetSymbolAddress((void**)&rbfP, g_rbf);

    cudaFuncSetAttribute(attn_tc_kernel, cudaFuncAttributeMaxDynamicSharedMemorySize, ATT_SMEM);
    cudaFuncSetAttribute(rbf_kernel, cudaFuncAttributeMaxDynamicSharedMemorySize, RBF_SMEM_BYTES);

    // 1) LN1
    ln_kernel<<<Sn, 256>>>(x, n1w, n1b, hP);
    // 2) qkv = h @ qkv_w^T   [8192 x 2304] (tf32x3 tensor core)
    gemm_tf32x3_nt<128><<<dim3(3 * Cdim / 128, Sn / 128), 256>>>(
        hP, qkvw, qkvP, Sn, 3 * Cdim, Cdim, nullptr, nullptr);
    // 3) gather into [BH,N,HD]
    gather_qkv_kernel<<<(BHn * Nn * HDn + 255) / 256, 256>>>(qkvP, QgP, KgP, VgP);
    // 4) M^T
    transpose_m_kernel<<<(HDn * HDn + 255) / 256, 256>>>(Mmat, MTP);
    // 5) qM = Q @ M, kM = K @ M
    gemm_tf32x3_nt<64><<<dim3(HDn / 64, BHn * Nn / 128), 256>>>(
        QgP, MTP, QMP, BHn * Nn, HDn, HDn, nullptr, nullptr);
    gemm_tf32x3_nt<64><<<dim3(HDn / 64, BHn * Nn / 128), 256>>>(
        KgP, MTP, KMP, BHn * Nn, HDn, HDn, nullptr, nullptr);
    // 6) per-key bias
    kbias_kernel<<<(BHn * Nn) * 32 / 256, 256>>>(KgP, KMP, scale, kbP);
    // 7) tensor-core flash attention -> y [B,N,C]
    attn_tc_kernel<<<dim3(BHn, Nn / 64), 256, ATT_SMEM>>>(QMP, KgP, VgP, kbP, scale, yP);
    // 8) x1 = x + y @ proj_w^T + proj_b (tf32x3)
    gemm_tf32x3_nt<128><<<dim3(Cdim / 128, Sn / 128), 256>>>(
        yP, projw, x1P, Sn, Cdim, Cdim, projb, x);
    // 9) LN2
    ln_kernel<<<Sn, 256>>>(x1P, n2w, n2b, h2P);
    // 10) RBF features
    rbf_kernel<<<Sn / 64, 256, RBF_SMEM_BYTES>>>(h2P, cent, beta, rbfP);
    // 11) out = x1 + rbf @ fc_w^T
    final_kernel<<<(Sn * Cdim + 255) / 256, 256>>>(x1P, rbfP, fcw, out);
}

// round 3
// speedup vs baseline: 3.7698x; 1.5716x over previous
#include <cuda_runtime.h>
#include <cstdint>

// ---------------- problem constants ----------------
constexpr int Cdim = 768;
constexpr int Bn   = 8;
constexpr int Nn   = 1024;
constexpr int HDn  = 192;            // head dim
constexpr int Sn   = Bn * Nn;        // 8192 rows
constexpr int BHn  = Bn * 4;         // 32
constexpr int CEN  = 20;
constexpr float EPSv = 1e-5f;

// ---------------- scratch (device globals; no allocation allowed) ----------------
__device__ float g_h     [Sn * Cdim];
__device__ float g_qkvwr [3 * Cdim * Cdim];
__device__ float g_projwr[Cdim * Cdim];
__device__ float g_Qg  [BHn * Nn * HDn];
__device__ float g_Kg  [BHn * Nn * HDn];
__device__ float g_Vg  [BHn * Nn * HDn];
__device__ float g_QM  [BHn * Nn * HDn];
__device__ float g_KM  [BHn * Nn * HDn];
__device__ float g_MT  [HDn * HDn];
__device__ float g_kb  [BHn * Nn];
__device__ float g_y   [Sn * Cdim];
__device__ float g_x1  [Sn * Cdim];
__device__ float g_h2  [Sn * Cdim];
__device__ float g_rbf [Sn * CEN];

// ---------------- helpers ----------------
__device__ __forceinline__ float warpsum32(float v) {
#pragma unroll
    for (int o = 16; o >= 1; o >>= 1) v += __shfl_xor_sync(0xffffffffu, v, o);
    return v;
}
__device__ __forceinline__ uint32_t f2tf(float f) {
    uint32_t u;
    asm("cvt.rna.tf32.f32 %0, %1;" : "=r"(u) : "f"(f));
    return u;
}
__device__ __forceinline__ float tfr(float f) {    // round-to-tf32, kept as float bits
    return __uint_as_float(f2tf(f));
}
__device__ __forceinline__ void mma8(float* c,
    uint32_t a0, uint32_t a1, uint32_t a2, uint32_t a3, uint32_t b0, uint32_t b1)
{
    asm volatile("mma.sync.aligned.m16n8k8.row.col.f32.tf32.tf32.f32 "
        "{%0,%1,%2,%3}, {%4,%5,%6,%7}, {%8,%9}, {%0,%1,%2,%3};"
        : "+f"(c[0]), "+f"(c[1]), "+f"(c[2]), "+f"(c[3])
        : "r"(a0), "r"(a1), "r"(a2), "r"(a3), "r"(b0), "r"(b1));
}

// ---------------- LayerNorm: one block per row; optional tf32 rounding ----------
template<bool ROUND>
__global__ __launch_bounds__(256) void ln_kernel(
    const float* __restrict__ x, const float* __restrict__ w,
    const float* __restrict__ b, float* __restrict__ out)
{
    const int row = blockIdx.x;
    const float* xr = x + (size_t)row * Cdim;
    float s = 0.f, s2 = 0.f;
    for (int i = threadIdx.x; i < Cdim; i += 256) {
        float v = xr[i];
        s += v; s2 += v * v;
    }
    s = warpsum32(s); s2 = warpsum32(s2);
    __shared__ float sh[16];
    const int wid = threadIdx.x >> 5, lane = threadIdx.x & 31;
    if (lane == 0) { sh[wid] = s; sh[8 + wid] = s2; }
    __syncthreads();
    if (threadIdx.x == 0) {
        float a = 0.f, c = 0.f;
#pragma unroll
        for (int i = 0; i < 8; i++) { a += sh[i]; c += sh[8 + i]; }
        sh[0] = a; sh[8] = c;
    }
    __syncthreads();
    const float mu  = sh[0] * (1.0f / Cdim);
    const float var = sh[8] * (1.0f / Cdim) - mu * mu;
    const float rs  = rsqrtf(var + EPSv);
    for (int i = threadIdx.x; i < Cdim; i += 256) {
        float v = (xr[i] - mu) * rs * w[i] + b[i];
        out[(size_t)row * Cdim + i] = ROUND ? tfr(v) : v;
    }
}

// ---------------- round-copy (weights -> tf32-rounded scratch) ----------------
__global__ __launch_bounds__(256) void round_copy_kernel(
    const float* __restrict__ src, float* __restrict__ dst, int n)
{
    for (int i = blockIdx.x * 256 + threadIdx.x; i < n; i += gridDim.x * 256)
        dst[i] = tfr(src[i]);
}

// ---------------- transpose + round M (192x192) ----------------
__global__ __launch_bounds__(256) void transpose_m_kernel(
    const float* __restrict__ M, float* __restrict__ MT)
{
    const int i = blockIdx.x * 256 + threadIdx.x;
    if (i >= HDn * HDn) return;
    const int r = i / HDn, c = i % HDn;
    MT[c * HDn + r] = tfr(M[r * HDn + c]);
}

// ---------------- tf32 single-pass NT GEMM: C = A[M,K] * B[N,K]^T ----------------
// Inputs must already be tf32-rounded floats. M%128==0, N%BN==0, K%32==0.
// MODE 0: store tf32-rounded to C.
// MODE 1: qkv scatter -> C(=Qg), C2(=Kg), C3(=Vg), rounded. Nd==3*Cdim.
// MODE 2: full-precision store to C with +bias +resid.
template<int BN, int MODE>
__global__ __launch_bounds__(256) void gemm_tf32_nt(
    const float* __restrict__ A, const float* __restrict__ B, float* __restrict__ Cc,
    float* __restrict__ C2, float* __restrict__ C3,
    int Md, int Nd, int Kd,
    const float* __restrict__ bias, const float* __restrict__ resid)
{
    constexpr int BM = 128, BK = 32, LDS = BK + 4;
    constexpr int WM = (BN == 128) ? 2 : 4;
    constexpr int WN = 8 / WM;
    constexpr int WTM = BM / WM, WTN = BN / WN;
    constexpr int MT = WTM / 16, NT = WTN / 8;
    __shared__ float As[BM * LDS];
    __shared__ float Bs[BN * LDS];

    const int t = threadIdx.x;
    const int wid = t >> 5, lane = t & 31;
    const int wm = wid % WM, wn = wid / WM;
    const int lr4 = lane >> 2, lc4 = lane & 3;
    const int m0 = blockIdx.y * BM, n0 = blockIdx.x * BN;
    const int lrow = t >> 3;            // 0..31
    const int lcol = (t & 7) << 2;      // 0,4,...,28

    float acc[MT][NT][4];
#pragma unroll
    for (int i = 0; i < MT; i++)
#pragma unroll
        for (int j = 0; j < NT; j++)
#pragma unroll
            for (int q = 0; q < 4; q++) acc[i][j][q] = 0.f;

    for (int k0 = 0; k0 < Kd; k0 += BK) {
        __syncthreads();
#pragma unroll
        for (int p = 0; p < 4; p++) {
            const int r = lrow + p * 32;
            float4 v = *(const float4*)(A + (size_t)(m0 + r) * Kd + k0 + lcol);
            *(float4*)&As[r * LDS + lcol] = v;
        }
#pragma unroll
        for (int p = 0; p < BN / 32; p++) {
            const int r = lrow + p * 32;
            float4 v = *(const float4*)(B + (size_t)(n0 + r) * Kd + k0 + lcol);
            *(float4*)&Bs[r * LDS + lcol] = v;
        }
        __syncthreads();

#pragma unroll
        for (int k8 = 0; k8 < BK / 8; k8++) {
            const int kk = k8 * 8;
            uint32_t bf[NT][2];
#pragma unroll
            for (int nt = 0; nt < NT; nt++) {
                const int nb = wn * WTN + nt * 8 + lr4;
                bf[nt][0] = __float_as_uint(Bs[nb * LDS + kk + lc4]);
                bf[nt][1] = __float_as_uint(Bs[nb * LDS + kk + lc4 + 4]);
            }
#pragma unroll
            for (int mt = 0; mt < MT; mt++) {
                const int mb = wm * WTM + mt * 16;
                const uint32_t a0 = __float_as_uint(As[(mb + lr4)     * LDS + kk + lc4]);
                const uint32_t a1 = __float_as_uint(As[(mb + lr4 + 8) * LDS + kk + lc4]);
                const uint32_t a2 = __float_as_uint(As[(mb + lr4)     * LDS + kk + lc4 + 4]);
                const uint32_t a3 = __float_as_uint(As[(mb + lr4 + 8) * LDS + kk + lc4 + 4]);
#pragma unroll
                for (int nt = 0; nt < NT; nt++)
                    mma8(acc[mt][nt], a0, a1, a2, a3, bf[nt][0], bf[nt][1]);
            }
        }
    }

#pragma unroll
    for (int mt = 0; mt < MT; mt++) {
        const int mbase = m0 + wm * WTM + mt * 16 + lr4;
#pragma unroll
        for (int nt = 0; nt < NT; nt++) {
            const int n = n0 + wn * WTN + nt * 8 + 2 * lc4;
            if (MODE == 0) {
                *(float2*)&Cc[(size_t)mbase * Nd + n] =
                    make_float2(tfr(acc[mt][nt][0]), tfr(acc[mt][nt][1]));
                *(float2*)&Cc[(size_t)(mbase + 8) * Nd + n] =
                    make_float2(tfr(acc[mt][nt][2]), tfr(acc[mt][nt][3]));
            } else if (MODE == 1) {
                const int which = n / Cdim;
                const int rem = n % Cdim;
                const int h = rem / HDn, d = rem % HDn;
                float* dst = (which == 0) ? Cc : (which == 1) ? C2 : C3;
#pragma unroll
                for (int rr = 0; rr < 2; rr++) {
                    const int m = mbase + rr * 8;
                    const int b = m >> 10, nr = m & 1023;
                    const size_t di = ((size_t)((b << 2) + h) * Nn + nr) * HDn + d;
                    *(float2*)&dst[di] = make_float2(tfr(acc[mt][nt][rr * 2]),
                                                     tfr(acc[mt][nt][rr * 2 + 1]));
                }
            } else {
                const float b0 = bias[n], b1 = bias[n + 1];
                const size_t i0 = (size_t)mbase * Nd + n;
                const size_t i1 = (size_t)(mbase + 8) * Nd + n;
                *(float2*)&Cc[i0] = make_float2(acc[mt][nt][0] + b0 + resid[i0],
                                                acc[mt][nt][1] + b1 + resid[i0 + 1]);
                *(float2*)&Cc[i1] = make_float2(acc[mt][nt][2] + b0 + resid[i1],
                                                acc[mt][nt][3] + b1 + resid[i1 + 1]);
            }
        }
    }
}

// ---------------- per-key bias: kb[r] = -scale * dot(K[r], KM[r]) ----------------
__global__ __launch_bounds__(256) void kbias_kernel(
    const float* __restrict__ Kg, const float* __restrict__ KM,
    const float* __restrict__ scale_p, float* __restrict__ kb)
{
    const int gw = (blockIdx.x * 256 + threadIdx.x) >> 5;
    const int lane = threadIdx.x & 31;
    if (gw >= BHn * Nn) return;
    const float* kr  = Kg + (size_t)gw * HDn;
    const float* kmr = KM + (size_t)gw * HDn;
    float s = 0.f;
#pragma unroll
    for (int i = lane; i < HDn; i += 32) s += kr[i] * kmr[i];
    s = warpsum32(s);
    if (lane == 0) kb[gw] = -scale_p[0] * s;
}

// ---------------- tensor-core flash attention ----------------
// logits S_ij = 2*scale*(qM_i . k_j) + kb_j   (qMq term cancels in softmax)
constexpr int QSs = 196;
constexpr int VSs = 200;
constexpr int PSs = 68;
constexpr int ATT_SMEM = (64 * QSs * 2 + 64 * VSs + 64 * PSs + 64 + 128 + 128) * 4;

__global__ __launch_bounds__(256) void attn_tc_kernel(
    const float* __restrict__ QM, const float* __restrict__ Kg,
    const float* __restrict__ Vg, const float* __restrict__ kbias,
    const float* __restrict__ scale_p, float* __restrict__ y)
{
    extern __shared__ __align__(16) float sm[];
    float* qs   = sm;
    float* ks   = qs + 64 * QSs;
    float* vs   = ks + 64 * QSs;
    float* ps   = vs + 64 * VSs;
    float* kbt  = ps + 64 * PSs;
    float* rmax = kbt + 64;
    float* rsum = rmax + 128;

    const int bh = blockIdx.x, qt = blockIdx.y;
    const int b = bh >> 2, h = bh & 3;
    const int t = threadIdx.x;
    const int wid = t >> 5, lane = t & 31;
    const int wm = wid & 3, wn = wid >> 2;   // 4 row-groups x 2 col-groups
    const int lr4 = lane >> 2, lc4 = lane & 3;
    const float twoscale = 2.0f * scale_p[0];
    const int r0 = wm * 16;

    {   // load q-tile (already tf32-rounded) once
        const float* qb = QM + ((size_t)bh * Nn + qt * 64) * HDn;
        for (int i = t; i < 64 * 48; i += 256) {
            const int r = i / 48, c = (i % 48) * 4;
            *(float4*)&qs[r * QSs + c] = *(const float4*)(qb + r * HDn + c);
        }
    }

    float O[12][4];
#pragma unroll
    for (int nt = 0; nt < 12; nt++)
#pragma unroll
        for (int q = 0; q < 4; q++) O[nt][q] = 0.f;
    float mr0 = -1e30f, mr1 = -1e30f, l0 = 0.f, l1 = 0.f;

    for (int kt = 0; kt < Nn / 64; kt++) {
        __syncthreads();
        {
            const float* kb_ = Kg + ((size_t)bh * Nn + kt * 64) * HDn;
            const float* vb_ = Vg + ((size_t)bh * Nn + kt * 64) * HDn;
            for (int i = t; i < 64 * 48; i += 256) {
                const int r = i / 48, c = (i % 48) * 4;
                *(float4*)&ks[r * QSs + c] = *(const float4*)(kb_ + r * HDn + c);
                *(float4*)&vs[r * VSs + c] = *(const float4*)(vb_ + r * HDn + c);
            }
            if (t < 64) kbt[t] = kbias[(size_t)bh * Nn + kt * 64 + t];
        }
        __syncthreads();

        // ---- S = qM_tile @ K_tile^T ----
        float s[4][4];
#pragma unroll
        for (int nt = 0; nt < 4; nt++)
#pragma unroll
            for (int q = 0; q < 4; q++) s[nt][q] = 0.f;
        const int cb = wn * 32;
#pragma unroll
        for (int k8 = 0; k8 < HDn / 8; k8++) {
            const int kk = k8 * 8;
            const uint32_t A0 = __float_as_uint(qs[(r0 + lr4)     * QSs + kk + lc4]);
            const uint32_t A1 = __float_as_uint(qs[(r0 + lr4 + 8) * QSs + kk + lc4]);
            const uint32_t A2 = __float_as_uint(qs[(r0 + lr4)     * QSs + kk + lc4 + 4]);
            const uint32_t A3 = __float_as_uint(qs[(r0 + lr4 + 8) * QSs + kk + lc4 + 4]);
#pragma unroll
            for (int nt = 0; nt < 4; nt++) {
                const int nb = cb + nt * 8 + lr4;
                const uint32_t B0 = __float_as_uint(ks[nb * QSs + kk + lc4]);
                const uint32_t B1 = __float_as_uint(ks[nb * QSs + kk + lc4 + 4]);
                mma8(s[nt], A0, A1, A2, A3, B0, B1);
            }
        }

        // ---- scale + key bias, partial rowmax ----
        float pm0 = -1e30f, pm1 = -1e30f;
#pragma unroll
        for (int nt = 0; nt < 4; nt++) {
            const int col = cb + nt * 8 + 2 * lc4;
            const float kb0 = kbt[col], kb1 = kbt[col + 1];
            s[nt][0] = fmaf(twoscale, s[nt][0], kb0);
            s[nt][1] = fmaf(twoscale, s[nt][1], kb1);
            s[nt][2] = fmaf(twoscale, s[nt][2], kb0);
            s[nt][3] = fmaf(twoscale, s[nt][3], kb1);
            pm0 = fmaxf(pm0, fmaxf(s[nt][0], s[nt][1]));
            pm1 = fmaxf(pm1, fmaxf(s[nt][2], s[nt][3]));
        }
        pm0 = fmaxf(pm0, __shfl_xor_sync(0xffffffffu, pm0, 1));
        pm0 = fmaxf(pm0, __shfl_xor_sync(0xffffffffu, pm0, 2));
        pm1 = fmaxf(pm1, __shfl_xor_sync(0xffffffffu, pm1, 1));
        pm1 = fmaxf(pm1, __shfl_xor_sync(0xffffffffu, pm1, 2));
        if (lc4 == 0) {
            rmax[wn * 64 + r0 + lr4]     = pm0;
            rmax[wn * 64 + r0 + lr4 + 8] = pm1;
        }
        __syncthreads();
        pm0 = fmaxf(pm0, rmax[(wn ^ 1) * 64 + r0 + lr4]);
        pm1 = fmaxf(pm1, rmax[(wn ^ 1) * 64 + r0 + lr4 + 8]);
        const float mn0 = fmaxf(mr0, pm0), mn1 = fmaxf(mr1, pm1);
        const float cor0 = __expf(mr0 - mn0), cor1 = __expf(mr1 - mn1);
        mr0 = mn0; mr1 = mn1;

        // ---- exp, partial rowsum, P (rounded) -> smem ----
        float q0 = 0.f, q1 = 0.f;
#pragma unroll
        for (int nt = 0; nt < 4; nt++) {
            const int col = cb + nt * 8 + 2 * lc4;
            const float e0 = __expf(s[nt][0] - mn0);
            const float e1 = __expf(s[nt][1] - mn0);
            const float e2 = __expf(s[nt][2] - mn1);
            const float e3 = __expf(s[nt][3] - mn1);
            q0 += e0 + e1; q1 += e2 + e3;
            ps[(r0 + lr4)     * PSs + col]     = tfr(e0);
            ps[(r0 + lr4)     * PSs + col + 1] = tfr(e1);
            ps[(r0 + lr4 + 8) * PSs + col]     = tfr(e2);
            ps[(r0 + lr4 + 8) * PSs + col + 1] = tfr(e3);
        }
        q0 += __shfl_xor_sync(0xffffffffu, q0, 1);
        q0 += __shfl_xor_sync(0xffffffffu, q0, 2);
        q1 += __shfl_xor_sync(0xffffffffu, q1, 1);
        q1 += __shfl_xor_sync(0xffffffffu, q1, 2);
        if (lc4 == 0) {
            rsum[wn * 64 + r0 + lr4]     = q0;
            rsum[wn * 64 + r0 + lr4 + 8] = q1;
        }
#pragma unroll
        for (int nt = 0; nt < 12; nt++) {
            O[nt][0] *= cor0; O[nt][1] *= cor0;
            O[nt][2] *= cor1; O[nt][3] *= cor1;
        }
        __syncthreads();
        l0 = l0 * cor0 + q0 + rsum[(wn ^ 1) * 64 + r0 + lr4];
        l1 = l1 * cor1 + q1 + rsum[(wn ^ 1) * 64 + r0 + lr4 + 8];

        // ---- O += P @ V ----
        const int ob = wn * 96;
#pragma unroll
        for (int k8 = 0; k8 < 8; k8++) {
            const int kk = k8 * 8;
            const uint32_t A0 = __float_as_uint(ps[(r0 + lr4)     * PSs + kk + lc4]);
            const uint32_t A1 = __float_as_uint(ps[(r0 + lr4 + 8) * PSs + kk + lc4]);
            const uint32_t A2 = __float_as_uint(ps[(r0 + lr4)     * PSs + kk + lc4 + 4]);
            const uint32_t A3 = __float_as_uint(ps[(r0 + lr4 + 8) * PSs + kk + lc4 + 4]);
#pragma unroll
            for (int nt = 0; nt < 12; nt++) {
                const int nb = ob + nt * 8 + lr4;
                const uint32_t B0 = __float_as_uint(vs[(kk + lc4)     * VSs + nb]);
                const uint32_t B1 = __float_as_uint(vs[(kk + lc4 + 4) * VSs + nb]);
                mma8(O[nt], A0, A1, A2, A3, B0, B1);
            }
        }
    }

    // ---- normalize + write y (tf32-rounded for proj GEMM) ----
    const float i0v = 1.0f / l0, i1v = 1.0f / l1;
    const int ob = wn * 96;
    const int nrow0 = qt * 64 + r0 + lr4;
    float* y0 = y + (size_t)(b * Nn + nrow0) * Cdim + h * HDn;
    float* y1 = y0 + 8 * Cdim;
#pragma unroll
    for (int nt = 0; nt < 12; nt++) {
        const int col = ob + nt * 8 + 2 * lc4;
        *(float2*)&y0[col] = make_float2(tfr(O[nt][0] * i0v), tfr(O[nt][1] * i0v));
        *(float2*)&y1[col] = make_float2(tfr(O[nt][2] * i1v), tfr(O[nt][3] * i1v));
    }
}

// ---------------- RBF features ----------------
constexpr int RBF_SMEM_BYTES = (CEN * Cdim + CEN) * 4;

__global__ __launch_bounds__(256) void rbf_kernel(
    const float* __restrict__ h2, const float* __restrict__ centers,
    const float* __restrict__ beta, float* __restrict__ rbf)
{
    extern __shared__ __align__(16) float rsm[];
    float* cs = rsm;
    float* cn = rsm + CEN * Cdim;
    const int t = threadIdx.x;
    for (int i = t; i < CEN * Cdim; i += 256) cs[i] = centers[i];
    __syncthreads();
    if (t < CEN) {
        float s = 0.f;
        for (int k = 0; k < Cdim; k++) s += cs[t * Cdim + k] * cs[t * Cdim + k];
        cn[t] = s;
    }
    __syncthreads();
    const int wid = t >> 5, lane = t & 31;
    for (int rr = 0; rr < 8; rr++) {
        const int row = blockIdx.x * 64 + wid * 8 + rr;
        const float* xr = h2 + (size_t)row * Cdim;
        float xv[24];
#pragma unroll
        for (int i = 0; i < 24; i++) xv[i] = xr[lane + i * 32];
        float a = 0.f;
#pragma unroll
        for (int i = 0; i < 24; i++) a += xv[i] * xv[i];
        a = warpsum32(a);
        for (int j = 0; j < CEN; j++) {
            float d = 0.f;
#pragma unroll
            for (int i = 0; i < 24; i++) d += xv[i] * cs[j * Cdim + lane + i * 32];
            d = warpsum32(d);
            if (lane == 0)
                rbf[(size_t)row * CEN + j] = __expf(-beta[j] * (a - 2.0f * d + cn[j]));
        }
    }
}

// ---------------- final: out = x1 + rbf @ fc_w^T ----------------
__global__ __launch_bounds__(256) void final_kernel(
    const float* __restrict__ x1, const float* __restrict__ rbf,
    const float* __restrict__ fcw, float* __restrict__ out)
{
    const int i = blockIdx.x * 256 + threadIdx.x;
    if (i >= Sn * Cdim) return;
    const int c = i % Cdim;
    const int r = i / Cdim;
    const float* rb = rbf + (size_t)r * CEN;
    const float* fw = fcw + (size_t)c * CEN;
    float acc = x1[i];
#pragma unroll
    for (int j = 0; j < CEN; j++) acc += rb[j] * fw[j];
    out[i] = acc;
}

// ---------------- launcher ----------------
extern "C" void kernel_launch(void* const* d_in, const int* in_sizes, int n_in,
                              void* d_out, int out_size)
{
    (void)in_sizes; (void)n_in; (void)out_size;
    const float* x     = (const float*)d_in[0];
    const float* n1w   = (const float*)d_in[1];
    const float* n1b   = (const float*)d_in[2];
    const float* qkvw  = (const float*)d_in[3];
    const float* Mmat  = (const float*)d_in[4];
    const float* scale = (const float*)d_in[5];
    const float* projw = (const float*)d_in[6];
    const float* projb = (const float*)d_in[7];
    const float* n2w   = (const float*)d_in[8];
    const float* n2b   = (const float*)d_in[9];
    const float* cent  = (const float*)d_in[10];
    const float* beta  = (const float*)d_in[11];
    const float* fcw   = (const float*)d_in[12];
    float* out = (float*)d_out;

    float *hP, *qwP, *pwP, *QgP, *KgP, *VgP, *QMP, *KMP, *MTP, *kbP, *yP, *x1P, *h2P, *rbfP;
    cudaGetSymbolAddress((void**)&hP,   g_h);
    cudaGetSymbolAddress((void**)&qwP,  g_qkvwr);
    cudaGetSymbolAddress((void**)&pwP,  g_projwr);
    cudaGetSymbolAddress((void**)&QgP,  g_Qg);
    cudaGetSymbolAddress((void**)&KgP,  g_Kg);
    cudaGetSymbolAddress((void**)&VgP,  g_Vg);
    cudaGetSymbolAddress((void**)&QMP,  g_QM);
    cudaGetSymbolAddress((void**)&KMP,  g_KM);
    cudaGetSymbolAddress((void**)&MTP,  g_MT);
    cudaGetSymbolAddress((void**)&kbP,  g_kb);
    cudaGetSymbolAddress((void**)&yP,   g_y);
    cudaGetSymbolAddress((void**)&x1P,  g_x1);
    cudaGetSymbolAddress((void**)&h2P,  g_h2);
    cudaGetSymbolAddress((void**)&rbfP, g_rbf);

    cudaFuncSetAttribute(attn_tc_kernel, cudaFuncAttributeMaxDynamicSharedMemorySize, ATT_SMEM);
    cudaFuncSetAttribute(rbf_kernel, cudaFuncAttributeMaxDynamicSharedMemorySize, RBF_SMEM_BYTES);

    // 0) weight rounding (tf32 copies)
    round_copy_kernel<<<512, 256>>>(qkvw, qwP, 3 * Cdim * Cdim);
    round_copy_kernel<<<512, 256>>>(projw, pwP, Cdim * Cdim);
    transpose_m_kernel<<<(HDn * HDn + 255) / 256, 256>>>(Mmat, MTP);
    // 1) LN1 (rounded output)
    ln_kernel<true><<<Sn, 256>>>(x, n1w, n1b, hP);
    // 2) qkv GEMM fused with gather -> Qg/Kg/Vg (rounded)
    gemm_tf32_nt<128, 1><<<dim3(3 * Cdim / 128, Sn / 128), 256>>>(
        hP, qwP, QgP, KgP, VgP, Sn, 3 * Cdim, Cdim, nullptr, nullptr);
    // 3) qM = Q @ M, kM = K @ M (rounded outputs)
    gemm_tf32_nt<64, 0><<<dim3(HDn / 64, BHn * Nn / 128), 256>>>(
        QgP, MTP, QMP, nullptr, nullptr, BHn * Nn, HDn, HDn, nullptr, nullptr);
    gemm_tf32_nt<64, 0><<<dim3(HDn / 64, BHn * Nn / 128), 256>>>(
        KgP, MTP, KMP, nullptr, nullptr, BHn * Nn, HDn, HDn, nullptr, nullptr);
    // 4) per-key bias
    kbias_kernel<<<(BHn * Nn) * 32 / 256, 256>>>(KgP, KMP, scale, kbP);
    // 5) tensor-core flash attention -> y (rounded)
    attn_tc_kernel<<<dim3(BHn, Nn / 64), 256, ATT_SMEM>>>(QMP, KgP, VgP, kbP, scale, yP);
    // 6) x1 = x + y @ proj_w^T + proj_b
    gemm_tf32_nt<128, 2><<<dim3(Cdim / 128, Sn / 128), 256>>>(
        yP, pwP, x1P, nullptr, nullptr, Sn, Cdim, Cdim, projb, x);
    // 7) LN2 (full precision)
    ln_kernel<false><<<Sn, 256>>>(x1P, n2w, n2b, h2P);
    // 8) RBF features
    rbf_kernel<<<Sn / 64, 256, RBF_SMEM_BYTES>>>(h2P, cent, beta, rbfP);
    // 9) out = x1 + rbf @ fc_w^T
    final_kernel<<<(Sn * Cdim + 255) / 256, 256>>>(x1P, rbfP, fcw, out);
}

// round 5
// speedup vs baseline: 5.3973x; 1.4317x over previous
#include <cuda_runtime.h>
#include <cstdint>

// ---------------- problem constants ----------------
constexpr int Cdim = 768;
constexpr int Bn   = 8;
constexpr int Nn   = 1024;
constexpr int HDn  = 192;            // head dim
constexpr int Sn   = Bn * Nn;        // 8192 rows
constexpr int BHn  = Bn * 4;         // 32
constexpr int CEN  = 20;
constexpr float EPSv = 1e-5f;

// ---------------- scratch (device globals; no allocation allowed) ----------------
__device__ float g_h     [Sn * Cdim];
__device__ float g_qkvwr [3 * Cdim * Cdim];
__device__ float g_projwr[Cdim * Cdim];
__device__ float g_Qg  [BHn * Nn * HDn];
__device__ float g_Kg  [BHn * Nn * HDn];
__device__ float g_Vg  [BHn * Nn * HDn];
__device__ float g_QM  [BHn * Nn * HDn];
__device__ float g_KM  [BHn * Nn * HDn];
__device__ float g_MT  [HDn * HDn];
__device__ float g_kb  [BHn * Nn];
__device__ float g_y   [Sn * Cdim];
__device__ float g_x1  [Sn * Cdim];
__device__ float g_h2  [Sn * Cdim];
__device__ float g_rbf [Sn * CEN];

// ---------------- helpers ----------------
__device__ __forceinline__ float warpsum32(float v) {
#pragma unroll
    for (int o = 16; o >= 1; o >>= 1) v += __shfl_xor_sync(0xffffffffu, v, o);
    return v;
}
__device__ __forceinline__ uint32_t f2tf(float f) {
    uint32_t u;
    asm("cvt.rna.tf32.f32 %0, %1;" : "=r"(u) : "f"(f));
    return u;
}
__device__ __forceinline__ float tfr(float f) {
    return __uint_as_float(f2tf(f));
}
__device__ __forceinline__ void mma8(float* c,
    uint32_t a0, uint32_t a1, uint32_t a2, uint32_t a3, uint32_t b0, uint32_t b1)
{
    asm volatile("mma.sync.aligned.m16n8k8.row.col.f32.tf32.tf32.f32 "
        "{%0,%1,%2,%3}, {%4,%5,%6,%7}, {%8,%9}, {%0,%1,%2,%3};"
        : "+f"(c[0]), "+f"(c[1]), "+f"(c[2]), "+f"(c[3])
        : "r"(a0), "r"(a1), "r"(a2), "r"(a3), "r"(b0), "r"(b1));
}
__device__ __forceinline__ void cp_async16(void* smem, const void* gmem) {
    uint32_t s = (uint32_t)__cvta_generic_to_shared(smem);
    asm volatile("cp.async.cg.shared.global [%0], [%1], 16;\n" :: "r"(s), "l"(gmem));
}
__device__ __forceinline__ void cp_commit() {
    asm volatile("cp.async.commit_group;\n");
}
template<int N>
__device__ __forceinline__ void cp_wait() {
    asm volatile("cp.async.wait_group %0;\n" :: "n"(N));
}

// ---------------- LayerNorm: warp per row, float4 ----------------
template<bool ROUND>
__global__ __launch_bounds__(256) void ln_kernel(
    const float* __restrict__ x, const float* __restrict__ w,
    const float* __restrict__ b, float* __restrict__ out)
{
    const int row  = blockIdx.x * 8 + (threadIdx.x >> 5);
    const int lane = threadIdx.x & 31;
    const float4* xr = (const float4*)(x + (size_t)row * Cdim);
    float4 v[6];
    float s = 0.f, s2 = 0.f;
#pragma unroll
    for (int i = 0; i < 6; i++) {
        v[i] = xr[lane + i * 32];
        s  += v[i].x + v[i].y + v[i].z + v[i].w;
        s2 += v[i].x * v[i].x + v[i].y * v[i].y + v[i].z * v[i].z + v[i].w * v[i].w;
    }
    s = warpsum32(s); s2 = warpsum32(s2);
    const float mu  = s * (1.0f / Cdim);
    const float var = s2 * (1.0f / Cdim) - mu * mu;
    const float rs  = rsqrtf(var + EPSv);
    const float4* w4 = (const float4*)w;
    const float4* b4 = (const float4*)b;
    float4* orow = (float4*)(out + (size_t)row * Cdim);
#pragma unroll
    for (int i = 0; i < 6; i++) {
        const float4 wv = w4[lane + i * 32], bv = b4[lane + i * 32];
        float4 o;
        o.x = (v[i].x - mu) * rs * wv.x + bv.x;
        o.y = (v[i].y - mu) * rs * wv.y + bv.y;
        o.z = (v[i].z - mu) * rs * wv.z + bv.z;
        o.w = (v[i].w - mu) * rs * wv.w + bv.w;
        if (ROUND) { o.x = tfr(o.x); o.y = tfr(o.y); o.z = tfr(o.z); o.w = tfr(o.w); }
        orow[lane + i * 32] = o;
    }
}

// ---------------- round-copy (weights -> tf32-rounded scratch) ----------------
__global__ __launch_bounds__(256) void round_copy_kernel(
    const float* __restrict__ src, float* __restrict__ dst, int n)
{
    for (int i = blockIdx.x * 256 + threadIdx.x; i < n; i += gridDim.x * 256)
        dst[i] = tfr(src[i]);
}

// ---------------- transpose + round M (192x192) ----------------
__global__ __launch_bounds__(256) void transpose_m_kernel(
    const float* __restrict__ M, float* __restrict__ MT)
{
    const int i = blockIdx.x * 256 + threadIdx.x;
    if (i >= HDn * HDn) return;
    const int r = i / HDn, c = i % HDn;
    MT[c * HDn + r] = tfr(M[r * HDn + c]);
}

// ---------------- pipelined tf32 NT GEMM: C = A[M,K] * B[N,K]^T ----------------
// Inputs already tf32-rounded. M%128==0, N%BN==0, K%32==0.
// MODE 0: tf32-rounded store. MODE 1: qkv scatter. MODE 2: +bias+resid fp32 store.
// smem: XOR-swizzled 16B chunks, cp.async double-buffered.
template<int BN, int MODE>
__global__ __launch_bounds__(256) void gemm_pipe(
    const float* __restrict__ A, const float* __restrict__ B, float* __restrict__ Cc,
    float* __restrict__ C2, float* __restrict__ C3,
    int Md, int Nd, int Kd,
    const float* __restrict__ bias, const float* __restrict__ resid)
{
    constexpr int BM = 128, BK = 32;
    constexpr int WM = (BN == 128) ? 2 : 4;
    constexpr int WN = 8 / WM;
    constexpr int WTM = BM / WM, WTN = BN / WN;
    constexpr int MT = WTM / 16, NT = WTN / 8;
    constexpr int ACH = BM * 8;      // float4 chunks per A stage
    constexpr int BCH = BN * 8;

    extern __shared__ __align__(16) float4 smp[];
    float4* As4 = smp;               // 2 stages
    float4* Bs4 = smp + 2 * ACH;

    const int t = threadIdx.x;
    const int wid = t >> 5, lane = t & 31;
    const int wm = wid % WM, wn = wid / WM;
    const int lr4 = lane >> 2, lc4 = lane & 3;
    const int m0 = blockIdx.y * BM, n0 = blockIdx.x * BN;

    const float* Ab = A + (size_t)m0 * Kd;
    const float* Bb = B + (size_t)n0 * Kd;

    auto prefetch = [&](int kt, int st) {
        const float* Ag = Ab + kt * BK;
        const float* Bg = Bb + kt * BK;
#pragma unroll
        for (int i = 0; i < 4; i++) {
            const int ch = t + i * 256;
            const int r = ch >> 3, c = ch & 7;
            cp_async16(&As4[st * ACH + r * 8 + (c ^ (r & 7))], Ag + (size_t)r * Kd + c * 4);
        }
#pragma unroll
        for (int i = 0; i < BN / 32; i++) {
            const int ch = t + i * 256;
            const int r = ch >> 3, c = ch & 7;
            cp_async16(&Bs4[st * BCH + r * 8 + (c ^ (r & 7))], Bg + (size_t)r * Kd + c * 4);
        }
    };

    float acc[MT][NT][4];
#pragma unroll
    for (int i = 0; i < MT; i++)
#pragma unroll
        for (int j = 0; j < NT; j++)
#pragma unroll
            for (int q = 0; q < 4; q++) acc[i][j][q] = 0.f;

    const int nK = Kd / BK;
    prefetch(0, 0);
    cp_commit();

    for (int kt = 0; kt < nK; kt++) {
        __syncthreads();    // all warps done reading buf to be overwritten
        if (kt + 1 < nK) { prefetch(kt + 1, (kt + 1) & 1); cp_commit(); cp_wait<1>(); }
        else             { cp_wait<0>(); }
        __syncthreads();

        const float* Asf = (const float*)(As4 + (kt & 1) * ACH);
        const float* Bsf = (const float*)(Bs4 + (kt & 1) * BCH);

#pragma unroll
        for (int k8 = 0; k8 < BK / 8; k8++) {
            const int c0 = (k8 * 2)     ^ lr4;
            const int c1 = (k8 * 2 + 1) ^ lr4;
            uint32_t bf[NT][2];
#pragma unroll
            for (int nt = 0; nt < NT; nt++) {
                const int nb = wn * WTN + nt * 8 + lr4;
                bf[nt][0] = __float_as_uint(Bsf[(nb * 8 + c0) * 4 + lc4]);
                bf[nt][1] = __float_as_uint(Bsf[(nb * 8 + c1) * 4 + lc4]);
            }
#pragma unroll
            for (int mt = 0; mt < MT; mt++) {
                const int mb = wm * WTM + mt * 16;
                const uint32_t a0 = __float_as_uint(Asf[((mb + lr4)     * 8 + c0) * 4 + lc4]);
                const uint32_t a1 = __float_as_uint(Asf[((mb + lr4 + 8) * 8 + c0) * 4 + lc4]);
                const uint32_t a2 = __float_as_uint(Asf[((mb + lr4)     * 8 + c1) * 4 + lc4]);
                const uint32_t a3 = __float_as_uint(Asf[((mb + lr4 + 8) * 8 + c1) * 4 + lc4]);
#pragma unroll
                for (int nt = 0; nt < NT; nt++)
                    mma8(acc[mt][nt], a0, a1, a2, a3, bf[nt][0], bf[nt][1]);
            }
        }
    }

#pragma unroll
    for (int mt = 0; mt < MT; mt++) {
        const int mbase = m0 + wm * WTM + mt * 16 + lr4;
#pragma unroll
        for (int nt = 0; nt < NT; nt++) {
            const int n = n0 + wn * WTN + nt * 8 + 2 * lc4;
            if (MODE == 0) {
                *(float2*)&Cc[(size_t)mbase * Nd + n] =
                    make_float2(tfr(acc[mt][nt][0]), tfr(acc[mt][nt][1]));
                *(float2*)&Cc[(size_t)(mbase + 8) * Nd + n] =
                    make_float2(tfr(acc[mt][nt][2]), tfr(acc[mt][nt][3]));
            } else if (MODE == 1) {
                const int which = n / Cdim;
                const int rem = n % Cdim;
                const int h = rem / HDn, d = rem % HDn;
                float* dst = (which == 0) ? Cc : (which == 1) ? C2 : C3;
#pragma unroll
                for (int rr = 0; rr < 2; rr++) {
                    const int m = mbase + rr * 8;
                    const int b = m >> 10, nr = m & 1023;
                    const size_t di = ((size_t)((b << 2) + h) * Nn + nr) * HDn + d;
                    *(float2*)&dst[di] = make_float2(tfr(acc[mt][nt][rr * 2]),
                                                     tfr(acc[mt][nt][rr * 2 + 1]));
                }
            } else {
                const float b0 = bias[n], b1 = bias[n + 1];
                const size_t i0 = (size_t)mbase * Nd + n;
                const size_t i1 = (size_t)(mbase + 8) * Nd + n;
                *(float2*)&Cc[i0] = make_float2(acc[mt][nt][0] + b0 + resid[i0],
                                                acc[mt][nt][1] + b1 + resid[i0 + 1]);
                *(float2*)&Cc[i1] = make_float2(acc[mt][nt][2] + b0 + resid[i1],
                                                acc[mt][nt][3] + b1 + resid[i1 + 1]);
            }
        }
    }
}

// ---------------- per-key bias: kb[r] = -scale * dot(K[r], KM[r]) ----------------
__global__ __launch_bounds__(256) void kbias_kernel(
    const float* __restrict__ Kg, const float* __restrict__ KM,
    const float* __restrict__ scale_p, float* __restrict__ kb)
{
    const int gw = (blockIdx.x * 256 + threadIdx.x) >> 5;
    const int lane = threadIdx.x & 31;
    if (gw >= BHn * Nn) return;
    const float* kr  = Kg + (size_t)gw * HDn;
    const float* kmr = KM + (size_t)gw * HDn;
    float s = 0.f;
#pragma unroll
    for (int i = lane; i < HDn; i += 32) s += kr[i] * kmr[i];
    s = warpsum32(s);
    if (lane == 0) kb[gw] = -scale_p[0] * s;
}

// ---------------- tensor-core flash attention (Q in registers, K/V cp.async 2-stage) --
// logits S_ij = 2*scale*(qM_i . k_j) + kb_j
constexpr int QSs = 196;
constexpr int VSs = 200;
constexpr int PSs = 68;
constexpr int KST = 64 * QSs;   // 12544 floats per K stage
constexpr int VST = 64 * VSs;   // 12800
constexpr int ATT_SMEM = (2 * KST + 2 * VST + 64 * PSs + 128 + 128 + 128) * 4;  // 221696

__global__ __launch_bounds__(256, 1) void attn_tc_kernel(
    const float* __restrict__ QM, const float* __restrict__ Kg,
    const float* __restrict__ Vg, const float* __restrict__ kbias,
    const float* __restrict__ scale_p, float* __restrict__ y)
{
    extern __shared__ __align__(16) float sm[];
    float* ks_base  = sm;
    float* vs_base  = sm + 2 * KST;
    float* ps       = vs_base + 2 * VST;
    float* kbt_base = ps + 64 * PSs;
    float* rmax     = kbt_base + 128;
    float* rsum     = rmax + 128;

    const int bh = blockIdx.x, qt = blockIdx.y;
    const int b = bh >> 2, h = bh & 3;
    const int t = threadIdx.x;
    const int wid = t >> 5, lane = t & 31;
    const int wm = wid & 3, wn = wid >> 2;
    const int lr4 = lane >> 2, lc4 = lane & 3;
    const float twoscale = 2.0f * scale_p[0];
    const int r0 = wm * 16;

    auto prefetch = [&](int kt, int st) {
        const float* kg = Kg + ((size_t)bh * Nn + kt * 64) * HDn;
        const float* vg = Vg + ((size_t)bh * Nn + kt * 64) * HDn;
        float* ksb = ks_base + st * KST;
        float* vsb = vs_base + st * VST;
#pragma unroll
        for (int i = 0; i < 12; i++) {
            const int ch = t + i * 256;
            const int r = ch / 48, c = (ch % 48) * 4;
            cp_async16(&ksb[r * QSs + c], kg + r * HDn + c);
            cp_async16(&vsb[r * VSs + c], vg + r * HDn + c);
        }
        if (t < 16) cp_async16(&kbt_base[st * 64 + t * 4],
                               kbias + (size_t)bh * Nn + kt * 64 + t * 4);
    };

    prefetch(0, 0);
    cp_commit();

    // ---- Q fragments into registers (one-time) ----
    float qf[24][4];
    {
        const float* qb = QM + ((size_t)bh * Nn + qt * 64) * HDn;
#pragma unroll
        for (int k8 = 0; k8 < 24; k8++) {
            const int kk = k8 * 8;
            qf[k8][0] = qb[(r0 + lr4)     * HDn + kk + lc4];
            qf[k8][1] = qb[(r0 + lr4 + 8) * HDn + kk + lc4];
            qf[k8][2] = qb[(r0 + lr4)     * HDn + kk + lc4 + 4];
            qf[k8][3] = qb[(r0 + lr4 + 8) * HDn + kk + lc4 + 4];
        }
    }

    float O[12][4];
#pragma unroll
    for (int nt = 0; nt < 12; nt++)
#pragma unroll
        for (int q = 0; q < 4; q++) O[nt][q] = 0.f;
    float mr0 = -1e30f, mr1 = -1e30f, l0 = 0.f, l1 = 0.f;

    for (int kt = 0; kt < Nn / 64; kt++) {
        __syncthreads();    // finish reads of the buffer about to be overwritten
        if (kt + 1 < Nn / 64) { prefetch(kt + 1, (kt + 1) & 1); cp_commit(); cp_wait<1>(); }
        else                  { cp_wait<0>(); }
        __syncthreads();

        const int st = kt & 1;
        const float* ks  = ks_base + st * KST;
        const float* vs  = vs_base + st * VST;
        const float* kbt = kbt_base + st * 64;

        // ---- S = qM_tile @ K_tile^T ----
        float s[4][4];
#pragma unroll
        for (int nt = 0; nt < 4; nt++)
#pragma unroll
            for (int q = 0; q < 4; q++) s[nt][q] = 0.f;
        const int cb = wn * 32;
#pragma unroll
        for (int k8 = 0; k8 < 24; k8++) {
            const int kk = k8 * 8;
            const uint32_t A0 = __float_as_uint(qf[k8][0]);
            const uint32_t A1 = __float_as_uint(qf[k8][1]);
            const uint32_t A2 = __float_as_uint(qf[k8][2]);
            const uint32_t A3 = __float_as_uint(qf[k8][3]);
#pragma unroll
            for (int nt = 0; nt < 4; nt++) {
                const int nb = cb + nt * 8 + lr4;
                const uint32_t B0 = __float_as_uint(ks[nb * QSs + kk + lc4]);
                const uint32_t B1 = __float_as_uint(ks[nb * QSs + kk + lc4 + 4]);
                mma8(s[nt], A0, A1, A2, A3, B0, B1);
            }
        }

        // ---- scale + key bias, partial rowmax ----
        float pm0 = -1e30f, pm1 = -1e30f;
#pragma unroll
        for (int nt = 0; nt < 4; nt++) {
            const int col = cb + nt * 8 + 2 * lc4;
            const float kb0 = kbt[col], kb1 = kbt[col + 1];
            s[nt][0] = fmaf(twoscale, s[nt][0], kb0);
            s[nt][1] = fmaf(twoscale, s[nt][1], kb1);
            s[nt][2] = fmaf(twoscale, s[nt][2], kb0);
            s[nt][3] = fmaf(twoscale, s[nt][3], kb1);
            pm0 = fmaxf(pm0, fmaxf(s[nt][0], s[nt][1]));
            pm1 = fmaxf(pm1, fmaxf(s[nt][2], s[nt][3]));
        }
        pm0 = fmaxf(pm0, __shfl_xor_sync(0xffffffffu, pm0, 1));
        pm0 = fmaxf(pm0, __shfl_xor_sync(0xffffffffu, pm0, 2));
        pm1 = fmaxf(pm1, __shfl_xor_sync(0xffffffffu, pm1, 1));
        pm1 = fmaxf(pm1, __shfl_xor_sync(0xffffffffu, pm1, 2));
        if (lc4 == 0) {
            rmax[wn * 64 + r0 + lr4]     = pm0;
            rmax[wn * 64 + r0 + lr4 + 8] = pm1;
        }
        __syncthreads();
        pm0 = fmaxf(pm0, rmax[(wn ^ 1) * 64 + r0 + lr4]);
        pm1 = fmaxf(pm1, rmax[(wn ^ 1) * 64 + r0 + lr4 + 8]);
        const float mn0 = fmaxf(mr0, pm0), mn1 = fmaxf(mr1, pm1);
        const float cor0 = __expf(mr0 - mn0), cor1 = __expf(mr1 - mn1);
        mr0 = mn0; mr1 = mn1;

        // ---- exp, partial rowsum, P (rounded) -> smem ----
        float q0 = 0.f, q1 = 0.f;
#pragma unroll
        for (int nt = 0; nt < 4; nt++) {
            const int col = cb + nt * 8 + 2 * lc4;
            const float e0 = __expf(s[nt][0] - mn0);
            const float e1 = __expf(s[nt][1] - mn0);
            const float e2 = __expf(s[nt][2] - mn1);
            const float e3 = __expf(s[nt][3] - mn1);
            q0 += e0 + e1; q1 += e2 + e3;
            ps[(r0 + lr4)     * PSs + col]     = tfr(e0);
            ps[(r0 + lr4)     * PSs + col + 1] = tfr(e1);
            ps[(r0 + lr4 + 8) * PSs + col]     = tfr(e2);
            ps[(r0 + lr4 + 8) * PSs + col + 1] = tfr(e3);
        }
        q0 += __shfl_xor_sync(0xffffffffu, q0, 1);
        q0 += __shfl_xor_sync(0xffffffffu, q0, 2);
        q1 += __shfl_xor_sync(0xffffffffu, q1, 1);
        q1 += __shfl_xor_sync(0xffffffffu, q1, 2);
        if (lc4 == 0) {
            rsum[wn * 64 + r0 + lr4]     = q0;
            rsum[wn * 64 + r0 + lr4 + 8] = q1;
        }
#pragma unroll
        for (int nt = 0; nt < 12; nt++) {
            O[nt][0] *= cor0; O[nt][1] *= cor0;
            O[nt][2] *= cor1; O[nt][3] *= cor1;
        }
        __syncthreads();
        l0 = l0 * cor0 + q0 + rsum[(wn ^ 1) * 64 + r0 + lr4];
        l1 = l1 * cor1 + q1 + rsum[(wn ^ 1) * 64 + r0 + lr4 + 8];

        // ---- O += P @ V ----
        const int ob = wn * 96;
#pragma unroll
        for (int k8 = 0; k8 < 8; k8++) {
            const int kk = k8 * 8;
            const uint32_t A0 = __float_as_uint(ps[(r0 + lr4)     * PSs + kk + lc4]);
            const uint32_t A1 = __float_as_uint(ps[(r0 + lr4 + 8) * PSs + kk + lc4]);
            const uint32_t A2 = __float_as_uint(ps[(r0 + lr4)     * PSs + kk + lc4 + 4]);
            const uint32_t A3 = __float_as_uint(ps[(r0 + lr4 + 8) * PSs + kk + lc4 + 4]);
#pragma unroll
            for (int nt = 0; nt < 12; nt++) {
                const int nb = ob + nt * 8 + lr4;
                const uint32_t B0 = __float_as_uint(vs[(kk + lc4)     * VSs + nb]);
                const uint32_t B1 = __float_as_uint(vs[(kk + lc4 + 4) * VSs + nb]);
                mma8(O[nt], A0, A1, A2, A3, B0, B1);
            }
        }
    }

    // ---- normalize + write y (tf32-rounded for proj GEMM) ----
    const float i0v = 1.0f / l0, i1v = 1.0f / l1;
    const int ob = wn * 96;
    const int nrow0 = qt * 64 + r0 + lr4;
    float* y0 = y + (size_t)(b * Nn + nrow0) * Cdim + h * HDn;
    float* y1 = y0 + 8 * Cdim;
#pragma unroll
    for (int nt = 0; nt < 12; nt++) {
        const int col = ob + nt * 8 + 2 * lc4;
        *(float2*)&y0[col] = make_float2(tfr(O[nt][0] * i0v), tfr(O[nt][1] * i0v));
        *(float2*)&y1[col] = make_float2(tfr(O[nt][2] * i1v), tfr(O[nt][3] * i1v));
    }
}

// ---------------- RBF features ----------------
constexpr int RBF_SMEM_BYTES = (CEN * Cdim + CEN) * 4;

__global__ __launch_bounds__(256) void rbf_kernel(
    const float* __restrict__ h2, const float* __restrict__ centers,
    const float* __restrict__ beta, float* __restrict__ rbf)
{
    extern __shared__ __align__(16) float rsm[];
    float* cs = rsm;
    float* cn = rsm + CEN * Cdim;
    const int t = threadIdx.x;
    for (int i = t; i < CEN * Cdim; i += 256) cs[i] = centers[i];
    __syncthreads();
    if (t < CEN) {
        float s = 0.f;
        for (int k = 0; k < Cdim; k++) s += cs[t * Cdim + k] * cs[t * Cdim + k];
        cn[t] = s;
    }
    __syncthreads();
    const int wid = t >> 5, lane = t & 31;
    for (int rr = 0; rr < 8; rr++) {
        const int row = blockIdx.x * 64 + wid * 8 + rr;
        const float* xr = h2 + (size_t)row * Cdim;
        float xv[24];
#pragma unroll
        for (int i = 0; i < 24; i++) xv[i] = xr[lane + i * 32];
        float a = 0.f;
#pragma unroll
        for (int i = 0; i < 24; i++) a += xv[i] * xv[i];
        a = warpsum32(a);
        for (int j = 0; j < CEN; j++) {
            float d = 0.f;
#pragma unroll
            for (int i = 0; i < 24; i++) d += xv[i] * cs[j * Cdim + lane + i * 32];
            d = warpsum32(d);
            if (lane == 0)
                rbf[(size_t)row * CEN + j] = __expf(-beta[j] * (a - 2.0f * d + cn[j]));
        }
    }
}

// ---------------- final: out = x1 + rbf @ fc_w^T ----------------
__global__ __launch_bounds__(256) void final_kernel(
    const float* __restrict__ x1, const float* __restrict__ rbf,
    const float* __restrict__ fcw, float* __restrict__ out)
{
    const int i = blockIdx.x * 256 + threadIdx.x;
    if (i >= Sn * Cdim) return;
    const int c = i % Cdim;
    const int r = i / Cdim;
    const float* rb = rbf + (size_t)r * CEN;
    const float* fw = fcw + (size_t)c * CEN;
    float acc = x1[i];
#pragma unroll
    for (int j = 0; j < CEN; j++) acc += rb[j] * fw[j];
    out[i] = acc;
}

// ---------------- launcher ----------------
extern "C" void kernel_launch(void* const* d_in, const int* in_sizes, int n_in,
                              void* d_out, int out_size)
{
    (void)in_sizes; (void)n_in; (void)out_size;
    const float* x     = (const float*)d_in[0];
    const float* n1w   = (const float*)d_in[1];
    const float* n1b   = (const float*)d_in[2];
    const float* qkvw  = (const float*)d_in[3];
    const float* Mmat  = (const float*)d_in[4];
    const float* scale = (const float*)d_in[5];
    const float* projw = (const float*)d_in[6];
    const float* projb = (const float*)d_in[7];
    const float* n2w   = (const float*)d_in[8];
    const float* n2b   = (const float*)d_in[9];
    const float* cent  = (const float*)d_in[10];
    const float* beta  = (const float*)d_in[11];
    const float* fcw   = (const float*)d_in[12];
    float* out = (float*)d_out;

    float *hP, *qwP, *pwP, *QgP, *KgP, *VgP, *QMP, *KMP, *MTP, *kbP, *yP, *x1P, *h2P, *rbfP;
    cudaGetSymbolAddress((void**)&hP,   g_h);
    cudaGetSymbolAddress((void**)&qwP,  g_qkvwr);
    cudaGetSymbolAddress((void**)&pwP,  g_projwr);
    cudaGetSymbolAddress((void**)&QgP,  g_Qg);
    cudaGetSymbolAddress((void**)&KgP,  g_Kg);
    cudaGetSymbolAddress((void**)&VgP,  g_Vg);
    cudaGetSymbolAddress((void**)&QMP,  g_QM);
    cudaGetSymbolAddress((void**)&KMP,  g_KM);
    cudaGetSymbolAddress((void**)&MTP,  g_MT);
    cudaGetSymbolAddress((void**)&kbP,  g_kb);
    cudaGetSymbolAddress((void**)&yP,   g_y);
    cudaGetSymbolAddress((void**)&x1P,  g_x1);
    cudaGetSymbolAddress((void**)&h2P,  g_h2);
    cudaGetSymbolAddress((void**)&rbfP, g_rbf);

    constexpr int GS128 = 2 * (128 + 128) * 32 * 4;   // 65536 B
    constexpr int GS64  = 2 * (128 + 64) * 32 * 4;    // 49152 B
    cudaFuncSetAttribute(gemm_pipe<128, 1>, cudaFuncAttributeMaxDynamicSharedMemorySize, GS128);
    cudaFuncSetAttribute(gemm_pipe<128, 2>, cudaFuncAttributeMaxDynamicSharedMemorySize, GS128);
    cudaFuncSetAttribute(gemm_pipe<64, 0>,  cudaFuncAttributeMaxDynamicSharedMemorySize, GS64);
    cudaFuncSetAttribute(attn_tc_kernel, cudaFuncAttributeMaxDynamicSharedMemorySize, ATT_SMEM);
    cudaFuncSetAttribute(rbf_kernel, cudaFuncAttributeMaxDynamicSharedMemorySize, RBF_SMEM_BYTES);

    // 0) weight rounding (tf32 copies)
    round_copy_kernel<<<512, 256>>>(qkvw, qwP, 3 * Cdim * Cdim);
    round_copy_kernel<<<512, 256>>>(projw, pwP, Cdim * Cdim);
    transpose_m_kernel<<<(HDn * HDn + 255) / 256, 256>>>(Mmat, MTP);
    // 1) LN1 (rounded)
    ln_kernel<true><<<Sn / 8, 256>>>(x, n1w, n1b, hP);
    // 2) qkv GEMM fused with gather -> Qg/Kg/Vg (rounded)
    gemm_pipe<128, 1><<<dim3(3 * Cdim / 128, Sn / 128), 256, GS128>>>(
        hP, qwP, QgP, KgP, VgP, Sn, 3 * Cdim, Cdim, nullptr, nullptr);
    // 3) qM = Q @ M, kM = K @ M (rounded)
    gemm_pipe<64, 0><<<dim3(HDn / 64, BHn * Nn / 128), 256, GS64>>>(
        QgP, MTP, QMP, nullptr, nullptr, BHn * Nn, HDn, HDn, nullptr, nullptr);
    gemm_pipe<64, 0><<<dim3(HDn / 64, BHn * Nn / 128), 256, GS64>>>(
        KgP, MTP, KMP, nullptr, nullptr, BHn * Nn, HDn, HDn, nullptr, nullptr);
    // 4) per-key bias
    kbias_kernel<<<(BHn * Nn) * 32 / 256, 256>>>(KgP, KMP, scale, kbP);
    // 5) flash attention -> y (rounded)
    attn_tc_kernel<<<dim3(BHn, Nn / 64), 256, ATT_SMEM>>>(QMP, KgP, VgP, kbP, scale, yP);
    // 6) x1 = x + y @ proj_w^T + proj_b
    gemm_pipe<128, 2><<<dim3(Cdim / 128, Sn / 128), 256, GS128>>>(
        yP, pwP, x1P, nullptr, nullptr, Sn, Cdim, Cdim, projb, x);
    // 7) LN2 (full precision)
    ln_kernel<false><<<Sn / 8, 256>>>(x1P, n2w, n2b, h2P);
    // 8) RBF features
    rbf_kernel<<<Sn / 64, 256, RBF_SMEM_BYTES>>>(h2P, cent, beta, rbfP);
    // 9) out = x1 + rbf @ fc_w^T
    final_kernel<<<(Sn * Cdim + 255) / 256, 256>>>(x1P, rbfP, fcw, out);
}

// round 6
// speedup vs baseline: 8.2331x; 1.5254x over previous
#include <cuda_runtime.h>
#include <cuda_fp16.h>
#include <cstdint>

// ---------------- problem constants ----------------
constexpr int Cdim = 768;
constexpr int Bn   = 8;
constexpr int Nn   = 1024;
constexpr int HDn  = 192;            // head dim
constexpr int Sn   = Bn * Nn;        // 8192 rows
constexpr int BHn  = Bn * 4;         // 32
constexpr int CEN  = 20;
constexpr float EPSv = 1e-5f;

// ---------------- scratch (device globals; no allocation allowed) ----------------
__device__ __half g_h     [Sn * Cdim];
__device__ __half g_qkvwr [3 * Cdim * Cdim];
__device__ __half g_projwr[Cdim * Cdim];
__device__ __half g_Qg  [BHn * Nn * HDn];
__device__ __half g_Kg  [BHn * Nn * HDn];
__device__ __half g_Vg  [BHn * Nn * HDn];
__device__ __half g_QM  [BHn * Nn * HDn];
__device__ __half g_KM  [BHn * Nn * HDn];
__device__ __half g_MT  [HDn * HDn];
__device__ float  g_kb  [BHn * Nn];
__device__ __half g_y   [Sn * Cdim];
__device__ float  g_x1  [Sn * Cdim];
__device__ float  g_h2  [Sn * Cdim];
__device__ float  g_rbf [Sn * CEN];

// ---------------- helpers ----------------
__device__ __forceinline__ float warpsum32(float v) {
#pragma unroll
    for (int o = 16; o >= 1; o >>= 1) v += __shfl_xor_sync(0xffffffffu, v, o);
    return v;
}
__device__ __forceinline__ void mma16h(float* c,
    uint32_t a0, uint32_t a1, uint32_t a2, uint32_t a3, uint32_t b0, uint32_t b1)
{
    asm volatile("mma.sync.aligned.m16n8k16.row.col.f32.f16.f16.f32 "
        "{%0,%1,%2,%3}, {%4,%5,%6,%7}, {%8,%9}, {%0,%1,%2,%3};"
        : "+f"(c[0]), "+f"(c[1]), "+f"(c[2]), "+f"(c[3])
        : "r"(a0), "r"(a1), "r"(a2), "r"(a3), "r"(b0), "r"(b1));
}
__device__ __forceinline__ void ldsm4(uint32_t& r0, uint32_t& r1, uint32_t& r2, uint32_t& r3,
                                      uint32_t addr)
{
    asm volatile("ldmatrix.sync.aligned.m8n8.x4.shared.b16 {%0,%1,%2,%3}, [%4];"
        : "=r"(r0), "=r"(r1), "=r"(r2), "=r"(r3) : "r"(addr));
}
__device__ __forceinline__ void ldsm4t(uint32_t& r0, uint32_t& r1, uint32_t& r2, uint32_t& r3,
                                       uint32_t addr)
{
    asm volatile("ldmatrix.sync.aligned.m8n8.x4.trans.shared.b16 {%0,%1,%2,%3}, [%4];"
        : "=r"(r0), "=r"(r1), "=r"(r2), "=r"(r3) : "r"(addr));
}
__device__ __forceinline__ void cp_async16(void* smem, const void* gmem) {
    uint32_t s = (uint32_t)__cvta_generic_to_shared(smem);
    asm volatile("cp.async.cg.shared.global [%0], [%1], 16;\n" :: "r"(s), "l"(gmem));
}
__device__ __forceinline__ void cp_commit() {
    asm volatile("cp.async.commit_group;\n");
}
template<int N>
__device__ __forceinline__ void cp_wait() {
    asm volatile("cp.async.wait_group %0;\n" :: "n"(N));
}

// ---------------- LayerNorm: warp per row, float4; optional half output ----------
template<bool TOHALF>
__global__ __launch_bounds__(256) void ln_kernel(
    const float* __restrict__ x, const float* __restrict__ w,
    const float* __restrict__ b, void* __restrict__ outv)
{
    const int row  = blockIdx.x * 8 + (threadIdx.x >> 5);
    const int lane = threadIdx.x & 31;
    const float4* xr = (const float4*)(x + (size_t)row * Cdim);
    float4 v[6];
    float s = 0.f, s2 = 0.f;
#pragma unroll
    for (int i = 0; i < 6; i++) {
        v[i] = xr[lane + i * 32];
        s  += v[i].x + v[i].y + v[i].z + v[i].w;
        s2 += v[i].x * v[i].x + v[i].y * v[i].y + v[i].z * v[i].z + v[i].w * v[i].w;
    }
    s = warpsum32(s); s2 = warpsum32(s2);
    const float mu  = s * (1.0f / Cdim);
    const float var = s2 * (1.0f / Cdim) - mu * mu;
    const float rs  = rsqrtf(var + EPSv);
    const float4* w4 = (const float4*)w;
    const float4* b4 = (const float4*)b;
#pragma unroll
    for (int i = 0; i < 6; i++) {
        const int idx = lane + i * 32;
        const float4 wv = w4[idx], bv = b4[idx];
        float4 o;
        o.x = (v[i].x - mu) * rs * wv.x + bv.x;
        o.y = (v[i].y - mu) * rs * wv.y + bv.y;
        o.z = (v[i].z - mu) * rs * wv.z + bv.z;
        o.w = (v[i].w - mu) * rs * wv.w + bv.w;
        if (TOHALF) {
            __half* orow = (__half*)outv + (size_t)row * Cdim + 4 * idx;
            *(__half2*)&orow[0] = __floats2half2_rn(o.x, o.y);
            *(__half2*)&orow[2] = __floats2half2_rn(o.z, o.w);
        } else {
            ((float4*)((float*)outv + (size_t)row * Cdim))[idx] = o;
        }
    }
}

// ---------------- f32 -> f16 copy ----------------
__global__ __launch_bounds__(256) void half_copy_kernel(
    const float* __restrict__ src, __half* __restrict__ dst, int n)
{
    for (int i = blockIdx.x * 256 + threadIdx.x; i < n; i += gridDim.x * 256)
        dst[i] = __float2half(src[i]);
}

// ---------------- transpose + convert M (192x192) ----------------
__global__ __launch_bounds__(256) void transpose_m_kernel(
    const float* __restrict__ M, __half* __restrict__ MT)
{
    const int i = blockIdx.x * 256 + threadIdx.x;
    if (i >= HDn * HDn) return;
    const int r = i / HDn, c = i % HDn;
    MT[c * HDn + r] = __float2half(M[r * HDn + c]);
}

// ---------------- pipelined fp16 NT GEMM: C = A[M,K] * B[N,K]^T ----------------
// A,B half. M%128==0, N%BN==0, K%64==0.
// MODE 0: half store to Cc. MODE 1: qkv scatter -> Cc(Q),C2(K),C3(V) half, [BH][N][HD].
// MODE 2: fp32 store to Cc with +bias +resid.
// smem: [row][8 chunks of 8 halfs], chunk swizzle c ^ (r&7), cp.async 2-stage.
template<int BN, int MODE>
__global__ __launch_bounds__(256) void gemm_h(
    const __half* __restrict__ A, const __half* __restrict__ B, void* __restrict__ Cv,
    __half* __restrict__ C2, __half* __restrict__ C3,
    int Md, int Nd, int Kd,
    const float* __restrict__ bias, const float* __restrict__ resid)
{
    (void)Md;
    constexpr int BM = 128, BK = 64;
    constexpr int WM = (BN == 128) ? 2 : 4;
    constexpr int WN = 8 / WM;
    constexpr int WTM = BM / WM, WTN = BN / WN;
    constexpr int MT = WTM / 16, NT = WTN / 8;
    constexpr int ASTG = BM * BK;    // halfs per A stage
    constexpr int BSTG = BN * BK;

    extern __shared__ __align__(16) __half smh[];
    __half* As = smh;
    __half* Bs = smh + 2 * ASTG;

    const int t = threadIdx.x;
    const int wid = t >> 5, lane = t & 31;
    const int wm = wid % WM, wn = wid / WM;
    const int lr4 = lane >> 2, lc4 = lane & 3;
    const int g8 = lane >> 3, l8 = lane & 7;
    const int m0 = blockIdx.y * BM, n0 = blockIdx.x * BN;

    const __half* Ab = A + (size_t)m0 * Kd;
    const __half* Bb = B + (size_t)n0 * Kd;

    auto prefetch = [&](int kt, int st) {
        const __half* Ag = Ab + kt * BK;
        const __half* Bg = Bb + kt * BK;
#pragma unroll
        for (int i = 0; i < BM / 32; i++) {
            const int ch = t + i * 256;
            const int r = ch >> 3, c = ch & 7;
            cp_async16(&As[st * ASTG + (r * 8 + (c ^ (r & 7))) * 8], Ag + (size_t)r * Kd + c * 8);
        }
#pragma unroll
        for (int i = 0; i < BN / 32; i++) {
            const int ch = t + i * 256;
            const int r = ch >> 3, c = ch & 7;
            cp_async16(&Bs[st * BSTG + (r * 8 + (c ^ (r & 7))) * 8], Bg + (size_t)r * Kd + c * 8);
        }
    };

    float acc[MT][NT][4];
#pragma unroll
    for (int i = 0; i < MT; i++)
#pragma unroll
        for (int j = 0; j < NT; j++)
#pragma unroll
            for (int q = 0; q < 4; q++) acc[i][j][q] = 0.f;

    const int nK = Kd / BK;
    prefetch(0, 0);
    cp_commit();

    for (int kt = 0; kt < nK; kt++) {
        __syncthreads();
        if (kt + 1 < nK) { prefetch(kt + 1, (kt + 1) & 1); cp_commit(); cp_wait<1>(); }
        else             { cp_wait<0>(); }
        __syncthreads();

        const uint32_t Au = (uint32_t)__cvta_generic_to_shared(As + (kt & 1) * ASTG);
        const uint32_t Bu = (uint32_t)__cvta_generic_to_shared(Bs + (kt & 1) * BSTG);

#pragma unroll
        for (int k16 = 0; k16 < BK / 16; k16++) {
            uint32_t bf[NT][2];
#pragma unroll
            for (int p = 0; p < NT / 2; p++) {
                const int row = wn * WTN + p * 16 + (g8 >> 1) * 8 + l8;
                const int ch  = (2 * k16 + (g8 & 1)) ^ l8;
                ldsm4(bf[2 * p][0], bf[2 * p][1], bf[2 * p + 1][0], bf[2 * p + 1][1],
                      Bu + (row * 8 + ch) * 16);
            }
#pragma unroll
            for (int mt = 0; mt < MT; mt++) {
                const int rowA = wm * WTM + mt * 16 + (g8 & 1) * 8 + l8;
                const int chA  = (2 * k16 + (g8 >> 1)) ^ l8;
                uint32_t a0, a1, a2, a3;
                ldsm4(a0, a1, a2, a3, Au + (rowA * 8 + chA) * 16);
#pragma unroll
                for (int nt = 0; nt < NT; nt++)
                    mma16h(acc[mt][nt], a0, a1, a2, a3, bf[nt][0], bf[nt][1]);
            }
        }
    }

#pragma unroll
    for (int mt = 0; mt < MT; mt++) {
        const int mbase = m0 + wm * WTM + mt * 16 + lr4;
#pragma unroll
        for (int nt = 0; nt < NT; nt++) {
            const int n = n0 + wn * WTN + nt * 8 + 2 * lc4;
            if (MODE == 0) {
                __half* C = (__half*)Cv;
                *(__half2*)&C[(size_t)mbase * Nd + n] =
                    __floats2half2_rn(acc[mt][nt][0], acc[mt][nt][1]);
                *(__half2*)&C[(size_t)(mbase + 8) * Nd + n] =
                    __floats2half2_rn(acc[mt][nt][2], acc[mt][nt][3]);
            } else if (MODE == 1) {
                const int which = n / Cdim;
                const int rem = n % Cdim;
                const int h = rem / HDn, d = rem % HDn;
                __half* dst = (which == 0) ? (__half*)Cv : (which == 1) ? C2 : C3;
#pragma unroll
                for (int rr = 0; rr < 2; rr++) {
                    const int m = mbase + rr * 8;
                    const int b = m >> 10, nr = m & 1023;
                    const size_t di = ((size_t)((b << 2) + h) * Nn + nr) * HDn + d;
                    *(__half2*)&dst[di] =
                        __floats2half2_rn(acc[mt][nt][rr * 2], acc[mt][nt][rr * 2 + 1]);
                }
            } else {
                float* C = (float*)Cv;
                const float b0 = bias[n], b1 = bias[n + 1];
                const size_t i0 = (size_t)mbase * Nd + n;
                const size_t i1 = (size_t)(mbase + 8) * Nd + n;
                *(float2*)&C[i0] = make_float2(acc[mt][nt][0] + b0 + resid[i0],
                                               acc[mt][nt][1] + b1 + resid[i0 + 1]);
                *(float2*)&C[i1] = make_float2(acc[mt][nt][2] + b0 + resid[i1],
                                               acc[mt][nt][3] + b1 + resid[i1 + 1]);
            }
        }
    }
}

// ---------------- per-key bias: kb[r] = -scale * dot(K[r], KM[r]) ----------------
__global__ __launch_bounds__(256) void kbias_kernel(
    const __half* __restrict__ Kg, const __half* __restrict__ KM,
    const float* __restrict__ scale_p, float* __restrict__ kb)
{
    const int gw = (blockIdx.x * 256 + threadIdx.x) >> 5;
    const int lane = threadIdx.x & 31;
    if (gw >= BHn * Nn) return;
    const __half2* kr  = (const __half2*)(Kg + (size_t)gw * HDn);
    const __half2* kmr = (const __half2*)(KM + (size_t)gw * HDn);
    float s = 0.f;
#pragma unroll
    for (int i = 0; i < 3; i++) {
        const float2 a = __half22float2(kr[lane + i * 32]);
        const float2 b = __half22float2(kmr[lane + i * 32]);
        s += a.x * b.x + a.y * b.y;
    }
    s = warpsum32(s);
    if (lane == 0) kb[gw] = -scale_p[0] * s;
}

// ---------------- fp16 tensor-core flash attention ----------------
// logits S_ij = 2*scale*(qM_i . k_j) + kb_j   (qMq cancels in softmax)
// Q frags in registers; K/V half tiles double-buffered via cp.async;
// fragment loads via ldmatrix (V via .trans).
constexpr int KSs = 200;        // K/V smem stride (halfs); 400 B rows, conflict-free
constexpr int PSs = 72;         // P smem stride (halfs)
constexpr int KVST = 64 * KSs;  // halfs per stage (12800)
constexpr int ATT_SMEM = (2 * KVST + 2 * KVST + 64 * PSs) * 2 + (128 + 128 + 128) * 4; // 113152

__global__ __launch_bounds__(256, 1) void attn_tc_kernel(
    const __half* __restrict__ QM, const __half* __restrict__ Kg,
    const __half* __restrict__ Vg, const float* __restrict__ kbias,
    const float* __restrict__ scale_p, __half* __restrict__ y)
{
    extern __shared__ __align__(16) __half smha[];
    __half* ks_base = smha;                       // 2 stages
    __half* vs_base = smha + 2 * KVST;            // 2 stages
    __half* ps      = smha + 4 * KVST;            // [64][72]
    float* kbt_base = (float*)(smha + 4 * KVST + 64 * PSs);
    float* rmax     = kbt_base + 128;
    float* rsum     = rmax + 128;

    const int bh = blockIdx.x, qt = blockIdx.y;
    const int b = bh >> 2, h = bh & 3;
    const int t = threadIdx.x;
    const int wid = t >> 5, lane = t & 31;
    const int wm = wid & 3, wn = wid >> 2;        // 4 row-groups x 2 col-groups
    const int lr4 = lane >> 2, lc4 = lane & 3;
    const int g8 = lane >> 3, l8 = lane & 7;
    const float twoscale = 2.0f * scale_p[0];
    const int r0 = wm * 16;

    auto prefetch = [&](int kt, int st) {
        const __half* kg = Kg + ((size_t)bh * Nn + kt * 64) * HDn;
        const __half* vg = Vg + ((size_t)bh * Nn + kt * 64) * HDn;
        __half* ksb = ks_base + st * KVST;
        __half* vsb = vs_base + st * KVST;
#pragma unroll
        for (int i = 0; i < 6; i++) {
            const int ch = t + i * 256;
            const int r = ch / 24, c = ch % 24;
            cp_async16(&ksb[r * KSs + c * 8], kg + r * HDn + c * 8);
            cp_async16(&vsb[r * KSs + c * 8], vg + r * HDn + c * 8);
        }
        if (t < 16) cp_async16(&kbt_base[st * 64 + t * 4],
                               kbias + (size_t)bh * Nn + kt * 64 + t * 4);
    };

    prefetch(0, 0);
    cp_commit();

    // ---- Q fragments (half2) into registers (one-time) ----
    uint32_t qa[12][4];
    {
        const __half* qb = QM + ((size_t)bh * Nn + qt * 64) * HDn;
#pragma unroll
        for (int k16 = 0; k16 < 12; k16++) {
            const int kk = k16 * 16;
            qa[k16][0] = *(const uint32_t*)&qb[(r0 + lr4)     * HDn + kk + 2 * lc4];
            qa[k16][1] = *(const uint32_t*)&qb[(r0 + lr4 + 8) * HDn + kk + 2 * lc4];
            qa[k16][2] = *(const uint32_t*)&qb[(r0 + lr4)     * HDn + kk + 8 + 2 * lc4];
            qa[k16][3] = *(const uint32_t*)&qb[(r0 + lr4 + 8) * HDn + kk + 8 + 2 * lc4];
        }
    }

    float O[12][4];
#pragma unroll
    for (int nt = 0; nt < 12; nt++)
#pragma unroll
        for (int q = 0; q < 4; q++) O[nt][q] = 0.f;
    float mr0 = -1e30f, mr1 = -1e30f, l0 = 0.f, l1 = 0.f;

    const int cb = wn * 32;
    const int ob = wn * 96;

    for (int kt = 0; kt < Nn / 64; kt++) {
        __syncthreads();
        if (kt + 1 < Nn / 64) { prefetch(kt + 1, (kt + 1) & 1); cp_commit(); cp_wait<1>(); }
        else                  { cp_wait<0>(); }
        __syncthreads();

        const int st = kt & 1;
        const uint32_t ks_u = (uint32_t)__cvta_generic_to_shared(ks_base + st * KVST);
        const uint32_t vs_u = (uint32_t)__cvta_generic_to_shared(vs_base + st * KVST);
        const float* kbt = kbt_base + st * 64;

        // ---- S = qM_tile @ K_tile^T ----
        float s[4][4];
#pragma unroll
        for (int nt = 0; nt < 4; nt++)
#pragma unroll
            for (int q = 0; q < 4; q++) s[nt][q] = 0.f;
#pragma unroll
        for (int k16 = 0; k16 < 12; k16++) {
            const int kk = k16 * 16;
            uint32_t bf[4][2];
#pragma unroll
            for (int p = 0; p < 2; p++) {
                const int row = cb + p * 16 + (g8 >> 1) * 8 + l8;
                const int col = kk + (g8 & 1) * 8;
                ldsm4(bf[2 * p][0], bf[2 * p][1], bf[2 * p + 1][0], bf[2 * p + 1][1],
                      ks_u + (row * KSs + col) * 2);
            }
#pragma unroll
            for (int nt = 0; nt < 4; nt++)
                mma16h(s[nt], qa[k16][0], qa[k16][1], qa[k16][2], qa[k16][3],
                       bf[nt][0], bf[nt][1]);
        }

        // ---- scale + key bias, partial rowmax ----
        float pm0 = -1e30f, pm1 = -1e30f;
#pragma unroll
        for (int nt = 0; nt < 4; nt++) {
            const int col = cb + nt * 8 + 2 * lc4;
            const float kb0 = kbt[col], kb1 = kbt[col + 1];
            s[nt][0] = fmaf(twoscale, s[nt][0], kb0);
            s[nt][1] = fmaf(twoscale, s[nt][1], kb1);
            s[nt][2] = fmaf(twoscale, s[nt][2], kb0);
            s[nt][3] = fmaf(twoscale, s[nt][3], kb1);
            pm0 = fmaxf(pm0, fmaxf(s[nt][0], s[nt][1]));
            pm1 = fmaxf(pm1, fmaxf(s[nt][2], s[nt][3]));
        }
        pm0 = fmaxf(pm0, __shfl_xor_sync(0xffffffffu, pm0, 1));
        pm0 = fmaxf(pm0, __shfl_xor_sync(0xffffffffu, pm0, 2));
        pm1 = fmaxf(pm1, __shfl_xor_sync(0xffffffffu, pm1, 1));
        pm1 = fmaxf(pm1, __shfl_xor_sync(0xffffffffu, pm1, 2));
        if (lc4 == 0) {
            rmax[wn * 64 + r0 + lr4]     = pm0;
            rmax[wn * 64 + r0 + lr4 + 8] = pm1;
        }
        __syncthreads();
        pm0 = fmaxf(pm0, rmax[(wn ^ 1) * 64 + r0 + lr4]);
        pm1 = fmaxf(pm1, rmax[(wn ^ 1) * 64 + r0 + lr4 + 8]);
        const float mn0 = fmaxf(mr0, pm0), mn1 = fmaxf(mr1, pm1);
        const float cor0 = __expf(mr0 - mn0), cor1 = __expf(mr1 - mn1);
        mr0 = mn0; mr1 = mn1;

        // ---- exp, partial rowsum, P (half) -> smem ----
        float q0 = 0.f, q1 = 0.f;
#pragma unroll
        for (int nt = 0; nt < 4; nt++) {
            const int col = cb + nt * 8 + 2 * lc4;
            const float e0 = __expf(s[nt][0] - mn0);
            const float e1 = __expf(s[nt][1] - mn0);
            const float e2 = __expf(s[nt][2] - mn1);
            const float e3 = __expf(s[nt][3] - mn1);
            q0 += e0 + e1; q1 += e2 + e3;
            *(__half2*)&ps[(r0 + lr4)     * PSs + col] = __floats2half2_rn(e0, e1);
            *(__half2*)&ps[(r0 + lr4 + 8) * PSs + col] = __floats2half2_rn(e2, e3);
        }
        q0 += __shfl_xor_sync(0xffffffffu, q0, 1);
        q0 += __shfl_xor_sync(0xffffffffu, q0, 2);
        q1 += __shfl_xor_sync(0xffffffffu, q1, 1);
        q1 += __shfl_xor_sync(0xffffffffu, q1, 2);
        if (lc4 == 0) {
            rsum[wn * 64 + r0 + lr4]     = q0;
            rsum[wn * 64 + r0 + lr4 + 8] = q1;
        }
#pragma unroll
        for (int nt = 0; nt < 12; nt++) {
            O[nt][0] *= cor0; O[nt][1] *= cor0;
            O[nt][2] *= cor1; O[nt][3] *= cor1;
        }
        __syncthreads();
        l0 = l0 * cor0 + q0 + rsum[(wn ^ 1) * 64 + r0 + lr4];
        l1 = l1 * cor1 + q1 + rsum[(wn ^ 1) * 64 + r0 + lr4 + 8];

        // ---- O += P @ V (P via ldmatrix, V via ldmatrix.trans) ----
        const uint32_t ps_u = (uint32_t)__cvta_generic_to_shared(ps);
#pragma unroll
        for (int k16 = 0; k16 < 4; k16++) {
            const int kk = k16 * 16;
            uint32_t A0, A1, A2, A3;
            {
                const int rowp = r0 + (g8 & 1) * 8 + l8;
                const int colp = kk + (g8 >> 1) * 8;
                ldsm4(A0, A1, A2, A3, ps_u + (rowp * PSs + colp) * 2);
            }
#pragma unroll
            for (int p = 0; p < 6; p++) {
                const int rowv = kk + (g8 & 1) * 8 + l8;
                const int colv = ob + p * 16 + (g8 >> 1) * 8;
                uint32_t b0A, b1A, b0B, b1B;
                ldsm4t(b0A, b1A, b0B, b1B, vs_u + (rowv * KSs + colv) * 2);
                mma16h(O[2 * p],     A0, A1, A2, A3, b0A, b1A);
                mma16h(O[2 * p + 1], A0, A1, A2, A3, b0B, b1B);
            }
        }
    }

    // ---- normalize + write y (half, for proj GEMM) ----
    const float i0v = 1.0f / l0, i1v = 1.0f / l1;
    const int nrow0 = qt * 64 + r0 + lr4;
    __half* y0 = y + (size_t)(b * Nn + nrow0) * Cdim + h * HDn;
    __half* y1 = y0 + 8 * Cdim;
#pragma unroll
    for (int nt = 0; nt < 12; nt++) {
        const int col = ob + nt * 8 + 2 * lc4;
        *(__half2*)&y0[col] = __floats2half2_rn(O[nt][0] * i0v, O[nt][1] * i0v);
        *(__half2*)&y1[col] = __floats2half2_rn(O[nt][2] * i1v, O[nt][3] * i1v);
    }
}

// ---------------- RBF features ----------------
constexpr int RBF_SMEM_BYTES = (CEN * Cdim + CEN) * 4;

__global__ __launch_bounds__(256) void rbf_kernel(
    const float* __restrict__ h2, const float* __restrict__ centers,
    const float* __restrict__ beta, float* __restrict__ rbf)
{
    extern __shared__ __align__(16) float rsm[];
    float* cs = rsm;
    float* cn = rsm + CEN * Cdim;
    const int t = threadIdx.x;
    for (int i = t; i < CEN * Cdim; i += 256) cs[i] = centers[i];
    __syncthreads();
    if (t < CEN) {
        float s = 0.f;
        for (int k = 0; k < Cdim; k++) s += cs[t * Cdim + k] * cs[t * Cdim + k];
        cn[t] = s;
    }
    __syncthreads();
    const int wid = t >> 5, lane = t & 31;
    for (int rr = 0; rr < 8; rr++) {
        const int row = blockIdx.x * 64 + wid * 8 + rr;
        const float* xr = h2 + (size_t)row * Cdim;
        float xv[24];
#pragma unroll
        for (int i = 0; i < 24; i++) xv[i] = xr[lane + i * 32];
        float a = 0.f;
#pragma unroll
        for (int i = 0; i < 24; i++) a += xv[i] * xv[i];
        a = warpsum32(a);
        for (int j = 0; j < CEN; j++) {
            float d = 0.f;
#pragma unroll
            for (int i = 0; i < 24; i++) d += xv[i] * cs[j * Cdim + lane + i * 32];
            d = warpsum32(d);
            if (lane == 0)
                rbf[(size_t)row * CEN + j] = __expf(-beta[j] * (a - 2.0f * d + cn[j]));
        }
    }
}

// ---------------- final: out = x1 + rbf @ fc_w^T ----------------
__global__ __launch_bounds__(256) void final_kernel(
    const float* __restrict__ x1, const float* __restrict__ rbf,
    const float* __restrict__ fcw, float* __restrict__ out)
{
    const int i = blockIdx.x * 256 + threadIdx.x;
    if (i >= Sn * Cdim) return;
    const int c = i % Cdim;
    const int r = i / Cdim;
    const float* rb = rbf + (size_t)r * CEN;
    const float* fw = fcw + (size_t)c * CEN;
    float acc = x1[i];
#pragma unroll
    for (int j = 0; j < CEN; j++) acc += rb[j] * fw[j];
    out[i] = acc;
}

// ---------------- launcher ----------------
extern "C" void kernel_launch(void* const* d_in, const int* in_sizes, int n_in,
                              void* d_out, int out_size)
{
    (void)in_sizes; (void)n_in; (void)out_size;
    const float* x     = (const float*)d_in[0];
    const float* n1w   = (const float*)d_in[1];
    const float* n1b   = (const float*)d_in[2];
    const float* qkvw  = (const float*)d_in[3];
    const float* Mmat  = (const float*)d_in[4];
    const float* scale = (const float*)d_in[5];
    const float* projw = (const float*)d_in[6];
    const float* projb = (const float*)d_in[7];
    const float* n2w   = (const float*)d_in[8];
    const float* n2b   = (const float*)d_in[9];
    const float* cent  = (const float*)d_in[10];
    const float* beta  = (const float*)d_in[11];
    const float* fcw   = (const float*)d_in[12];
    float* out = (float*)d_out;

    __half *hP, *qwP, *pwP, *QgP, *KgP, *VgP, *QMP, *KMP, *MTP, *yP;
    float *kbP, *x1P, *h2P, *rbfP;
    cudaGetSymbolAddress((void**)&hP,   g_h);
    cudaGetSymbolAddress((void**)&qwP,  g_qkvwr);
    cudaGetSymbolAddress((void**)&pwP,  g_projwr);
    cudaGetSymbolAddress((void**)&QgP,  g_Qg);
    cudaGetSymbolAddress((void**)&KgP,  g_Kg);
    cudaGetSymbolAddress((void**)&VgP,  g_Vg);
    cudaGetSymbolAddress((void**)&QMP,  g_QM);
    cudaGetSymbolAddress((void**)&KMP,  g_KM);
    cudaGetSymbolAddress((void**)&MTP,  g_MT);
    cudaGetSymbolAddress((void**)&kbP,  g_kb);
    cudaGetSymbolAddress((void**)&yP,   g_y);
    cudaGetSymbolAddress((void**)&x1P,  g_x1);
    cudaGetSymbolAddress((void**)&h2P,  g_h2);
    cudaGetSymbolAddress((void**)&rbfP, g_rbf);

    constexpr int GS128 = 2 * (128 + 128) * 64 * 2;   // 65536 B
    constexpr int GS64  = 2 * (128 + 64) * 64 * 2;    // 49152 B
    cudaFuncSetAttribute(gemm_h<128, 1>, cudaFuncAttributeMaxDynamicSharedMemorySize, GS128);
    cudaFuncSetAttribute(gemm_h<128, 2>, cudaFuncAttributeMaxDynamicSharedMemorySize, GS128);
    cudaFuncSetAttribute(gemm_h<64, 0>,  cudaFuncAttributeMaxDynamicSharedMemorySize, GS64);
    cudaFuncSetAttribute(attn_tc_kernel, cudaFuncAttributeMaxDynamicSharedMemorySize, ATT_SMEM);
    cudaFuncSetAttribute(rbf_kernel, cudaFuncAttributeMaxDynamicSharedMemorySize, RBF_SMEM_BYTES);

    // 0) weight conversion (fp16 copies)
    half_copy_kernel<<<512, 256>>>(qkvw, qwP, 3 * Cdim * Cdim);
    half_copy_kernel<<<512, 256>>>(projw, pwP, Cdim * Cdim);
    transpose_m_kernel<<<(HDn * HDn + 255) / 256, 256>>>(Mmat, MTP);
    // 1) LN1 (half out)
    ln_kernel<true><<<Sn / 8, 256>>>(x, n1w, n1b, hP);
    // 2) qkv GEMM fused with gather -> Qg/Kg/Vg (half)
    gemm_h<128, 1><<<dim3(3 * Cdim / 128, Sn / 128), 256, GS128>>>(
        hP, qwP, QgP, KgP, VgP, Sn, 3 * Cdim, Cdim, nullptr, nullptr);
    // 3) qM = Q @ M, kM = K @ M (half out)
    gemm_h<64, 0><<<dim3(HDn / 64, BHn * Nn / 128), 256, GS64>>>(
        QgP, MTP, QMP, nullptr, nullptr, BHn * Nn, HDn, HDn, nullptr, nullptr);
    gemm_h<64, 0><<<dim3(HDn / 64, BHn * Nn / 128), 256, GS64>>>(
        KgP, MTP, KMP, nullptr, nullptr, BHn * Nn, HDn, HDn, nullptr, nullptr);
    // 4) per-key bias
    kbias_kernel<<<(BHn * Nn) * 32 / 256, 256>>>(KgP, KMP, scale, kbP);
    // 5) fp16 flash attention -> y (half)
    attn_tc_kernel<<<dim3(BHn, Nn / 64), 256, ATT_SMEM>>>(QMP, KgP, VgP, kbP, scale, yP);
    // 6) x1 = x + y @ proj_w^T + proj_b (fp32 out)
    gemm_h<128, 2><<<dim3(Cdim / 128, Sn / 128), 256, GS128>>>(
        yP, pwP, x1P, nullptr, nullptr, Sn, Cdim, Cdim, projb, x);
    // 7) LN2 (fp32 out)
    ln_kernel<false><<<Sn / 8, 256>>>(x1P, n2w, n2b, h2P);
    // 8) RBF features
    rbf_kernel<<<Sn / 64, 256, RBF_SMEM_BYTES>>>(h2P, cent, beta, rbfP);
    // 9) out = x1 + rbf @ fc_w^T
    final_kernel<<<(Sn * Cdim + 255) / 256, 256>>>(x1P, rbfP, fcw, out);
}

// round 8
// speedup vs baseline: 8.9909x; 1.0920x over previous
#include <cuda_runtime.h>
#include <cuda_fp16.h>
#include <cstdint>

// ---------------- problem constants ----------------
constexpr int Cdim = 768;
constexpr int Bn   = 8;
constexpr int Nn   = 1024;
constexpr int HDn  = 192;            // head dim
constexpr int Sn   = Bn * Nn;        // 8192 rows
constexpr int BHn  = Bn * 4;         // 32
constexpr int CEN  = 20;
constexpr float EPSv = 1e-5f;

// ---------------- scratch (device globals; no allocation allowed) ----------------
__device__ __half g_h     [Sn * Cdim];
__device__ __half g_qkvwr [3 * Cdim * Cdim];
__device__ __half g_projwr[Cdim * Cdim];
__device__ __half g_Qg  [BHn * Nn * HDn];
__device__ __half g_Kg  [BHn * Nn * HDn];
__device__ __half g_Vg  [BHn * Nn * HDn];
__device__ __half g_QM  [BHn * Nn * HDn];
__device__ __half g_KM  [BHn * Nn * HDn];
__device__ __half g_MT  [HDn * HDn];
__device__ float  g_kb  [BHn * Nn];
__device__ __half g_y   [Sn * Cdim];
__device__ float  g_x1  [Sn * Cdim];
__device__ float  g_rbf [Sn * CEN];

// ---------------- helpers ----------------
__device__ __forceinline__ float warpsum32(float v) {
#pragma unroll
    for (int o = 16; o >= 1; o >>= 1) v += __shfl_xor_sync(0xffffffffu, v, o);
    return v;
}
__device__ __forceinline__ uint32_t h2u(__half2 h) {
    return *reinterpret_cast<uint32_t*>(&h);
}
__device__ __forceinline__ void mma16h(float* c,
    uint32_t a0, uint32_t a1, uint32_t a2, uint32_t a3, uint32_t b0, uint32_t b1)
{
    asm volatile("mma.sync.aligned.m16n8k16.row.col.f32.f16.f16.f32 "
        "{%0,%1,%2,%3}, {%4,%5,%6,%7}, {%8,%9}, {%0,%1,%2,%3};"
        : "+f"(c[0]), "+f"(c[1]), "+f"(c[2]), "+f"(c[3])
        : "r"(a0), "r"(a1), "r"(a2), "r"(a3), "r"(b0), "r"(b1));
}
__device__ __forceinline__ void ldsm4(uint32_t& r0, uint32_t& r1, uint32_t& r2, uint32_t& r3,
                                      uint32_t addr)
{
    asm volatile("ldmatrix.sync.aligned.m8n8.x4.shared.b16 {%0,%1,%2,%3}, [%4];"
        : "=r"(r0), "=r"(r1), "=r"(r2), "=r"(r3) : "r"(addr));
}
__device__ __forceinline__ void ldsm4t(uint32_t& r0, uint32_t& r1, uint32_t& r2, uint32_t& r3,
                                       uint32_t addr)
{
    asm volatile("ldmatrix.sync.aligned.m8n8.x4.trans.shared.b16 {%0,%1,%2,%3}, [%4];"
        : "=r"(r0), "=r"(r1), "=r"(r2), "=r"(r3) : "r"(addr));
}
__device__ __forceinline__ void cp_async16(void* smem, const void* gmem) {
    uint32_t s = (uint32_t)__cvta_generic_to_shared(smem);
    asm volatile("cp.async.cg.shared.global [%0], [%1], 16;\n" :: "r"(s), "l"(gmem));
}
__device__ __forceinline__ void cp_commit() {
    asm volatile("cp.async.commit_group;\n");
}
template<int N>
__device__ __forceinline__ void cp_wait() {
    asm volatile("cp.async.wait_group %0;\n" :: "n"(N));
}

// ---------------- LayerNorm (LN1): warp per row, half output ----------------
__global__ __launch_bounds__(256) void ln1_kernel(
    const float* __restrict__ x, const float* __restrict__ w,
    const float* __restrict__ b, __half* __restrict__ out)
{
    const int row  = blockIdx.x * 8 + (threadIdx.x >> 5);
    const int lane = threadIdx.x & 31;
    const float4* xr = (const float4*)(x + (size_t)row * Cdim);
    float4 v[6];
    float s = 0.f, s2 = 0.f;
#pragma unroll
    for (int i = 0; i < 6; i++) {
        v[i] = xr[lane + i * 32];
        s  += v[i].x + v[i].y + v[i].z + v[i].w;
        s2 += v[i].x * v[i].x + v[i].y * v[i].y + v[i].z * v[i].z + v[i].w * v[i].w;
    }
    s = warpsum32(s); s2 = warpsum32(s2);
    const float mu  = s * (1.0f / Cdim);
    const float var = s2 * (1.0f / Cdim) - mu * mu;
    const float rs  = rsqrtf(var + EPSv);
    const float4* w4 = (const float4*)w;
    const float4* b4 = (const float4*)b;
#pragma unroll
    for (int i = 0; i < 6; i++) {
        const int idx = lane + i * 32;
        const float4 wv = w4[idx], bv = b4[idx];
        __half* orow = out + (size_t)row * Cdim + 4 * idx;
        *(__half2*)&orow[0] = __floats2half2_rn((v[i].x - mu) * rs * wv.x + bv.x,
                                                (v[i].y - mu) * rs * wv.y + bv.y);
        *(__half2*)&orow[2] = __floats2half2_rn((v[i].z - mu) * rs * wv.z + bv.z,
                                                (v[i].w - mu) * rs * wv.w + bv.w);
    }
}

// ---------------- f32 -> f16 copy ----------------
__global__ __launch_bounds__(256) void half_copy_kernel(
    const float* __restrict__ src, __half* __restrict__ dst, int n)
{
    for (int i = blockIdx.x * 256 + threadIdx.x; i < n; i += gridDim.x * 256)
        dst[i] = __float2half(src[i]);
}

// ---------------- transpose + convert M (192x192) ----------------
__global__ __launch_bounds__(256) void transpose_m_kernel(
    const float* __restrict__ M, __half* __restrict__ MT)
{
    const int i = blockIdx.x * 256 + threadIdx.x;
    if (i >= HDn * HDn) return;
    const int r = i / HDn, c = i % HDn;
    MT[c * HDn + r] = __float2half(M[r * HDn + c]);
}

// ---------------- pipelined fp16 NT GEMM: C = A[M,K] * B[N,K]^T ----------------
// MODE 0: half store. MODE 1: qkv scatter -> Q/K/V half [BH][N][HD]. MODE 2: fp32 +bias+resid.
template<int BN, int MODE>
__global__ __launch_bounds__(256) void gemm_h(
    const __half* __restrict__ A, const __half* __restrict__ B, void* __restrict__ Cv,
    __half* __restrict__ C2, __half* __restrict__ C3,
    int Md, int Nd, int Kd,
    const float* __restrict__ bias, const float* __restrict__ resid)
{
    (void)Md;
    constexpr int BM = 128, BK = 64;
    constexpr int WM = (BN == 128) ? 2 : 4;
    constexpr int WN = 8 / WM;
    constexpr int WTM = BM / WM, WTN = BN / WN;
    constexpr int MT = WTM / 16, NT = WTN / 8;
    constexpr int ASTG = BM * BK;
    constexpr int BSTG = BN * BK;

    extern __shared__ __align__(16) __half smh[];
    __half* As = smh;
    __half* Bs = smh + 2 * ASTG;

    const int t = threadIdx.x;
    const int wid = t >> 5, lane = t & 31;
    const int wm = wid % WM, wn = wid / WM;
    const int lr4 = lane >> 2, lc4 = lane & 3;
    const int g8 = lane >> 3, l8 = lane & 7;
    const int m0 = blockIdx.y * BM, n0 = blockIdx.x * BN;

    const __half* Ab = A + (size_t)m0 * Kd;
    const __half* Bb = B + (size_t)n0 * Kd;

    auto prefetch = [&](int kt, int st) {
        const __half* Ag = Ab + kt * BK;
        const __half* Bg = Bb + kt * BK;
#pragma unroll
        for (int i = 0; i < BM / 32; i++) {
            const int ch = t + i * 256;
            const int r = ch >> 3, c = ch & 7;
            cp_async16(&As[st * ASTG + (r * 8 + (c ^ (r & 7))) * 8], Ag + (size_t)r * Kd + c * 8);
        }
#pragma unroll
        for (int i = 0; i < BN / 32; i++) {
            const int ch = t + i * 256;
            const int r = ch >> 3, c = ch & 7;
            cp_async16(&Bs[st * BSTG + (r * 8 + (c ^ (r & 7))) * 8], Bg + (size_t)r * Kd + c * 8);
        }
    };

    float acc[MT][NT][4];
#pragma unroll
    for (int i = 0; i < MT; i++)
#pragma unroll
        for (int j = 0; j < NT; j++)
#pragma unroll
            for (int q = 0; q < 4; q++) acc[i][j][q] = 0.f;

    const int nK = Kd / BK;
    prefetch(0, 0);
    cp_commit();

    for (int kt = 0; kt < nK; kt++) {
        __syncthreads();
        if (kt + 1 < nK) { prefetch(kt + 1, (kt + 1) & 1); cp_commit(); cp_wait<1>(); }
        else             { cp_wait<0>(); }
        __syncthreads();

        const uint32_t Au = (uint32_t)__cvta_generic_to_shared(As + (kt & 1) * ASTG);
        const uint32_t Bu = (uint32_t)__cvta_generic_to_shared(Bs + (kt & 1) * BSTG);

#pragma unroll
        for (int k16 = 0; k16 < BK / 16; k16++) {
            uint32_t bf[NT][2];
#pragma unroll
            for (int p = 0; p < NT / 2; p++) {
                const int row = wn * WTN + p * 16 + (g8 >> 1) * 8 + l8;
                const int ch  = (2 * k16 + (g8 & 1)) ^ l8;
                ldsm4(bf[2 * p][0], bf[2 * p][1], bf[2 * p + 1][0], bf[2 * p + 1][1],
                      Bu + (row * 8 + ch) * 16);
            }
#pragma unroll
            for (int mt = 0; mt < MT; mt++) {
                const int rowA = wm * WTM + mt * 16 + (g8 & 1) * 8 + l8;
                const int chA  = (2 * k16 + (g8 >> 1)) ^ l8;
                uint32_t a0, a1, a2, a3;
                ldsm4(a0, a1, a2, a3, Au + (rowA * 8 + chA) * 16);
#pragma unroll
                for (int nt = 0; nt < NT; nt++)
                    mma16h(acc[mt][nt], a0, a1, a2, a3, bf[nt][0], bf[nt][1]);
            }
        }
    }

#pragma unroll
    for (int mt = 0; mt < MT; mt++) {
        const int mbase = m0 + wm * WTM + mt * 16 + lr4;
#pragma unroll
        for (int nt = 0; nt < NT; nt++) {
            const int n = n0 + wn * WTN + nt * 8 + 2 * lc4;
            if (MODE == 0) {
                __half* C = (__half*)Cv;
                *(__half2*)&C[(size_t)mbase * Nd + n] =
                    __floats2half2_rn(acc[mt][nt][0], acc[mt][nt][1]);
                *(__half2*)&C[(size_t)(mbase + 8) * Nd + n] =
                    __floats2half2_rn(acc[mt][nt][2], acc[mt][nt][3]);
            } else if (MODE == 1) {
                const int which = n / Cdim;
                const int rem = n % Cdim;
                const int h = rem / HDn, d = rem % HDn;
                __half* dst = (which == 0) ? (__half*)Cv : (which == 1) ? C2 : C3;
#pragma unroll
                for (int rr = 0; rr < 2; rr++) {
                    const int m = mbase + rr * 8;
                    const int b = m >> 10, nr = m & 1023;
                    const size_t di = ((size_t)((b << 2) + h) * Nn + nr) * HDn + d;
                    *(__half2*)&dst[di] =
                        __floats2half2_rn(acc[mt][nt][rr * 2], acc[mt][nt][rr * 2 + 1]);
                }
            } else {
                float* C = (float*)Cv;
                const float b0 = bias[n], b1 = bias[n + 1];
                const size_t i0 = (size_t)mbase * Nd + n;
                const size_t i1 = (size_t)(mbase + 8) * Nd + n;
                *(float2*)&C[i0] = make_float2(acc[mt][nt][0] + b0 + resid[i0],
                                               acc[mt][nt][1] + b1 + resid[i0 + 1]);
                *(float2*)&C[i1] = make_float2(acc[mt][nt][2] + b0 + resid[i1],
                                               acc[mt][nt][3] + b1 + resid[i1 + 1]);
            }
        }
    }
}

// ---------------- per-key bias: kb[r] = -scale * dot(K[r], KM[r]) ----------------
__global__ __launch_bounds__(256) void kbias_kernel(
    const __half* __restrict__ Kg, const __half* __restrict__ KM,
    const float* __restrict__ scale_p, float* __restrict__ kb)
{
    const int gw = (blockIdx.x * 256 + threadIdx.x) >> 5;
    const int lane = threadIdx.x & 31;
    if (gw >= BHn * Nn) return;
    const __half2* kr  = (const __half2*)(Kg + (size_t)gw * HDn);
    const __half2* kmr = (const __half2*)(KM + (size_t)gw * HDn);
    float s = 0.f;
#pragma unroll
    for (int i = 0; i < 3; i++) {
        const float2 a = __half22float2(kr[lane + i * 32]);
        const float2 b = __half22float2(kmr[lane + i * 32]);
        s += a.x * b.x + a.y * b.y;
    }
    s = warpsum32(s);
    if (lane == 0) kb[gw] = -scale_p[0] * s;
}

// ---------------- fp16 flash attention: 128-row q-tile, warp-owns-full-rows ----------
// logits S_ij = 2*scale*(qM_i . k_j) + kb_j   (qMq cancels in softmax)
// Each of 8 warps owns 16 q-rows x ALL 64 keys -> in-warp softmax, P stays in registers
// (S accumulator frags map exactly onto A-operand frags for P@V).
constexpr int KSs = 200;        // K/V smem stride (halfs)
constexpr int KVST = 64 * KSs;  // halfs per stage
constexpr int ATT_SMEM = 4 * KVST * 2 + 2 * 64 * 4;   // 102912 B

__global__ __launch_bounds__(256, 1) void attn_tc_kernel(
    const __half* __restrict__ QM, const __half* __restrict__ Kg,
    const __half* __restrict__ Vg, const float* __restrict__ kbias,
    const float* __restrict__ scale_p, __half* __restrict__ y)
{
    extern __shared__ __align__(16) __half smha[];
    __half* ks_base = smha;                       // 2 stages
    __half* vs_base = smha + 2 * KVST;            // 2 stages
    float* kbt_base = (float*)(smha + 4 * KVST);  // 2 x 64

    const int bh = blockIdx.x, qt = blockIdx.y;   // qt: 128-row tile
    const int b = bh >> 2, h = bh & 3;
    const int t = threadIdx.x;
    const int wid = t >> 5, lane = t & 31;
    const int lr4 = lane >> 2, lc4 = lane & 3;
    const int g8 = lane >> 3, l8 = lane & 7;
    const float twoscale = 2.0f * scale_p[0];
    const int r0 = wid * 16;                      // warp's q-row base within tile

    auto prefetch = [&](int kt, int st) {
        const __half* kg = Kg + ((size_t)bh * Nn + kt * 64) * HDn;
        const __half* vg = Vg + ((size_t)bh * Nn + kt * 64) * HDn;
        __half* ksb = ks_base + st * KVST;
        __half* vsb = vs_base + st * KVST;
#pragma unroll
        for (int i = 0; i < 6; i++) {
            const int ch = t + i * 256;
            const int r = ch / 24, c = ch % 24;
            cp_async16(&ksb[r * KSs + c * 8], kg + r * HDn + c * 8);
            cp_async16(&vsb[r * KSs + c * 8], vg + r * HDn + c * 8);
        }
        if (t < 16) cp_async16(&kbt_base[st * 64 + t * 4],
                               kbias + (size_t)bh * Nn + kt * 64 + t * 4);
    };

    prefetch(0, 0);
    cp_commit();

    // ---- Q fragments (half2) into registers (one-time) ----
    uint32_t qa[12][4];
    {
        const __half* qb = QM + ((size_t)bh * Nn + qt * 128) * HDn;
#pragma unroll
        for (int k16 = 0; k16 < 12; k16++) {
            const int kk = k16 * 16;
            qa[k16][0] = *(const uint32_t*)&qb[(r0 + lr4)     * HDn + kk + 2 * lc4];
            qa[k16][1] = *(const uint32_t*)&qb[(r0 + lr4 + 8) * HDn + kk + 2 * lc4];
            qa[k16][2] = *(const uint32_t*)&qb[(r0 + lr4)     * HDn + kk + 8 + 2 * lc4];
            qa[k16][3] = *(const uint32_t*)&qb[(r0 + lr4 + 8) * HDn + kk + 8 + 2 * lc4];
        }
    }

    float O[24][4];
#pragma unroll
    for (int nt = 0; nt < 24; nt++)
#pragma unroll
        for (int q = 0; q < 4; q++) O[nt][q] = 0.f;
    float mr0 = -1e30f, mr1 = -1e30f, l0 = 0.f, l1 = 0.f;

    for (int kt = 0; kt < Nn / 64; kt++) {
        __syncthreads();
        if (kt + 1 < Nn / 64) { prefetch(kt + 1, (kt + 1) & 1); cp_commit(); cp_wait<1>(); }
        else                  { cp_wait<0>(); }
        __syncthreads();

        const int st = kt & 1;
        const uint32_t ks_u = (uint32_t)__cvta_generic_to_shared(ks_base + st * KVST);
        const uint32_t vs_u = (uint32_t)__cvta_generic_to_shared(vs_base + st * KVST);
        const float* kbt = kbt_base + st * 64;

        // ---- S[16 x 64] = qM rows @ K_tile^T (8 ntiles per warp) ----
        float s[8][4];
#pragma unroll
        for (int nt = 0; nt < 8; nt++)
#pragma unroll
            for (int q = 0; q < 4; q++) s[nt][q] = 0.f;
#pragma unroll
        for (int k16 = 0; k16 < 12; k16++) {
            const int kk = k16 * 16;
            uint32_t bf[8][2];
#pragma unroll
            for (int p = 0; p < 4; p++) {
                const int row = p * 16 + (g8 >> 1) * 8 + l8;
                const int col = kk + (g8 & 1) * 8;
                ldsm4(bf[2 * p][0], bf[2 * p][1], bf[2 * p + 1][0], bf[2 * p + 1][1],
                      ks_u + (row * KSs + col) * 2);
            }
#pragma unroll
            for (int nt = 0; nt < 8; nt++)
                mma16h(s[nt], qa[k16][0], qa[k16][1], qa[k16][2], qa[k16][3],
                       bf[nt][0], bf[nt][1]);
        }

        // ---- scale + key bias, in-warp rowmax ----
        float pm0 = -1e30f, pm1 = -1e30f;
#pragma unroll
        for (int nt = 0; nt < 8; nt++) {
            const int col = nt * 8 + 2 * lc4;
            const float kb0 = kbt[col], kb1 = kbt[col + 1];
            s[nt][0] = fmaf(twoscale, s[nt][0], kb0);
            s[nt][1] = fmaf(twoscale, s[nt][1], kb1);
            s[nt][2] = fmaf(twoscale, s[nt][2], kb0);
            s[nt][3] = fmaf(twoscale, s[nt][3], kb1);
            pm0 = fmaxf(pm0, fmaxf(s[nt][0], s[nt][1]));
            pm1 = fmaxf(pm1, fmaxf(s[nt][2], s[nt][3]));
        }
        pm0 = fmaxf(pm0, __shfl_xor_sync(0xffffffffu, pm0, 1));
        pm0 = fmaxf(pm0, __shfl_xor_sync(0xffffffffu, pm0, 2));
        pm1 = fmaxf(pm1, __shfl_xor_sync(0xffffffffu, pm1, 1));
        pm1 = fmaxf(pm1, __shfl_xor_sync(0xffffffffu, pm1, 2));
        const float mn0 = fmaxf(mr0, pm0), mn1 = fmaxf(mr1, pm1);
        const float cor0 = __expf(mr0 - mn0), cor1 = __expf(mr1 - mn1);
        mr0 = mn0; mr1 = mn1;

        // ---- exp -> P fragments in registers; rowsum ----
        uint32_t pa[4][4];
        float q0 = 0.f, q1 = 0.f;
#pragma unroll
        for (int j = 0; j < 4; j++) {
#pragma unroll
            for (int hh = 0; hh < 2; hh++) {
                const int nt = 2 * j + hh;
                const float e0 = __expf(s[nt][0] - mn0);
                const float e1 = __expf(s[nt][1] - mn0);
                const float e2 = __expf(s[nt][2] - mn1);
                const float e3 = __expf(s[nt][3] - mn1);
                q0 += e0 + e1; q1 += e2 + e3;
                pa[j][2 * hh]     = h2u(__floats2half2_rn(e0, e1));
                pa[j][2 * hh + 1] = h2u(__floats2half2_rn(e2, e3));
            }
        }
        q0 += __shfl_xor_sync(0xffffffffu, q0, 1);
        q0 += __shfl_xor_sync(0xffffffffu, q0, 2);
        q1 += __shfl_xor_sync(0xffffffffu, q1, 1);
        q1 += __shfl_xor_sync(0xffffffffu, q1, 2);
        l0 = l0 * cor0 + q0;
        l1 = l1 * cor1 + q1;
#pragma unroll
        for (int nt = 0; nt < 24; nt++) {
            O[nt][0] *= cor0; O[nt][1] *= cor0;
            O[nt][2] *= cor1; O[nt][3] *= cor1;
        }

        // ---- O += P @ V (V via ldmatrix.trans; P from registers) ----
#pragma unroll
        for (int j = 0; j < 4; j++) {
            const int kk = j * 16;
#pragma unroll
            for (int p = 0; p < 12; p++) {
                const int rowv = kk + (g8 & 1) * 8 + l8;
                const int colv = p * 16 + (g8 >> 1) * 8;
                uint32_t b0A, b1A, b0B, b1B;
                ldsm4t(b0A, b1A, b0B, b1B, vs_u + (rowv * KSs + colv) * 2);
                mma16h(O[2 * p],     pa[j][0], pa[j][1], pa[j][2], pa[j][3], b0A, b1A);
                mma16h(O[2 * p + 1], pa[j][0], pa[j][1], pa[j][2], pa[j][3], b0B, b1B);
            }
        }
    }

    // ---- normalize + write y (half, for proj GEMM) ----
    const float i0v = 1.0f / l0, i1v = 1.0f / l1;
    const int nrow0 = qt * 128 + r0 + lr4;
    __half* y0 = y + (size_t)(b * Nn + nrow0) * Cdim + h * HDn;
    __half* y1 = y0 + 8 * Cdim;
#pragma unroll
    for (int nt = 0; nt < 24; nt++) {
        const int col = nt * 8 + 2 * lc4;
        *(__half2*)&y0[col] = __floats2half2_rn(O[nt][0] * i0v, O[nt][1] * i0v);
        *(__half2*)&y1[col] = __floats2half2_rn(O[nt][2] * i1v, O[nt][3] * i1v);
    }
}

// ---------------- fused LN2 + RBF features ----------------
constexpr int RBF_SMEM_BYTES = (CEN * Cdim + 2 * CEN) * 4;

__global__ __launch_bounds__(256) void rbf_fused_kernel(
    const float* __restrict__ x1, const float* __restrict__ n2w,
    const float* __restrict__ n2b, const float* __restrict__ centers,
    const float* __restrict__ beta, float* __restrict__ rbf)
{
    extern __shared__ __align__(16) float rsm[];
    float* cs = rsm;                    // [CEN][Cdim]
    float* cn = rsm + CEN * Cdim;       // [CEN]
    float* bt = cn + CEN;               // [CEN]
    const int t = threadIdx.x;
    for (int i = t; i < CEN * Cdim; i += 256) cs[i] = centers[i];
    __syncthreads();
    if (t < CEN) {
        float s = 0.f;
        for (int k = 0; k < Cdim; k++) s += cs[t * Cdim + k] * cs[t * Cdim + k];
        cn[t] = s;
        bt[t] = beta[t];
    }
    __syncthreads();
    const int wid = t >> 5, lane = t & 31;
    const float4* w4 = (const float4*)n2w;
    const float4* b4 = (const float4*)n2b;
    for (int rr = 0; rr < 8; rr++) {
        const int row = blockIdx.x * 64 + wid * 8 + rr;
        const float4* xr = (const float4*)(x1 + (size_t)row * Cdim);
        float4 v[6];
        float s = 0.f, s2 = 0.f;
#pragma unroll
        for (int i = 0; i < 6; i++) {
            v[i] = xr[lane + i * 32];
            s  += v[i].x + v[i].y + v[i].z + v[i].w;
            s2 += v[i].x * v[i].x + v[i].y * v[i].y + v[i].z * v[i].z + v[i].w * v[i].w;
        }
        s = warpsum32(s); s2 = warpsum32(s2);
        const float mu  = s * (1.0f / Cdim);
        const float var = s2 * (1.0f / Cdim) - mu * mu;
        const float rs  = rsqrtf(var + EPSv);
        float hv[24];
        float a = 0.f;
#pragma unroll
        for (int i = 0; i < 6; i++) {
            const int idx = lane + i * 32;
            const float4 wv = w4[idx], bv = b4[idx];
            hv[4 * i + 0] = (v[i].x - mu) * rs * wv.x + bv.x;
            hv[4 * i + 1] = (v[i].y - mu) * rs * wv.y + bv.y;
            hv[4 * i + 2] = (v[i].z - mu) * rs * wv.z + bv.z;
            hv[4 * i + 3] = (v[i].w - mu) * rs * wv.w + bv.w;
            a += hv[4*i]*hv[4*i] + hv[4*i+1]*hv[4*i+1] + hv[4*i+2]*hv[4*i+2] + hv[4*i+3]*hv[4*i+3];
        }
        a = warpsum32(a);
        for (int j = 0; j < CEN; j++) {
            const float4* cj = (const float4*)(cs + j * Cdim);
            float d = 0.f;
#pragma unroll
            for (int i = 0; i < 6; i++) {
                const float4 cv = cj[lane + i * 32];
                d += hv[4*i]*cv.x + hv[4*i+1]*cv.y + hv[4*i+2]*cv.z + hv[4*i+3]*cv.w;
            }
            d = warpsum32(d);
            if (lane == 0)
                rbf[(size_t)row * CEN + j] = __expf(-bt[j] * (a - 2.0f * d + cn[j]));
        }
    }
}

// ---------------- final: out = x1 + rbf @ fc_w^T ----------------
__global__ __launch_bounds__(256) void final_kernel(
    const float* __restrict__ x1, const float* __restrict__ rbf,
    const float* __restrict__ fcw, float* __restrict__ out)
{
    const int i = blockIdx.x * 256 + threadIdx.x;
    if (i >= Sn * Cdim) return;
    const int c = i % Cdim;
    const int r = i / Cdim;
    const float* rb = rbf + (size_t)r * CEN;
    const float* fw = fcw + (size_t)c * CEN;
    float acc = x1[i];
#pragma unroll
    for (int j = 0; j < CEN; j++) acc += rb[j] * fw[j];
    out[i] = acc;
}

// ---------------- launcher ----------------
extern "C" void kernel_launch(void* const* d_in, const int* in_sizes, int n_in,
                              void* d_out, int out_size)
{
    (void)in_sizes; (void)n_in; (void)out_size;
    const float* x     = (const float*)d_in[0];
    const float* n1w   = (const float*)d_in[1];
    const float* n1b   = (const float*)d_in[2];
    const float* qkvw  = (const float*)d_in[3];
    const float* Mmat  = (const float*)d_in[4];
    const float* scale = (const float*)d_in[5];
    const float* projw = (const float*)d_in[6];
    const float* projb = (const float*)d_in[7];
    const float* n2w   = (const float*)d_in[8];
    const float* n2b   = (const float*)d_in[9];
    const float* cent  = (const float*)d_in[10];
    const float* beta  = (const float*)d_in[11];
    const float* fcw   = (const float*)d_in[12];
    float* out = (float*)d_out;

    __half *hP, *qwP, *pwP, *QgP, *KgP, *VgP, *QMP, *KMP, *MTP, *yP;
    float *kbP, *x1P, *rbfP;
    cudaGetSymbolAddress((void**)&hP,   g_h);
    cudaGetSymbolAddress((void**)&qwP,  g_qkvwr);
    cudaGetSymbolAddress((void**)&pwP,  g_projwr);
    cudaGetSymbolAddress((void**)&QgP,  g_Qg);
    cudaGetSymbolAddress((void**)&KgP,  g_Kg);
    cudaGetSymbolAddress((void**)&VgP,  g_Vg);
    cudaGetSymbolAddress((void**)&QMP,  g_QM);
    cudaGetSymbolAddress((void**)&KMP,  g_KM);
    cudaGetSymbolAddress((void**)&MTP,  g_MT);
    cudaGetSymbolAddress((void**)&kbP,  g_kb);
    cudaGetSymbolAddress((void**)&yP,   g_y);
    cudaGetSymbolAddress((void**)&x1P,  g_x1);
    cudaGetSymbolAddress((void**)&rbfP, g_rbf);

    constexpr int GS128 = 2 * (128 + 128) * 64 * 2;   // 65536 B
    constexpr int GS64  = 2 * (128 + 64) * 64 * 2;    // 49152 B
    cudaFuncSetAttribute(gemm_h<128, 1>, cudaFuncAttributeMaxDynamicSharedMemorySize, GS128);
    cudaFuncSetAttribute(gemm_h<128, 2>, cudaFuncAttributeMaxDynamicSharedMemorySize, GS128);
    cudaFuncSetAttribute(gemm_h<64, 0>,  cudaFuncAttributeMaxDynamicSharedMemorySize, GS64);
    cudaFuncSetAttribute(attn_tc_kernel, cudaFuncAttributeMaxDynamicSharedMemorySize, ATT_SMEM);
    cudaFuncSetAttribute(rbf_fused_kernel, cudaFuncAttributeMaxDynamicSharedMemorySize, RBF_SMEM_BYTES);

    // 0) weight conversion (fp16 copies)
    half_copy_kernel<<<512, 256>>>(qkvw, qwP, 3 * Cdim * Cdim);
    half_copy_kernel<<<512, 256>>>(projw, pwP, Cdim * Cdim);
    transpose_m_kernel<<<(HDn * HDn + 255) / 256, 256>>>(Mmat, MTP);
    // 1) LN1 (half out)
    ln1_kernel<<<Sn / 8, 256>>>(x, n1w, n1b, hP);
    // 2) qkv GEMM fused with gather -> Qg/Kg/Vg (half)
    gemm_h<128, 1><<<dim3(3 * Cdim / 128, Sn / 128), 256, GS128>>>(
        hP, qwP, QgP, KgP, VgP, Sn, 3 * Cdim, Cdim, nullptr, nullptr);
    // 3) qM = Q @ M, kM = K @ M (half out)
    gemm_h<64, 0><<<dim3(HDn / 64, BHn * Nn / 128), 256, GS64>>>(
        QgP, MTP, QMP, nullptr, nullptr, BHn * Nn, HDn, HDn, nullptr, nullptr);
    gemm_h<64, 0><<<dim3(HDn / 64, BHn * Nn / 128), 256, GS64>>>(
        KgP, MTP, KMP, nullptr, nullptr, BHn * Nn, HDn, HDn, nullptr, nullptr);
    // 4) per-key bias
    kbias_kernel<<<(BHn * Nn) * 32 / 256, 256>>>(KgP, KMP, scale, kbP);
    // 5) fp16 flash attention (128-row tiles) -> y (half)
    attn_tc_kernel<<<dim3(BHn, Nn / 128), 256, ATT_SMEM>>>(QMP, KgP, VgP, kbP, scale, yP);
    // 6) x1 = x + y @ proj_w^T + proj_b (fp32 out)
    gemm_h<128, 2><<<dim3(Cdim / 128, Sn / 128), 256, GS128>>>(
        yP, pwP, x1P, nullptr, nullptr, Sn, Cdim, Cdim, projb, x);
    // 7) fused LN2 + RBF
    rbf_fused_kernel<<<Sn / 64, 256, RBF_SMEM_BYTES>>>(x1P, n2w, n2b, cent, beta, rbfP);
    // 8) out = x1 + rbf @ fc_w^T
    final_kernel<<<(Sn * Cdim + 255) / 256, 256>>>(x1P, rbfP, fcw, out);
}

// round 9
// speedup vs baseline: 9.3414x; 1.0390x over previous
#include <cuda_runtime.h>
#include <cuda_fp16.h>
#include <cstdint>

// ---------------- problem constants ----------------
constexpr int Cdim = 768;
constexpr int Bn   = 8;
constexpr int Nn   = 1024;
constexpr int HDn  = 192;            // head dim
constexpr int Sn   = Bn * Nn;        // 8192 rows
constexpr int BHn  = Bn * 4;         // 32
constexpr int CEN  = 20;
constexpr float EPSv = 1e-5f;

// ---------------- scratch (device globals; no allocation allowed) ----------------
__device__ __half g_h     [Sn * Cdim];
__device__ __half g_qkvwr [3 * Cdim * Cdim];
__device__ __half g_projwr[Cdim * Cdim];
__device__ __half g_Qg  [BHn * Nn * HDn];
__device__ __half g_Kg  [BHn * Nn * HDn];
__device__ __half g_Vg  [BHn * Nn * HDn];
__device__ __half g_KM  [BHn * Nn * HDn];   // KM2 = K @ (2*scale*M)^T
__device__ __half g_Mh  [HDn * HDn];        // 2*scale*M (half)
__device__ float  g_kb  [BHn * Nn];
__device__ __half g_y   [Sn * Cdim];
__device__ float  g_x1  [Sn * Cdim];
__device__ float  g_rbf [Sn * CEN];

// ---------------- helpers ----------------
__device__ __forceinline__ float warpsum32(float v) {
#pragma unroll
    for (int o = 16; o >= 1; o >>= 1) v += __shfl_xor_sync(0xffffffffu, v, o);
    return v;
}
__device__ __forceinline__ uint32_t h2u(__half2 h) {
    return *reinterpret_cast<uint32_t*>(&h);
}
__device__ __forceinline__ void mma16h(float* c,
    uint32_t a0, uint32_t a1, uint32_t a2, uint32_t a3, uint32_t b0, uint32_t b1)
{
    asm volatile("mma.sync.aligned.m16n8k16.row.col.f32.f16.f16.f32 "
        "{%0,%1,%2,%3}, {%4,%5,%6,%7}, {%8,%9}, {%0,%1,%2,%3};"
        : "+f"(c[0]), "+f"(c[1]), "+f"(c[2]), "+f"(c[3])
        : "r"(a0), "r"(a1), "r"(a2), "r"(a3), "r"(b0), "r"(b1));
}
__device__ __forceinline__ void ldsm4(uint32_t& r0, uint32_t& r1, uint32_t& r2, uint32_t& r3,
                                      uint32_t addr)
{
    asm volatile("ldmatrix.sync.aligned.m8n8.x4.shared.b16 {%0,%1,%2,%3}, [%4];"
        : "=r"(r0), "=r"(r1), "=r"(r2), "=r"(r3) : "r"(addr));
}
__device__ __forceinline__ void ldsm4t(uint32_t& r0, uint32_t& r1, uint32_t& r2, uint32_t& r3,
                                       uint32_t addr)
{
    asm volatile("ldmatrix.sync.aligned.m8n8.x4.trans.shared.b16 {%0,%1,%2,%3}, [%4];"
        : "=r"(r0), "=r"(r1), "=r"(r2), "=r"(r3) : "r"(addr));
}
__device__ __forceinline__ void cp_async16(void* smem, const void* gmem) {
    uint32_t s = (uint32_t)__cvta_generic_to_shared(smem);
    asm volatile("cp.async.cg.shared.global [%0], [%1], 16;\n" :: "r"(s), "l"(gmem));
}
__device__ __forceinline__ void cp_commit() {
    asm volatile("cp.async.commit_group;\n");
}
template<int N>
__device__ __forceinline__ void cp_wait() {
    asm volatile("cp.async.wait_group %0;\n" :: "n"(N));
}

// ---------------- LayerNorm (LN1): warp per row, half output ----------------
__global__ __launch_bounds__(256) void ln1_kernel(
    const float* __restrict__ x, const float* __restrict__ w,
    const float* __restrict__ b, __half* __restrict__ out)
{
    const int row  = blockIdx.x * 8 + (threadIdx.x >> 5);
    const int lane = threadIdx.x & 31;
    const float4* xr = (const float4*)(x + (size_t)row * Cdim);
    float4 v[6];
    float s = 0.f, s2 = 0.f;
#pragma unroll
    for (int i = 0; i < 6; i++) {
        v[i] = xr[lane + i * 32];
        s  += v[i].x + v[i].y + v[i].z + v[i].w;
        s2 += v[i].x * v[i].x + v[i].y * v[i].y + v[i].z * v[i].z + v[i].w * v[i].w;
    }
    s = warpsum32(s); s2 = warpsum32(s2);
    const float mu  = s * (1.0f / Cdim);
    const float var = s2 * (1.0f / Cdim) - mu * mu;
    const float rs  = rsqrtf(var + EPSv);
    const float4* w4 = (const float4*)w;
    const float4* b4 = (const float4*)b;
#pragma unroll
    for (int i = 0; i < 6; i++) {
        const int idx = lane + i * 32;
        const float4 wv = w4[idx], bv = b4[idx];
        __half* orow = out + (size_t)row * Cdim + 4 * idx;
        *(__half2*)&orow[0] = __floats2half2_rn((v[i].x - mu) * rs * wv.x + bv.x,
                                                (v[i].y - mu) * rs * wv.y + bv.y);
        *(__half2*)&orow[2] = __floats2half2_rn((v[i].z - mu) * rs * wv.z + bv.z,
                                                (v[i].w - mu) * rs * wv.w + bv.w);
    }
}

// ---------------- f32 -> f16 copy (vectorized) ----------------
__global__ __launch_bounds__(256) void half_copy4_kernel(
    const float4* __restrict__ src, __half* __restrict__ dst, int n4)
{
    for (int i = blockIdx.x * 256 + threadIdx.x; i < n4; i += gridDim.x * 256) {
        const float4 v = src[i];
        *(__half2*)&dst[4 * i]     = __floats2half2_rn(v.x, v.y);
        *(__half2*)&dst[4 * i + 2] = __floats2half2_rn(v.z, v.w);
    }
}

// ---------------- Mh = 2*scale*M (half, same layout) ----------------
__global__ __launch_bounds__(256) void scale_m_kernel(
    const float* __restrict__ M, const float* __restrict__ scale_p,
    __half* __restrict__ Mh)
{
    const int i = blockIdx.x * 256 + threadIdx.x;
    if (i >= HDn * HDn) return;
    Mh[i] = __float2half(2.0f * scale_p[0] * M[i]);
}

// ---------------- 3-stage pipelined fp16 NT GEMM: C = A[M,K] * B[N,K]^T ----------------
// MODE 0: half store. MODE 1: qkv scatter -> Q/K/V half [BH][N][HD]. MODE 2: fp32 +bias+resid.
template<int BN, int MODE>
__global__ __launch_bounds__(256) void gemm_h(
    const __half* __restrict__ A, const __half* __restrict__ B, void* __restrict__ Cv,
    __half* __restrict__ C2, __half* __restrict__ C3,
    int Md, int Nd, int Kd,
    const float* __restrict__ bias, const float* __restrict__ resid)
{
    (void)Md;
    constexpr int BM = 128, BK = 64;
    constexpr int WM = (BN == 128) ? 2 : 4;
    constexpr int WN = 8 / WM;
    constexpr int WTM = BM / WM, WTN = BN / WN;
    constexpr int MT = WTM / 16, NT = WTN / 8;
    constexpr int ASTG = BM * BK;
    constexpr int BSTG = BN * BK;

    extern __shared__ __align__(16) __half smh[];
    __half* As = smh;                 // 3 stages
    __half* Bs = smh + 3 * ASTG;      // 3 stages

    const int t = threadIdx.x;
    const int wid = t >> 5, lane = t & 31;
    const int wm = wid % WM, wn = wid / WM;
    const int lr4 = lane >> 2, lc4 = lane & 3;
    const int g8 = lane >> 3, l8 = lane & 7;
    const int m0 = blockIdx.y * BM, n0 = blockIdx.x * BN;

    const __half* Ab = A + (size_t)m0 * Kd;
    const __half* Bb = B + (size_t)n0 * Kd;

    auto prefetch = [&](int kt, int st) {
        const __half* Ag = Ab + kt * BK;
        const __half* Bg = Bb + kt * BK;
#pragma unroll
        for (int i = 0; i < BM / 32; i++) {
            const int ch = t + i * 256;
            const int r = ch >> 3, c = ch & 7;
            cp_async16(&As[st * ASTG + (r * 8 + (c ^ (r & 7))) * 8], Ag + (size_t)r * Kd + c * 8);
        }
#pragma unroll
        for (int i = 0; i < BN / 32; i++) {
            const int ch = t + i * 256;
            const int r = ch >> 3, c = ch & 7;
            cp_async16(&Bs[st * BSTG + (r * 8 + (c ^ (r & 7))) * 8], Bg + (size_t)r * Kd + c * 8);
        }
    };

    float acc[MT][NT][4];
#pragma unroll
    for (int i = 0; i < MT; i++)
#pragma unroll
        for (int j = 0; j < NT; j++)
#pragma unroll
            for (int q = 0; q < 4; q++) acc[i][j][q] = 0.f;

    const int nK = Kd / BK;
    prefetch(0, 0); cp_commit();
    prefetch(1, 1); cp_commit();

    for (int kt = 0; kt < nK; kt++) {
        cp_wait<1>();
        __syncthreads();
        if (kt + 2 < nK) prefetch(kt + 2, (kt + 2) % 3);
        cp_commit();

        const int st = kt % 3;
        const uint32_t Au = (uint32_t)__cvta_generic_to_shared(As + st * ASTG);
        const uint32_t Bu = (uint32_t)__cvta_generic_to_shared(Bs + st * BSTG);

#pragma unroll
        for (int k16 = 0; k16 < BK / 16; k16++) {
            uint32_t bf[NT][2];
#pragma unroll
            for (int p = 0; p < NT / 2; p++) {
                const int row = wn * WTN + p * 16 + (g8 >> 1) * 8 + l8;
                const int ch  = (2 * k16 + (g8 & 1)) ^ l8;
                ldsm4(bf[2 * p][0], bf[2 * p][1], bf[2 * p + 1][0], bf[2 * p + 1][1],
                      Bu + (row * 8 + ch) * 16);
            }
#pragma unroll
            for (int mt = 0; mt < MT; mt++) {
                const int rowA = wm * WTM + mt * 16 + (g8 & 1) * 8 + l8;
                const int chA  = (2 * k16 + (g8 >> 1)) ^ l8;
                uint32_t a0, a1, a2, a3;
                ldsm4(a0, a1, a2, a3, Au + (rowA * 8 + chA) * 16);
#pragma unroll
                for (int nt = 0; nt < NT; nt++)
                    mma16h(acc[mt][nt], a0, a1, a2, a3, bf[nt][0], bf[nt][1]);
            }
        }
    }

#pragma unroll
    for (int mt = 0; mt < MT; mt++) {
        const int mbase = m0 + wm * WTM + mt * 16 + lr4;
#pragma unroll
        for (int nt = 0; nt < NT; nt++) {
            const int n = n0 + wn * WTN + nt * 8 + 2 * lc4;
            if (MODE == 0) {
                __half* C = (__half*)Cv;
                *(__half2*)&C[(size_t)mbase * Nd + n] =
                    __floats2half2_rn(acc[mt][nt][0], acc[mt][nt][1]);
                *(__half2*)&C[(size_t)(mbase + 8) * Nd + n] =
                    __floats2half2_rn(acc[mt][nt][2], acc[mt][nt][3]);
            } else if (MODE == 1) {
                const int which = n / Cdim;
                const int rem = n % Cdim;
                const int h = rem / HDn, d = rem % HDn;
                __half* dst = (which == 0) ? (__half*)Cv : (which == 1) ? C2 : C3;
#pragma unroll
                for (int rr = 0; rr < 2; rr++) {
                    const int m = mbase + rr * 8;
                    const int b = m >> 10, nr = m & 1023;
                    const size_t di = ((size_t)((b << 2) + h) * Nn + nr) * HDn + d;
                    *(__half2*)&dst[di] =
                        __floats2half2_rn(acc[mt][nt][rr * 2], acc[mt][nt][rr * 2 + 1]);
                }
            } else {
                float* C = (float*)Cv;
                const float b0 = bias[n], b1 = bias[n + 1];
                const size_t i0 = (size_t)mbase * Nd + n;
                const size_t i1 = (size_t)(mbase + 8) * Nd + n;
                *(float2*)&C[i0] = make_float2(acc[mt][nt][0] + b0 + resid[i0],
                                               acc[mt][nt][1] + b1 + resid[i0 + 1]);
                *(float2*)&C[i1] = make_float2(acc[mt][nt][2] + b0 + resid[i1],
                                               acc[mt][nt][3] + b1 + resid[i1 + 1]);
            }
        }
    }
}

// ---------------- per-key bias: kb[r] = -0.5 * dot(K[r], KM2[r]) ----------------
__global__ __launch_bounds__(256) void kbias_kernel(
    const __half* __restrict__ Kg, const __half* __restrict__ KM,
    float* __restrict__ kb)
{
    const int gw = (blockIdx.x * 256 + threadIdx.x) >> 5;
    const int lane = threadIdx.x & 31;
    if (gw >= BHn * Nn) return;
    const __half2* kr  = (const __half2*)(Kg + (size_t)gw * HDn);
    const __half2* kmr = (const __half2*)(KM + (size_t)gw * HDn);
    float s = 0.f;
#pragma unroll
    for (int i = 0; i < 3; i++) {
        const float2 a = __half22float2(kr[lane + i * 32]);
        const float2 b = __half22float2(kmr[lane + i * 32]);
        s += a.x * b.x + a.y * b.y;
    }
    s = warpsum32(s);
    if (lane == 0) kb[gw] = -0.5f * s;
}

// ---------------- fp16 flash attention (3-stage): S = q . KM2 + kb ----------------
// 128-row q-tile; each of 8 warps owns 16 full rows; P stays in registers.
constexpr int KSs = 200;        // K/V smem stride (halfs)
constexpr int KVST = 64 * KSs;  // halfs per stage
constexpr int ATT_SMEM = 3 * 2 * KVST * 2 + 3 * 64 * 4;   // 154368 B

__global__ __launch_bounds__(256, 1) void attn_tc_kernel(
    const __half* __restrict__ Qg, const __half* __restrict__ KM,
    const __half* __restrict__ Vg, const float* __restrict__ kbias,
    __half* __restrict__ y)
{
    extern __shared__ __align__(16) __half smha[];
    __half* ks_base = smha;                       // 3 stages (KM2 tiles)
    __half* vs_base = smha + 3 * KVST;            // 3 stages
    float* kbt_base = (float*)(smha + 6 * KVST);  // 3 x 64

    const int bh = blockIdx.x, qt = blockIdx.y;   // qt: 128-row tile
    const int b = bh >> 2, h = bh & 3;
    const int t = threadIdx.x;
    const int wid = t >> 5, lane = t & 31;
    const int lr4 = lane >> 2, lc4 = lane & 3;
    const int g8 = lane >> 3, l8 = lane & 7;
    const int r0 = wid * 16;                      // warp's q-row base within tile

    auto prefetch = [&](int kt, int st) {
        const __half* kg = KM + ((size_t)bh * Nn + kt * 64) * HDn;
        const __half* vg = Vg + ((size_t)bh * Nn + kt * 64) * HDn;
        __half* ksb = ks_base + st * KVST;
        __half* vsb = vs_base + st * KVST;
#pragma unroll
        for (int i = 0; i < 6; i++) {
            const int ch = t + i * 256;
            const int r = ch / 24, c = ch % 24;
            cp_async16(&ksb[r * KSs + c * 8], kg + r * HDn + c * 8);
            cp_async16(&vsb[r * KSs + c * 8], vg + r * HDn + c * 8);
        }
        if (t < 16) cp_async16(&kbt_base[st * 64 + t * 4],
                               kbias + (size_t)bh * Nn + kt * 64 + t * 4);
    };

    prefetch(0, 0); cp_commit();
    prefetch(1, 1); cp_commit();

    // ---- Q fragments (half2) into registers (one-time) ----
    uint32_t qa[12][4];
    {
        const __half* qb = Qg + ((size_t)bh * Nn + qt * 128) * HDn;
#pragma unroll
        for (int k16 = 0; k16 < 12; k16++) {
            const int kk = k16 * 16;
            qa[k16][0] = *(const uint32_t*)&qb[(r0 + lr4)     * HDn + kk + 2 * lc4];
            qa[k16][1] = *(const uint32_t*)&qb[(r0 + lr4 + 8) * HDn + kk + 2 * lc4];
            qa[k16][2] = *(const uint32_t*)&qb[(r0 + lr4)     * HDn + kk + 8 + 2 * lc4];
            qa[k16][3] = *(const uint32_t*)&qb[(r0 + lr4 + 8) * HDn + kk + 8 + 2 * lc4];
        }
    }

    float O[24][4];
#pragma unroll
    for (int nt = 0; nt < 24; nt++)
#pragma unroll
        for (int q = 0; q < 4; q++) O[nt][q] = 0.f;
    float mr0 = -1e30f, mr1 = -1e30f, l0 = 0.f, l1 = 0.f;

    for (int kt = 0; kt < Nn / 64; kt++) {
        cp_wait<1>();
        __syncthreads();
        if (kt + 2 < Nn / 64) prefetch(kt + 2, (kt + 2) % 3);
        cp_commit();

        const int st = kt % 3;
        const uint32_t ks_u = (uint32_t)__cvta_generic_to_shared(ks_base + st * KVST);
        const uint32_t vs_u = (uint32_t)__cvta_generic_to_shared(vs_base + st * KVST);
        const float* kbt = kbt_base + st * 64;

        // ---- S[16 x 64] = q rows @ KM2_tile^T ----
        float s[8][4];
#pragma unroll
        for (int nt = 0; nt < 8; nt++)
#pragma unroll
            for (int q = 0; q < 4; q++) s[nt][q] = 0.f;
#pragma unroll
        for (int k16 = 0; k16 < 12; k16++) {
            const int kk = k16 * 16;
            uint32_t bf[8][2];
#pragma unroll
            for (int p = 0; p < 4; p++) {
                const int row = p * 16 + (g8 >> 1) * 8 + l8;
                const int col = kk + (g8 & 1) * 8;
                ldsm4(bf[2 * p][0], bf[2 * p][1], bf[2 * p + 1][0], bf[2 * p + 1][1],
                      ks_u + (row * KSs + col) * 2);
            }
#pragma unroll
            for (int nt = 0; nt < 8; nt++)
                mma16h(s[nt], qa[k16][0], qa[k16][1], qa[k16][2], qa[k16][3],
                       bf[nt][0], bf[nt][1]);
        }

        // ---- + key bias, in-warp rowmax ----
        float pm0 = -1e30f, pm1 = -1e30f;
#pragma unroll
        for (int nt = 0; nt < 8; nt++) {
            const int col = nt * 8 + 2 * lc4;
            const float kb0 = kbt[col], kb1 = kbt[col + 1];
            s[nt][0] += kb0; s[nt][1] += kb1;
            s[nt][2] += kb0; s[nt][3] += kb1;
            pm0 = fmaxf(pm0, fmaxf(s[nt][0], s[nt][1]));
            pm1 = fmaxf(pm1, fmaxf(s[nt][2], s[nt][3]));
        }
        pm0 = fmaxf(pm0, __shfl_xor_sync(0xffffffffu, pm0, 1));
        pm0 = fmaxf(pm0, __shfl_xor_sync(0xffffffffu, pm0, 2));
        pm1 = fmaxf(pm1, __shfl_xor_sync(0xffffffffu, pm1, 1));
        pm1 = fmaxf(pm1, __shfl_xor_sync(0xffffffffu, pm1, 2));
        const float mn0 = fmaxf(mr0, pm0), mn1 = fmaxf(mr1, pm1);
        const float cor0 = __expf(mr0 - mn0), cor1 = __expf(mr1 - mn1);
        mr0 = mn0; mr1 = mn1;

        // ---- exp -> P fragments in registers; rowsum ----
        uint32_t pa[4][4];
        float q0 = 0.f, q1 = 0.f;
#pragma unroll
        for (int j = 0; j < 4; j++) {
#pragma unroll
            for (int hh = 0; hh < 2; hh++) {
                const int nt = 2 * j + hh;
                const float e0 = __expf(s[nt][0] - mn0);
                const float e1 = __expf(s[nt][1] - mn0);
                const float e2 = __expf(s[nt][2] - mn1);
                const float e3 = __expf(s[nt][3] - mn1);
                q0 += e0 + e1; q1 += e2 + e3;
                pa[j][2 * hh]     = h2u(__floats2half2_rn(e0, e1));
                pa[j][2 * hh + 1] = h2u(__floats2half2_rn(e2, e3));
            }
        }
        q0 += __shfl_xor_sync(0xffffffffu, q0, 1);
        q0 += __shfl_xor_sync(0xffffffffu, q0, 2);
        q1 += __shfl_xor_sync(0xffffffffu, q1, 1);
        q1 += __shfl_xor_sync(0xffffffffu, q1, 2);
        l0 = l0 * cor0 + q0;
        l1 = l1 * cor1 + q1;
#pragma unroll
        for (int nt = 0; nt < 24; nt++) {
            O[nt][0] *= cor0; O[nt][1] *= cor0;
            O[nt][2] *= cor1; O[nt][3] *= cor1;
        }

        // ---- O += P @ V (V via ldmatrix.trans; P from registers) ----
#pragma unroll
        for (int j = 0; j < 4; j++) {
            const int kk = j * 16;
#pragma unroll
            for (int p = 0; p < 12; p++) {
                const int rowv = kk + (g8 & 1) * 8 + l8;
                const int colv = p * 16 + (g8 >> 1) * 8;
                uint32_t b0A, b1A, b0B, b1B;
                ldsm4t(b0A, b1A, b0B, b1B, vs_u + (rowv * KSs + colv) * 2);
                mma16h(O[2 * p],     pa[j][0], pa[j][1], pa[j][2], pa[j][3], b0A, b1A);
                mma16h(O[2 * p + 1], pa[j][0], pa[j][1], pa[j][2], pa[j][3], b0B, b1B);
            }
        }
    }

    // ---- normalize + write y (half, for proj GEMM) ----
    const float i0v = 1.0f / l0, i1v = 1.0f / l1;
    const int nrow0 = qt * 128 + r0 + lr4;
    __half* y0 = y + (size_t)(b * Nn + nrow0) * Cdim + h * HDn;
    __half* y1 = y0 + 8 * Cdim;
#pragma unroll
    for (int nt = 0; nt < 24; nt++) {
        const int col = nt * 8 + 2 * lc4;
        *(__half2*)&y0[col] = __floats2half2_rn(O[nt][0] * i0v, O[nt][1] * i0v);
        *(__half2*)&y1[col] = __floats2half2_rn(O[nt][2] * i1v, O[nt][3] * i1v);
    }
}

// ---------------- fused LN2 + RBF features ----------------
constexpr int RBF_SMEM_BYTES = (CEN * Cdim + 2 * CEN) * 4;

__global__ __launch_bounds__(256) void rbf_fused_kernel(
    const float* __restrict__ x1, const float* __restrict__ n2w,
    const float* __restrict__ n2b, const float* __restrict__ centers,
    const float* __restrict__ beta, float* __restrict__ rbf)
{
    extern __shared__ __align__(16) float rsm[];
    float* cs = rsm;                    // [CEN][Cdim]
    float* cn = rsm + CEN * Cdim;       // [CEN]
    float* bt = cn + CEN;               // [CEN]
    const int t = threadIdx.x;
    for (int i = t; i < CEN * Cdim; i += 256) cs[i] = centers[i];
    __syncthreads();
    if (t < CEN) {
        float s = 0.f;
        for (int k = 0; k < Cdim; k++) s += cs[t * Cdim + k] * cs[t * Cdim + k];
        cn[t] = s;
        bt[t] = beta[t];
    }
    __syncthreads();
    const int wid = t >> 5, lane = t & 31;
    const float4* w4 = (const float4*)n2w;
    const float4* b4 = (const float4*)n2b;
    for (int rr = 0; rr < 8; rr++) {
        const int row = blockIdx.x * 64 + wid * 8 + rr;
        const float4* xr = (const float4*)(x1 + (size_t)row * Cdim);
        float4 v[6];
        float s = 0.f, s2 = 0.f;
#pragma unroll
        for (int i = 0; i < 6; i++) {
            v[i] = xr[lane + i * 32];
            s  += v[i].x + v[i].y + v[i].z + v[i].w;
            s2 += v[i].x * v[i].x + v[i].y * v[i].y + v[i].z * v[i].z + v[i].w * v[i].w;
        }
        s = warpsum32(s); s2 = warpsum32(s2);
        const float mu  = s * (1.0f / Cdim);
        const float var = s2 * (1.0f / Cdim) - mu * mu;
        const float rs  = rsqrtf(var + EPSv);
        float hv[24];
        float a = 0.f;
#pragma unroll
        for (int i = 0; i < 6; i++) {
            const int idx = lane + i * 32;
            const float4 wv = w4[idx], bv = b4[idx];
            hv[4 * i + 0] = (v[i].x - mu) * rs * wv.x + bv.x;
            hv[4 * i + 1] = (v[i].y - mu) * rs * wv.y + bv.y;
            hv[4 * i + 2] = (v[i].z - mu) * rs * wv.z + bv.z;
            hv[4 * i + 3] = (v[i].w - mu) * rs * wv.w + bv.w;
            a += hv[4*i]*hv[4*i] + hv[4*i+1]*hv[4*i+1] + hv[4*i+2]*hv[4*i+2] + hv[4*i+3]*hv[4*i+3];
        }
        a = warpsum32(a);
        for (int j = 0; j < CEN; j++) {
            const float4* cj = (const float4*)(cs + j * Cdim);
            float d = 0.f;
#pragma unroll
            for (int i = 0; i < 6; i++) {
                const float4 cv = cj[lane + i * 32];
                d += hv[4*i]*cv.x + hv[4*i+1]*cv.y + hv[4*i+2]*cv.z + hv[4*i+3]*cv.w;
            }
            d = warpsum32(d);
            if (lane == 0)
                rbf[(size_t)row * CEN + j] = __expf(-bt[j] * (a - 2.0f * d + cn[j]));
        }
    }
}

// ---------------- final: out = x1 + rbf @ fc_w^T ----------------
__global__ __launch_bounds__(256) void final_kernel(
    const float* __restrict__ x1, const float* __restrict__ rbf,
    const float* __restrict__ fcw, float* __restrict__ out)
{
    const int i = blockIdx.x * 256 + threadIdx.x;
    if (i >= Sn * Cdim) return;
    const int c = i % Cdim;
    const int r = i / Cdim;
    const float* rb = rbf + (size_t)r * CEN;
    const float* fw = fcw + (size_t)c * CEN;
    float acc = x1[i];
#pragma unroll
    for (int j = 0; j < CEN; j++) acc += rb[j] * fw[j];
    out[i] = acc;
}

// ---------------- launcher ----------------
extern "C" void kernel_launch(void* const* d_in, const int* in_sizes, int n_in,
                              void* d_out, int out_size)
{
    (void)in_sizes; (void)n_in; (void)out_size;
    const float* x     = (const float*)d_in[0];
    const float* n1w   = (const float*)d_in[1];
    const float* n1b   = (const float*)d_in[2];
    const float* qkvw  = (const float*)d_in[3];
    const float* Mmat  = (const float*)d_in[4];
    const float* scale = (const float*)d_in[5];
    const float* projw = (const float*)d_in[6];
    const float* projb = (const float*)d_in[7];
    const float* n2w   = (const float*)d_in[8];
    const float* n2b   = (const float*)d_in[9];
    const float* cent  = (const float*)d_in[10];
    const float* beta  = (const float*)d_in[11];
    const float* fcw   = (const float*)d_in[12];
    float* out = (float*)d_out;

    __half *hP, *qwP, *pwP, *QgP, *KgP, *VgP, *KMP, *MhP, *yP;
    float *kbP, *x1P, *rbfP;
    cudaGetSymbolAddress((void**)&hP,   g_h);
    cudaGetSymbolAddress((void**)&qwP,  g_qkvwr);
    cudaGetSymbolAddress((void**)&pwP,  g_projwr);
    cudaGetSymbolAddress((void**)&QgP,  g_Qg);
    cudaGetSymbolAddress((void**)&KgP,  g_Kg);
    cudaGetSymbolAddress((void**)&VgP,  g_Vg);
    cudaGetSymbolAddress((void**)&KMP,  g_KM);
    cudaGetSymbolAddress((void**)&MhP,  g_Mh);
    cudaGetSymbolAddress((void**)&kbP,  g_kb);
    cudaGetSymbolAddress((void**)&yP,   g_y);
    cudaGetSymbolAddress((void**)&x1P,  g_x1);
    cudaGetSymbolAddress((void**)&rbfP, g_rbf);

    constexpr int GS128 = 3 * (128 + 128) * 64 * 2;   // 98304 B
    constexpr int GS64  = 3 * (128 + 64) * 64 * 2;    // 73728 B
    cudaFuncSetAttribute(gemm_h<128, 1>, cudaFuncAttributeMaxDynamicSharedMemorySize, GS128);
    cudaFuncSetAttribute(gemm_h<128, 2>, cudaFuncAttributeMaxDynamicSharedMemorySize, GS128);
    cudaFuncSetAttribute(gemm_h<64, 0>,  cudaFuncAttributeMaxDynamicSharedMemorySize, GS64);
    cudaFuncSetAttribute(attn_tc_kernel, cudaFuncAttributeMaxDynamicSharedMemorySize, ATT_SMEM);
    cudaFuncSetAttribute(rbf_fused_kernel, cudaFuncAttributeMaxDynamicSharedMemorySize, RBF_SMEM_BYTES);

    // 0) weight conversion (fp16) + scaled M
    half_copy4_kernel<<<512, 256>>>((const float4*)qkvw, qwP, 3 * Cdim * Cdim / 4);
    half_copy4_kernel<<<256, 256>>>((const float4*)projw, pwP, Cdim * Cdim / 4);
    scale_m_kernel<<<(HDn * HDn + 255) / 256, 256>>>(Mmat, scale, MhP);
    // 1) LN1 (half out)
    ln1_kernel<<<Sn / 8, 256>>>(x, n1w, n1b, hP);
    // 2) qkv GEMM fused with gather -> Qg/Kg/Vg (half)
    gemm_h<128, 1><<<dim3(3 * Cdim / 128, Sn / 128), 256, GS128>>>(
        hP, qwP, QgP, KgP, VgP, Sn, 3 * Cdim, Cdim, nullptr, nullptr);
    // 3) KM2 = K @ (2*scale*M)^T (half out)  — the only M-transform needed
    gemm_h<64, 0><<<dim3(HDn / 64, BHn * Nn / 128), 256, GS64>>>(
        KgP, MhP, KMP, nullptr, nullptr, BHn * Nn, HDn, HDn, nullptr, nullptr);
    // 4) per-key bias kb = -0.5 * K.KM2
    kbias_kernel<<<(BHn * Nn) * 32 / 256, 256>>>(KgP, KMP, kbP);
    // 5) fp16 flash attention (q . KM2 + kb) -> y (half)
    attn_tc_kernel<<<dim3(BHn, Nn / 128), 256, ATT_SMEM>>>(QgP, KMP, VgP, kbP, yP);
    // 6) x1 = x + y @ proj_w^T + proj_b (fp32 out)
    gemm_h<128, 2><<<dim3(Cdim / 128, Sn / 128), 256, GS128>>>(
        yP, pwP, x1P, nullptr, nullptr, Sn, Cdim, Cdim, projb, x);
    // 7) fused LN2 + RBF
    rbf_fused_kernel<<<Sn / 64, 256, RBF_SMEM_BYTES>>>(x1P, n2w, n2b, cent, beta, rbfP);
    // 8) out = x1 + rbf @ fc_w^T
    final_kernel<<<(Sn * Cdim + 255) / 256, 256>>>(x1P, rbfP, fcw, out);
}

// round 11
// speedup vs baseline: 12.2214x; 1.3083x over previous
#include <cuda_runtime.h>
#include <cuda_fp16.h>
#include <cstdint>

// ---------------- problem constants ----------------
constexpr int Cdim = 768;
constexpr int Bn   = 8;
constexpr int Nn   = 1024;
constexpr int HDn  = 192;            // head dim
constexpr int Sn   = Bn * Nn;        // 8192 rows
constexpr int BHn  = Bn * 4;         // 32
constexpr int CEN  = 20;
constexpr float EPSv = 1e-5f;

// ---------------- scratch (device globals; no allocation allowed) ----------------
__device__ __half g_h     [Sn * Cdim];
__device__ __half g_qkvwr [3 * Cdim * Cdim];
__device__ __half g_projwr[Cdim * Cdim];
__device__ __half g_Qg  [BHn * Nn * HDn];
__device__ __half g_Kg  [BHn * Nn * HDn];
__device__ __half g_Vg  [BHn * Nn * HDn];
__device__ __half g_KM  [BHn * Nn * HDn];   // KM2 = K @ (2*scale*M)^T
__device__ __half g_Mh  [HDn * HDn];        // 2*scale*M (half)
__device__ float  g_kb  [BHn * Nn];
__device__ __half g_y   [Sn * Cdim];
__device__ float  g_x1  [Sn * Cdim];

// ---------------- helpers ----------------
__device__ __forceinline__ float warpsum32(float v) {
#pragma unroll
    for (int o = 16; o >= 1; o >>= 1) v += __shfl_xor_sync(0xffffffffu, v, o);
    return v;
}
__device__ __forceinline__ uint32_t h2u(__half2 h) {
    return *reinterpret_cast<uint32_t*>(&h);
}
__device__ __forceinline__ void mma16h(float* c,
    uint32_t a0, uint32_t a1, uint32_t a2, uint32_t a3, uint32_t b0, uint32_t b1)
{
    asm volatile("mma.sync.aligned.m16n8k16.row.col.f32.f16.f16.f32 "
        "{%0,%1,%2,%3}, {%4,%5,%6,%7}, {%8,%9}, {%0,%1,%2,%3};"
        : "+f"(c[0]), "+f"(c[1]), "+f"(c[2]), "+f"(c[3])
        : "r"(a0), "r"(a1), "r"(a2), "r"(a3), "r"(b0), "r"(b1));
}
__device__ __forceinline__ void ldsm4(uint32_t& r0, uint32_t& r1, uint32_t& r2, uint32_t& r3,
                                      uint32_t addr)
{
    asm volatile("ldmatrix.sync.aligned.m8n8.x4.shared.b16 {%0,%1,%2,%3}, [%4];"
        : "=r"(r0), "=r"(r1), "=r"(r2), "=r"(r3) : "r"(addr));
}
__device__ __forceinline__ void ldsm4t(uint32_t& r0, uint32_t& r1, uint32_t& r2, uint32_t& r3,
                                       uint32_t addr)
{
    asm volatile("ldmatrix.sync.aligned.m8n8.x4.trans.shared.b16 {%0,%1,%2,%3}, [%4];"
        : "=r"(r0), "=r"(r1), "=r"(r2), "=r"(r3) : "r"(addr));
}
__device__ __forceinline__ void cp_async16(void* smem, const void* gmem) {
    uint32_t s = (uint32_t)__cvta_generic_to_shared(smem);
    asm volatile("cp.async.cg.shared.global [%0], [%1], 16;\n" :: "r"(s), "l"(gmem));
}
__device__ __forceinline__ void cp_commit() {
    asm volatile("cp.async.commit_group;\n");
}
template<int N>
__device__ __forceinline__ void cp_wait() {
    asm volatile("cp.async.wait_group %0;\n" :: "n"(N));
}

// ---------------- LayerNorm (LN1): warp per row, half output ----------------
__global__ __launch_bounds__(256) void ln1_kernel(
    const float* __restrict__ x, const float* __restrict__ w,
    const float* __restrict__ b, __half* __restrict__ out)
{
    const int row  = blockIdx.x * 8 + (threadIdx.x >> 5);
    const int lane = threadIdx.x & 31;
    const float4* xr = (const float4*)(x + (size_t)row * Cdim);
    float4 v[6];
    float s = 0.f, s2 = 0.f;
#pragma unroll
    for (int i = 0; i < 6; i++) {
        v[i] = xr[lane + i * 32];
        s  += v[i].x + v[i].y + v[i].z + v[i].w;
        s2 += v[i].x * v[i].x + v[i].y * v[i].y + v[i].z * v[i].z + v[i].w * v[i].w;
    }
    s = warpsum32(s); s2 = warpsum32(s2);
    const float mu  = s * (1.0f / Cdim);
    const float var = s2 * (1.0f / Cdim) - mu * mu;
    const float rs  = rsqrtf(var + EPSv);
    const float4* w4 = (const float4*)w;
    const float4* b4 = (const float4*)b;
#pragma unroll
    for (int i = 0; i < 6; i++) {
        const int idx = lane + i * 32;
        const float4 wv = w4[idx], bv = b4[idx];
        __half* orow = out + (size_t)row * Cdim + 4 * idx;
        *(__half2*)&orow[0] = __floats2half2_rn((v[i].x - mu) * rs * wv.x + bv.x,
                                                (v[i].y - mu) * rs * wv.y + bv.y);
        *(__half2*)&orow[2] = __floats2half2_rn((v[i].z - mu) * rs * wv.z + bv.z,
                                                (v[i].w - mu) * rs * wv.w + bv.w);
    }
}

// ---------------- f32 -> f16 copy (vectorized) ----------------
__global__ __launch_bounds__(256) void half_copy4_kernel(
    const float4* __restrict__ src, __half* __restrict__ dst, int n4)
{
    for (int i = blockIdx.x * 256 + threadIdx.x; i < n4; i += gridDim.x * 256) {
        const float4 v = src[i];
        *(__half2*)&dst[4 * i]     = __floats2half2_rn(v.x, v.y);
        *(__half2*)&dst[4 * i + 2] = __floats2half2_rn(v.z, v.w);
    }
}

// ---------------- Mh = 2*scale*M (half, same layout) ----------------
__global__ __launch_bounds__(256) void scale_m_kernel(
    const float* __restrict__ M, const float* __restrict__ scale_p,
    __half* __restrict__ Mh)
{
    const int i = blockIdx.x * 256 + threadIdx.x;
    if (i >= HDn * HDn) return;
    Mh[i] = __float2half(2.0f * scale_p[0] * M[i]);
}

// ---------------- 3-stage pipelined fp16 NT GEMM: C = A[M,K] * B[N,K]^T ----------------
// MODE 0: half store. MODE 1: qkv scatter -> Q/K/V half [BH][N][HD]. MODE 2: fp32 +bias+resid.
template<int BN, int MODE>
__global__ __launch_bounds__(256) void gemm_h(
    const __half* __restrict__ A, const __half* __restrict__ B, void* __restrict__ Cv,
    __half* __restrict__ C2, __half* __restrict__ C3,
    int Md, int Nd, int Kd,
    const float* __restrict__ bias, const float* __restrict__ resid)
{
    (void)Md;
    constexpr int BM = 128, BK = 64;
    constexpr int WM = (BN == 128) ? 2 : 4;
    constexpr int WN = 8 / WM;
    constexpr int WTM = BM / WM, WTN = BN / WN;
    constexpr int MT = WTM / 16, NT = WTN / 8;
    constexpr int ASTG = BM * BK;
    constexpr int BSTG = BN * BK;

    extern __shared__ __align__(16) __half smh[];
    __half* As = smh;                 // 3 stages
    __half* Bs = smh + 3 * ASTG;      // 3 stages

    const int t = threadIdx.x;
    const int wid = t >> 5, lane = t & 31;
    const int wm = wid % WM, wn = wid / WM;
    const int lr4 = lane >> 2, lc4 = lane & 3;
    const int g8 = lane >> 3, l8 = lane & 7;
    const int m0 = blockIdx.y * BM, n0 = blockIdx.x * BN;

    const __half* Ab = A + (size_t)m0 * Kd;
    const __half* Bb = B + (size_t)n0 * Kd;

    auto prefetch = [&](int kt, int st) {
        const __half* Ag = Ab + kt * BK;
        const __half* Bg = Bb + kt * BK;
#pragma unroll
        for (int i = 0; i < BM / 32; i++) {
            const int ch = t + i * 256;
            const int r = ch >> 3, c = ch & 7;
            cp_async16(&As[st * ASTG + (r * 8 + (c ^ (r & 7))) * 8], Ag + (size_t)r * Kd + c * 8);
        }
#pragma unroll
        for (int i = 0; i < BN / 32; i++) {
            const int ch = t + i * 256;
            const int r = ch >> 3, c = ch & 7;
            cp_async16(&Bs[st * BSTG + (r * 8 + (c ^ (r & 7))) * 8], Bg + (size_t)r * Kd + c * 8);
        }
    };

    float acc[MT][NT][4];
#pragma unroll
    for (int i = 0; i < MT; i++)
#pragma unroll
        for (int j = 0; j < NT; j++)
#pragma unroll
            for (int q = 0; q < 4; q++) acc[i][j][q] = 0.f;

    const int nK = Kd / BK;
    prefetch(0, 0); cp_commit();
    prefetch(1, 1); cp_commit();

    for (int kt = 0; kt < nK; kt++) {
        cp_wait<1>();
        __syncthreads();
        if (kt + 2 < nK) prefetch(kt + 2, (kt + 2) % 3);
        cp_commit();

        const int st = kt % 3;
        const uint32_t Au = (uint32_t)__cvta_generic_to_shared(As + st * ASTG);
        const uint32_t Bu = (uint32_t)__cvta_generic_to_shared(Bs + st * BSTG);

#pragma unroll
        for (int k16 = 0; k16 < BK / 16; k16++) {
            uint32_t bf[NT][2];
#pragma unroll
            for (int p = 0; p < NT / 2; p++) {
                const int row = wn * WTN + p * 16 + (g8 >> 1) * 8 + l8;
                const int ch  = (2 * k16 + (g8 & 1)) ^ l8;
                ldsm4(bf[2 * p][0], bf[2 * p][1], bf[2 * p + 1][0], bf[2 * p + 1][1],
                      Bu + (row * 8 + ch) * 16);
            }
#pragma unroll
            for (int mt = 0; mt < MT; mt++) {
                const int rowA = wm * WTM + mt * 16 + (g8 & 1) * 8 + l8;
                const int chA  = (2 * k16 + (g8 >> 1)) ^ l8;
                uint32_t a0, a1, a2, a3;
                ldsm4(a0, a1, a2, a3, Au + (rowA * 8 + chA) * 16);
#pragma unroll
                for (int nt = 0; nt < NT; nt++)
                    mma16h(acc[mt][nt], a0, a1, a2, a3, bf[nt][0], bf[nt][1]);
            }
        }
    }

#pragma unroll
    for (int mt = 0; mt < MT; mt++) {
        const int mbase = m0 + wm * WTM + mt * 16 + lr4;
#pragma unroll
        for (int nt = 0; nt < NT; nt++) {
            const int n = n0 + wn * WTN + nt * 8 + 2 * lc4;
            if (MODE == 0) {
                __half* C = (__half*)Cv;
                *(__half2*)&C[(size_t)mbase * Nd + n] =
                    __floats2half2_rn(acc[mt][nt][0], acc[mt][nt][1]);
                *(__half2*)&C[(size_t)(mbase + 8) * Nd + n] =
                    __floats2half2_rn(acc[mt][nt][2], acc[mt][nt][3]);
            } else if (MODE == 1) {
                const int which = n / Cdim;
                const int rem = n % Cdim;
                const int h = rem / HDn, d = rem % HDn;
                __half* dst = (which == 0) ? (__half*)Cv : (which == 1) ? C2 : C3;
#pragma unroll
                for (int rr = 0; rr < 2; rr++) {
                    const int m = mbase + rr * 8;
                    const int b = m >> 10, nr = m & 1023;
                    const size_t di = ((size_t)((b << 2) + h) * Nn + nr) * HDn + d;
                    *(__half2*)&dst[di] =
                        __floats2half2_rn(acc[mt][nt][rr * 2], acc[mt][nt][rr * 2 + 1]);
                }
            } else {
                float* C = (float*)Cv;
                const float b0 = bias[n], b1 = bias[n + 1];
                const size_t i0 = (size_t)mbase * Nd + n;
                const size_t i1 = (size_t)(mbase + 8) * Nd + n;
                *(float2*)&C[i0] = make_float2(acc[mt][nt][0] + b0 + resid[i0],
                                               acc[mt][nt][1] + b1 + resid[i0 + 1]);
                *(float2*)&C[i1] = make_float2(acc[mt][nt][2] + b0 + resid[i1],
                                               acc[mt][nt][3] + b1 + resid[i1 + 1]);
            }
        }
    }
}

// ---------------- per-key bias: kb[r] = -0.5 * dot(K[r], KM2[r]) ----------------
__global__ __launch_bounds__(256) void kbias_kernel(
    const __half* __restrict__ Kg, const __half* __restrict__ KM,
    float* __restrict__ kb)
{
    const int gw = (blockIdx.x * 256 + threadIdx.x) >> 5;
    const int lane = threadIdx.x & 31;
    if (gw >= BHn * Nn) return;
    const __half2* kr  = (const __half2*)(Kg + (size_t)gw * HDn);
    const __half2* kmr = (const __half2*)(KM + (size_t)gw * HDn);
    float s = 0.f;
#pragma unroll
    for (int i = 0; i < 3; i++) {
        const float2 a = __half22float2(kr[lane + i * 32]);
        const float2 b = __half22float2(kmr[lane + i * 32]);
        s += a.x * b.x + a.y * b.y;
    }
    s = warpsum32(s);
    if (lane == 0) kb[gw] = -0.5f * s;
}

// ---------------- fp16 flash attention (3-stage): S = q . KM2 + kb ----------------
// 128-row q-tile; each of 8 warps owns 16 full rows; P stays in registers.
constexpr int KSs = 200;        // K/V smem stride (halfs)
constexpr int KVST = 64 * KSs;  // halfs per stage
constexpr int ATT_SMEM = 3 * 2 * KVST * 2 + 3 * 64 * 4;   // 154368 B

__global__ __launch_bounds__(256, 1) void attn_tc_kernel(
    const __half* __restrict__ Qg, const __half* __restrict__ KM,
    const __half* __restrict__ Vg, const float* __restrict__ kbias,
    __half* __restrict__ y)
{
    extern __shared__ __align__(16) __half smha[];
    __half* ks_base = smha;                       // 3 stages (KM2 tiles)
    __half* vs_base = smha + 3 * KVST;            // 3 stages
    float* kbt_base = (float*)(smha + 6 * KVST);  // 3 x 64

    const int bh = blockIdx.x, qt = blockIdx.y;   // qt: 128-row tile
    const int b = bh >> 2, h = bh & 3;
    const int t = threadIdx.x;
    const int wid = t >> 5, lane = t & 31;
    const int lr4 = lane >> 2, lc4 = lane & 3;
    const int g8 = lane >> 3, l8 = lane & 7;
    const int r0 = wid * 16;

    auto prefetch = [&](int kt, int st) {
        const __half* kg = KM + ((size_t)bh * Nn + kt * 64) * HDn;
        const __half* vg = Vg + ((size_t)bh * Nn + kt * 64) * HDn;
        __half* ksb = ks_base + st * KVST;
        __half* vsb = vs_base + st * KVST;
#pragma unroll
        for (int i = 0; i < 6; i++) {
            const int ch = t + i * 256;
            const int r = ch / 24, c = ch % 24;
            cp_async16(&ksb[r * KSs + c * 8], kg + r * HDn + c * 8);
            cp_async16(&vsb[r * KSs + c * 8], vg + r * HDn + c * 8);
        }
        if (t < 16) cp_async16(&kbt_base[st * 64 + t * 4],
                               kbias + (size_t)bh * Nn + kt * 64 + t * 4);
    };

    prefetch(0, 0); cp_commit();
    prefetch(1, 1); cp_commit();

    uint32_t qa[12][4];
    {
        const __half* qb = Qg + ((size_t)bh * Nn + qt * 128) * HDn;
#pragma unroll
        for (int k16 = 0; k16 < 12; k16++) {
            const int kk = k16 * 16;
            qa[k16][0] = *(const uint32_t*)&qb[(r0 + lr4)     * HDn + kk + 2 * lc4];
            qa[k16][1] = *(const uint32_t*)&qb[(r0 + lr4 + 8) * HDn + kk + 2 * lc4];
            qa[k16][2] = *(const uint32_t*)&qb[(r0 + lr4)     * HDn + kk + 8 + 2 * lc4];
            qa[k16][3] = *(const uint32_t*)&qb[(r0 + lr4 + 8) * HDn + kk + 8 + 2 * lc4];
        }
    }

    float O[24][4];
#pragma unroll
    for (int nt = 0; nt < 24; nt++)
#pragma unroll
        for (int q = 0; q < 4; q++) O[nt][q] = 0.f;
    float mr0 = -1e30f, mr1 = -1e30f, l0 = 0.f, l1 = 0.f;

    for (int kt = 0; kt < Nn / 64; kt++) {
        cp_wait<1>();
        __syncthreads();
        if (kt + 2 < Nn / 64) prefetch(kt + 2, (kt + 2) % 3);
        cp_commit();

        const int st = kt % 3;
        const uint32_t ks_u = (uint32_t)__cvta_generic_to_shared(ks_base + st * KVST);
        const uint32_t vs_u = (uint32_t)__cvta_generic_to_shared(vs_base + st * KVST);
        const float* kbt = kbt_base + st * 64;

        float s[8][4];
#pragma unroll
        for (int nt = 0; nt < 8; nt++)
#pragma unroll
            for (int q = 0; q < 4; q++) s[nt][q] = 0.f;
#pragma unroll
        for (int k16 = 0; k16 < 12; k16++) {
            const int kk = k16 * 16;
            uint32_t bf[8][2];
#pragma unroll
            for (int p = 0; p < 4; p++) {
                const int row = p * 16 + (g8 >> 1) * 8 + l8;
                const int col = kk + (g8 & 1) * 8;
                ldsm4(bf[2 * p][0], bf[2 * p][1], bf[2 * p + 1][0], bf[2 * p + 1][1],
                      ks_u + (row * KSs + col) * 2);
            }
#pragma unroll
            for (int nt = 0; nt < 8; nt++)
                mma16h(s[nt], qa[k16][0], qa[k16][1], qa[k16][2], qa[k16][3],
                       bf[nt][0], bf[nt][1]);
        }

        float pm0 = -1e30f, pm1 = -1e30f;
#pragma unroll
        for (int nt = 0; nt < 8; nt++) {
            const int col = nt * 8 + 2 * lc4;
            const float kb0 = kbt[col], kb1 = kbt[col + 1];
            s[nt][0] += kb0; s[nt][1] += kb1;
            s[nt][2] += kb0; s[nt][3] += kb1;
            pm0 = fmaxf(pm0, fmaxf(s[nt][0], s[nt][1]));
            pm1 = fmaxf(pm1, fmaxf(s[nt][2], s[nt][3]));
        }
        pm0 = fmaxf(pm0, __shfl_xor_sync(0xffffffffu, pm0, 1));
        pm0 = fmaxf(pm0, __shfl_xor_sync(0xffffffffu, pm0, 2));
        pm1 = fmaxf(pm1, __shfl_xor_sync(0xffffffffu, pm1, 1));
        pm1 = fmaxf(pm1, __shfl_xor_sync(0xffffffffu, pm1, 2));
        const float mn0 = fmaxf(mr0, pm0), mn1 = fmaxf(mr1, pm1);
        const float cor0 = __expf(mr0 - mn0), cor1 = __expf(mr1 - mn1);
        mr0 = mn0; mr1 = mn1;

        uint32_t pa[4][4];
        float q0 = 0.f, q1 = 0.f;
#pragma unroll
        for (int j = 0; j < 4; j++) {
#pragma unroll
            for (int hh = 0; hh < 2; hh++) {
                const int nt = 2 * j + hh;
                const float e0 = __expf(s[nt][0] - mn0);
                const float e1 = __expf(s[nt][1] - mn0);
                const float e2 = __expf(s[nt][2] - mn1);
                const float e3 = __expf(s[nt][3] - mn1);
                q0 += e0 + e1; q1 += e2 + e3;
                pa[j][2 * hh]     = h2u(__floats2half2_rn(e0, e1));
                pa[j][2 * hh + 1] = h2u(__floats2half2_rn(e2, e3));
            }
        }
        q0 += __shfl_xor_sync(0xffffffffu, q0, 1);
        q0 += __shfl_xor_sync(0xffffffffu, q0, 2);
        q1 += __shfl_xor_sync(0xffffffffu, q1, 1);
        q1 += __shfl_xor_sync(0xffffffffu, q1, 2);
        l0 = l0 * cor0 + q0;
        l1 = l1 * cor1 + q1;
#pragma unroll
        for (int nt = 0; nt < 24; nt++) {
            O[nt][0] *= cor0; O[nt][1] *= cor0;
            O[nt][2] *= cor1; O[nt][3] *= cor1;
        }

#pragma unroll
        for (int j = 0; j < 4; j++) {
            const int kk = j * 16;
#pragma unroll
            for (int p = 0; p < 12; p++) {
                const int rowv = kk + (g8 & 1) * 8 + l8;
                const int colv = p * 16 + (g8 >> 1) * 8;
                uint32_t b0A, b1A, b0B, b1B;
                ldsm4t(b0A, b1A, b0B, b1B, vs_u + (rowv * KSs + colv) * 2);
                mma16h(O[2 * p],     pa[j][0], pa[j][1], pa[j][2], pa[j][3], b0A, b1A);
                mma16h(O[2 * p + 1], pa[j][0], pa[j][1], pa[j][2], pa[j][3], b0B, b1B);
            }
        }
    }

    const float i0v = 1.0f / l0, i1v = 1.0f / l1;
    const int nrow0 = qt * 128 + r0 + lr4;
    __half* y0 = y + (size_t)(b * Nn + nrow0) * Cdim + h * HDn;
    __half* y1 = y0 + 8 * Cdim;
#pragma unroll
    for (int nt = 0; nt < 24; nt++) {
        const int col = nt * 8 + 2 * lc4;
        *(__half2*)&y0[col] = __floats2half2_rn(O[nt][0] * i0v, O[nt][1] * i0v);
        *(__half2*)&y1[col] = __floats2half2_rn(O[nt][2] * i1v, O[nt][3] * i1v);
    }
}

// ---------------- fused LN2 + RBF + fc + residual -> out ----------------
// out[row] = x1[row] + rbf(LN2(x1[row])) @ fc_w^T
constexpr int RBF_SMEM_BYTES = (2 * CEN * Cdim + 2 * CEN) * 4;  // 123040 B

__global__ __launch_bounds__(256) void rbf_final_kernel(
    const float* __restrict__ x1, const float* __restrict__ n2w,
    const float* __restrict__ n2b, const float* __restrict__ centers,
    const float* __restrict__ beta, const float* __restrict__ fcw,
    float* __restrict__ out)
{
    extern __shared__ __align__(16) float rsm[];
    float* cs   = rsm;                       // [CEN][Cdim] centers
    float* fwT  = rsm + CEN * Cdim;          // [CEN][Cdim] fc_w transposed
    float* cn   = fwT + CEN * Cdim;          // [CEN]
    float* bt   = cn + CEN;                  // [CEN]
    const int t = threadIdx.x;
    for (int i = t; i < CEN * Cdim; i += 256) {
        cs[i] = centers[i];
        const int j = i / Cdim, c = i % Cdim;
        fwT[i] = fcw[c * CEN + j];
    }
    __syncthreads();
    if (t < CEN) {
        float s = 0.f;
        for (int k = 0; k < Cdim; k++) s += cs[t * Cdim + k] * cs[t * Cdim + k];
        cn[t] = s;
        bt[t] = beta[t];
    }
    __syncthreads();
    const int wid = t >> 5, lane = t & 31;
    const float4* w4 = (const float4*)n2w;
    const float4* b4 = (const float4*)n2b;
    for (int rr = 0; rr < 8; rr++) {
        const int row = blockIdx.x * 64 + wid * 8 + rr;
        const float4* xr = (const float4*)(x1 + (size_t)row * Cdim);
        float4 v[6];
        float s = 0.f, s2 = 0.f;
#pragma unroll
        for (int i = 0; i < 6; i++) {
            v[i] = xr[lane + i * 32];
            s  += v[i].x + v[i].y + v[i].z + v[i].w;
            s2 += v[i].x * v[i].x + v[i].y * v[i].y + v[i].z * v[i].z + v[i].w * v[i].w;
        }
        s = warpsum32(s); s2 = warpsum32(s2);
        const float mu  = s * (1.0f / Cdim);
        const float var = s2 * (1.0f / Cdim) - mu * mu;
        const float rs  = rsqrtf(var + EPSv);
        float hv[24];
        float a = 0.f;
#pragma unroll
        for (int i = 0; i < 6; i++) {
            const int idx = lane + i * 32;
            const float4 wv = w4[idx], bv = b4[idx];
            hv[4 * i + 0] = (v[i].x - mu) * rs * wv.x + bv.x;
            hv[4 * i + 1] = (v[i].y - mu) * rs * wv.y + bv.y;
            hv[4 * i + 2] = (v[i].z - mu) * rs * wv.z + bv.z;
            hv[4 * i + 3] = (v[i].w - mu) * rs * wv.w + bv.w;
            a += hv[4*i]*hv[4*i] + hv[4*i+1]*hv[4*i+1] + hv[4*i+2]*hv[4*i+2] + hv[4*i+3]*hv[4*i+3];
        }
        a = warpsum32(a);
        // rbf values — warpsum leaves result in all lanes, so every lane holds all 20
        float rj[CEN];
#pragma unroll
        for (int j = 0; j < CEN; j++) {
            const float4* cj = (const float4*)(cs + j * Cdim);
            float d = 0.f;
#pragma unroll
            for (int i = 0; i < 6; i++) {
                const float4 cv = cj[lane + i * 32];
                d += hv[4*i]*cv.x + hv[4*i+1]*cv.y + hv[4*i+2]*cv.z + hv[4*i+3]*cv.w;
            }
            d = warpsum32(d);
            rj[j] = __expf(-bt[j] * (a - 2.0f * d + cn[j]));
        }
        // out = x1 + rbf @ fc_w^T  (fwT[j][c] in smem)
        float4* orow = (float4*)(out + (size_t)row * Cdim);
#pragma unroll
        for (int i = 0; i < 6; i++) {
            const int idx = lane + i * 32;
            float4 o = v[i];
#pragma unroll
            for (int j = 0; j < CEN; j++) {
                const float4 fv = *(const float4*)&fwT[j * Cdim + 4 * idx];
                o.x += rj[j] * fv.x;
                o.y += rj[j] * fv.y;
                o.z += rj[j] * fv.z;
                o.w += rj[j] * fv.w;
            }
            orow[idx] = o;
        }
    }
}

// ---------------- launcher ----------------
extern "C" void kernel_launch(void* const* d_in, const int* in_sizes, int n_in,
                              void* d_out, int out_size)
{
    (void)in_sizes; (void)n_in; (void)out_size;
    const float* x     = (const float*)d_in[0];
    const float* n1w   = (const float*)d_in[1];
    const float* n1b   = (const float*)d_in[2];
    const float* qkvw  = (const float*)d_in[3];
    const float* Mmat  = (const float*)d_in[4];
    const float* scale = (const float*)d_in[5];
    const float* projw = (const float*)d_in[6];
    const float* projb = (const float*)d_in[7];
    const float* n2w   = (const float*)d_in[8];
    const float* n2b   = (const float*)d_in[9];
    const float* cent  = (const float*)d_in[10];
    const float* beta  = (const float*)d_in[11];
    const float* fcw   = (const float*)d_in[12];
    float* out = (float*)d_out;

    __half *hP, *qwP, *pwP, *QgP, *KgP, *VgP, *KMP, *MhP, *yP;
    float *kbP, *x1P;
    cudaGetSymbolAddress((void**)&hP,   g_h);
    cudaGetSymbolAddress((void**)&qwP,  g_qkvwr);
    cudaGetSymbolAddress((void**)&pwP,  g_projwr);
    cudaGetSymbolAddress((void**)&QgP,  g_Qg);
    cudaGetSymbolAddress((void**)&KgP,  g_Kg);
    cudaGetSymbolAddress((void**)&VgP,  g_Vg);
    cudaGetSymbolAddress((void**)&KMP,  g_KM);
    cudaGetSymbolAddress((void**)&MhP,  g_Mh);
    cudaGetSymbolAddress((void**)&kbP,  g_kb);
    cudaGetSymbolAddress((void**)&yP,   g_y);
    cudaGetSymbolAddress((void**)&x1P,  g_x1);

    constexpr int GS128 = 3 * (128 + 128) * 64 * 2;   // 98304 B
    constexpr int GS64  = 3 * (128 + 64) * 64 * 2;    // 73728 B
    cudaFuncSetAttribute(gemm_h<128, 1>, cudaFuncAttributeMaxDynamicSharedMemorySize, GS128);
    cudaFuncSetAttribute(gemm_h<128, 2>, cudaFuncAttributeMaxDynamicSharedMemorySize, GS128);
    cudaFuncSetAttribute(gemm_h<64, 0>,  cudaFuncAttributeMaxDynamicSharedMemorySize, GS64);
    cudaFuncSetAttribute(attn_tc_kernel, cudaFuncAttributeMaxDynamicSharedMemorySize, ATT_SMEM);
    cudaFuncSetAttribute(rbf_final_kernel, cudaFuncAttributeMaxDynamicSharedMemorySize, RBF_SMEM_BYTES);

    // 0) weight conversion (fp16) + scaled M
    half_copy4_kernel<<<512, 256>>>((const float4*)qkvw, qwP, 3 * Cdim * Cdim / 4);
    half_copy4_kernel<<<256, 256>>>((const float4*)projw, pwP, Cdim * Cdim / 4);
    scale_m_kernel<<<(HDn * HDn + 255) / 256, 256>>>(Mmat, scale, MhP);
    // 1) LN1 (half out)
    ln1_kernel<<<Sn / 8, 256>>>(x, n1w, n1b, hP);
    // 2) qkv GEMM fused with gather -> Qg/Kg/Vg (half)
    gemm_h<128, 1><<<dim3(3 * Cdim / 128, Sn / 128), 256, GS128>>>(
        hP, qwP, QgP, KgP, VgP, Sn, 3 * Cdim, Cdim, nullptr, nullptr);
    // 3) KM2 = K @ (2*scale*M)^T (half out)
    gemm_h<64, 0><<<dim3(HDn / 64, BHn * Nn / 128), 256, GS64>>>(
        KgP, MhP, KMP, nullptr, nullptr, BHn * Nn, HDn, HDn, nullptr, nullptr);
    // 4) per-key bias kb = -0.5 * K.KM2
    kbias_kernel<<<(BHn * Nn) * 32 / 256, 256>>>(KgP, KMP, kbP);
    // 5) fp16 flash attention (q . KM2 + kb) -> y (half)
    attn_tc_kernel<<<dim3(BHn, Nn / 128), 256, ATT_SMEM>>>(QgP, KMP, VgP, kbP, yP);
    // 6) x1 = x + y @ proj_w^T + proj_b (fp32 out)
    gemm_h<128, 2><<<dim3(Cdim / 128, Sn / 128), 256, GS128>>>(
        yP, pwP, x1P, nullptr, nullptr, Sn, Cdim, Cdim, projb, x);
    // 7) fused LN2 + RBF + fc + residual -> out
    rbf_final_kernel<<<Sn / 64, 256, RBF_SMEM_BYTES>>>(x1P, n2w, n2b, cent, beta, fcw, out);
}

// round 12
// speedup vs baseline: 12.9548x; 1.0600x over previous
#include <cuda_runtime.h>
#include <cuda_fp16.h>
#include <cstdint>

// ---------------- problem constants ----------------
constexpr int Cdim = 768;
constexpr int Bn   = 8;
constexpr int Nn   = 1024;
constexpr int HDn  = 192;            // head dim
constexpr int Sn   = Bn * Nn;        // 8192 rows
constexpr int BHn  = Bn * 4;         // 32
constexpr int CEN  = 20;
constexpr float EPSv = 1e-5f;

// ---------------- scratch (device globals; no allocation allowed) ----------------
__device__ __half g_h     [Sn * Cdim];
__device__ __half g_qkvwr [3 * Cdim * Cdim];
__device__ __half g_projwr[Cdim * Cdim];
__device__ __half g_Qg  [BHn * Nn * HDn];
__device__ __half g_Kg  [BHn * Nn * HDn];
__device__ __half g_Vg  [BHn * Nn * HDn];
__device__ __half g_KM  [BHn * Nn * HDn];   // KM2 = K @ (2*scale*M)^T
__device__ __half g_Mh  [HDn * HDn];        // 2*scale*M (half)
__device__ float  g_kbp [3 * BHn * Nn];     // kbias partials (one per N-block)
__device__ float  g_kb  [BHn * Nn];
__device__ __half g_y   [Sn * Cdim];
__device__ float  g_x1  [Sn * Cdim];

// ---------------- helpers ----------------
__device__ __forceinline__ float warpsum32(float v) {
#pragma unroll
    for (int o = 16; o >= 1; o >>= 1) v += __shfl_xor_sync(0xffffffffu, v, o);
    return v;
}
__device__ __forceinline__ uint32_t h2u(__half2 h) {
    return *reinterpret_cast<uint32_t*>(&h);
}
__device__ __forceinline__ void mma16h(float* c,
    uint32_t a0, uint32_t a1, uint32_t a2, uint32_t a3, uint32_t b0, uint32_t b1)
{
    asm volatile("mma.sync.aligned.m16n8k16.row.col.f32.f16.f16.f32 "
        "{%0,%1,%2,%3}, {%4,%5,%6,%7}, {%8,%9}, {%0,%1,%2,%3};"
        : "+f"(c[0]), "+f"(c[1]), "+f"(c[2]), "+f"(c[3])
        : "r"(a0), "r"(a1), "r"(a2), "r"(a3), "r"(b0), "r"(b1));
}
__device__ __forceinline__ void ldsm4(uint32_t& r0, uint32_t& r1, uint32_t& r2, uint32_t& r3,
                                      uint32_t addr)
{
    asm volatile("ldmatrix.sync.aligned.m8n8.x4.shared.b16 {%0,%1,%2,%3}, [%4];"
        : "=r"(r0), "=r"(r1), "=r"(r2), "=r"(r3) : "r"(addr));
}
__device__ __forceinline__ void ldsm4t(uint32_t& r0, uint32_t& r1, uint32_t& r2, uint32_t& r3,
                                       uint32_t addr)
{
    asm volatile("ldmatrix.sync.aligned.m8n8.x4.trans.shared.b16 {%0,%1,%2,%3}, [%4];"
        : "=r"(r0), "=r"(r1), "=r"(r2), "=r"(r3) : "r"(addr));
}
__device__ __forceinline__ void cp_async16(void* smem, const void* gmem) {
    uint32_t s = (uint32_t)__cvta_generic_to_shared(smem);
    asm volatile("cp.async.cg.shared.global [%0], [%1], 16;\n" :: "r"(s), "l"(gmem));
}
__device__ __forceinline__ void cp_commit() {
    asm volatile("cp.async.commit_group;\n");
}
template<int N>
__device__ __forceinline__ void cp_wait() {
    asm volatile("cp.async.wait_group %0;\n" :: "n"(N));
}

// ---------------- LayerNorm (LN1): warp per row, half output ----------------
__global__ __launch_bounds__(256) void ln1_kernel(
    const float* __restrict__ x, const float* __restrict__ w,
    const float* __restrict__ b, __half* __restrict__ out)
{
    const int row  = blockIdx.x * 8 + (threadIdx.x >> 5);
    const int lane = threadIdx.x & 31;
    const float4* xr = (const float4*)(x + (size_t)row * Cdim);
    float4 v[6];
    float s = 0.f, s2 = 0.f;
#pragma unroll
    for (int i = 0; i < 6; i++) {
        v[i] = xr[lane + i * 32];
        s  += v[i].x + v[i].y + v[i].z + v[i].w;
        s2 += v[i].x * v[i].x + v[i].y * v[i].y + v[i].z * v[i].z + v[i].w * v[i].w;
    }
    s = warpsum32(s); s2 = warpsum32(s2);
    const float mu  = s * (1.0f / Cdim);
    const float var = s2 * (1.0f / Cdim) - mu * mu;
    const float rs  = rsqrtf(var + EPSv);
    const float4* w4 = (const float4*)w;
    const float4* b4 = (const float4*)b;
#pragma unroll
    for (int i = 0; i < 6; i++) {
        const int idx = lane + i * 32;
        const float4 wv = w4[idx], bv = b4[idx];
        __half* orow = out + (size_t)row * Cdim + 4 * idx;
        *(__half2*)&orow[0] = __floats2half2_rn((v[i].x - mu) * rs * wv.x + bv.x,
                                                (v[i].y - mu) * rs * wv.y + bv.y);
        *(__half2*)&orow[2] = __floats2half2_rn((v[i].z - mu) * rs * wv.z + bv.z,
                                                (v[i].w - mu) * rs * wv.w + bv.w);
    }
}

// ---------------- f32 -> f16 copy (vectorized) ----------------
__global__ __launch_bounds__(256) void half_copy4_kernel(
    const float4* __restrict__ src, __half* __restrict__ dst, int n4)
{
    for (int i = blockIdx.x * 256 + threadIdx.x; i < n4; i += gridDim.x * 256) {
        const float4 v = src[i];
        *(__half2*)&dst[4 * i]     = __floats2half2_rn(v.x, v.y);
        *(__half2*)&dst[4 * i + 2] = __floats2half2_rn(v.z, v.w);
    }
}

// ---------------- Mh = 2*scale*M (half, same layout) ----------------
__global__ __launch_bounds__(256) void scale_m_kernel(
    const float* __restrict__ M, const float* __restrict__ scale_p,
    __half* __restrict__ Mh)
{
    const int i = blockIdx.x * 256 + threadIdx.x;
    if (i >= HDn * HDn) return;
    Mh[i] = __float2half(2.0f * scale_p[0] * M[i]);
}

// ---------------- 3-stage pipelined fp16 NT GEMM: C = A[M,K] * B[N,K]^T ----------------
// MODE 0: half store. MODE 1: qkv scatter -> Q/K/V half [BH][N][HD]. MODE 2: fp32 +bias+resid.
// MODE 3: half store + kbias partials kbp[bx*Md + row] = sum_n A[row,n]*acc[row,n].
template<int BN, int MODE>
__global__ __launch_bounds__(256) void gemm_h(
    const __half* __restrict__ A, const __half* __restrict__ B, void* __restrict__ Cv,
    __half* __restrict__ C2, __half* __restrict__ C3,
    int Md, int Nd, int Kd,
    const float* __restrict__ bias, const float* __restrict__ resid,
    float* __restrict__ kbp)
{
    constexpr int BM = 128, BK = 64;
    constexpr int WM = (BN == 128) ? 2 : 4;
    constexpr int WN = 8 / WM;
    constexpr int WTM = BM / WM, WTN = BN / WN;
    constexpr int MT = WTM / 16, NT = WTN / 8;
    constexpr int ASTG = BM * BK;
    constexpr int BSTG = BN * BK;

    extern __shared__ __align__(16) __half smh[];
    __half* As = smh;                 // 3 stages
    __half* Bs = smh + 3 * ASTG;      // 3 stages

    const int t = threadIdx.x;
    const int wid = t >> 5, lane = t & 31;
    const int wm = wid % WM, wn = wid / WM;
    const int lr4 = lane >> 2, lc4 = lane & 3;
    const int g8 = lane >> 3, l8 = lane & 7;
    const int m0 = blockIdx.y * BM, n0 = blockIdx.x * BN;

    const __half* Ab = A + (size_t)m0 * Kd;
    const __half* Bb = B + (size_t)n0 * Kd;

    auto prefetch = [&](int kt, int st) {
        const __half* Ag = Ab + kt * BK;
        const __half* Bg = Bb + kt * BK;
#pragma unroll
        for (int i = 0; i < BM / 32; i++) {
            const int ch = t + i * 256;
            const int r = ch >> 3, c = ch & 7;
            cp_async16(&As[st * ASTG + (r * 8 + (c ^ (r & 7))) * 8], Ag + (size_t)r * Kd + c * 8);
        }
#pragma unroll
        for (int i = 0; i < BN / 32; i++) {
            const int ch = t + i * 256;
            const int r = ch >> 3, c = ch & 7;
            cp_async16(&Bs[st * BSTG + (r * 8 + (c ^ (r & 7))) * 8], Bg + (size_t)r * Kd + c * 8);
        }
    };

    float acc[MT][NT][4];
#pragma unroll
    for (int i = 0; i < MT; i++)
#pragma unroll
        for (int j = 0; j < NT; j++)
#pragma unroll
            for (int q = 0; q < 4; q++) acc[i][j][q] = 0.f;

    const int nK = Kd / BK;
    prefetch(0, 0); cp_commit();
    prefetch(1, 1); cp_commit();

    for (int kt = 0; kt < nK; kt++) {
        cp_wait<1>();
        __syncthreads();
        if (kt + 2 < nK) prefetch(kt + 2, (kt + 2) % 3);
        cp_commit();

        const int st = kt % 3;
        const uint32_t Au = (uint32_t)__cvta_generic_to_shared(As + st * ASTG);
        const uint32_t Bu = (uint32_t)__cvta_generic_to_shared(Bs + st * BSTG);

#pragma unroll
        for (int k16 = 0; k16 < BK / 16; k16++) {
            uint32_t bf[NT][2];
#pragma unroll
            for (int p = 0; p < NT / 2; p++) {
                const int row = wn * WTN + p * 16 + (g8 >> 1) * 8 + l8;
                const int ch  = (2 * k16 + (g8 & 1)) ^ l8;
                ldsm4(bf[2 * p][0], bf[2 * p][1], bf[2 * p + 1][0], bf[2 * p + 1][1],
                      Bu + (row * 8 + ch) * 16);
            }
#pragma unroll
            for (int mt = 0; mt < MT; mt++) {
                const int rowA = wm * WTM + mt * 16 + (g8 & 1) * 8 + l8;
                const int chA  = (2 * k16 + (g8 >> 1)) ^ l8;
                uint32_t a0, a1, a2, a3;
                ldsm4(a0, a1, a2, a3, Au + (rowA * 8 + chA) * 16);
#pragma unroll
                for (int nt = 0; nt < NT; nt++)
                    mma16h(acc[mt][nt], a0, a1, a2, a3, bf[nt][0], bf[nt][1]);
            }
        }
    }

    float part[MT][2];
    if (MODE == 3) {
#pragma unroll
        for (int mt = 0; mt < MT; mt++) { part[mt][0] = 0.f; part[mt][1] = 0.f; }
    }

#pragma unroll
    for (int mt = 0; mt < MT; mt++) {
        const int mbase = m0 + wm * WTM + mt * 16 + lr4;
#pragma unroll
        for (int nt = 0; nt < NT; nt++) {
            const int n = n0 + wn * WTN + nt * 8 + 2 * lc4;
            if (MODE == 0 || MODE == 3) {
                __half* C = (__half*)Cv;
                *(__half2*)&C[(size_t)mbase * Nd + n] =
                    __floats2half2_rn(acc[mt][nt][0], acc[mt][nt][1]);
                *(__half2*)&C[(size_t)(mbase + 8) * Nd + n] =
                    __floats2half2_rn(acc[mt][nt][2], acc[mt][nt][3]);
                if (MODE == 3) {
                    const float2 k0 = __half22float2(*(const __half2*)&A[(size_t)mbase * Kd + n]);
                    const float2 k1 = __half22float2(*(const __half2*)&A[(size_t)(mbase + 8) * Kd + n]);
                    part[mt][0] += k0.x * acc[mt][nt][0] + k0.y * acc[mt][nt][1];
                    part[mt][1] += k1.x * acc[mt][nt][2] + k1.y * acc[mt][nt][3];
                }
            } else if (MODE == 1) {
                const int which = n / Cdim;
                const int rem = n % Cdim;
                const int h = rem / HDn, d = rem % HDn;
                __half* dst = (which == 0) ? (__half*)Cv : (which == 1) ? C2 : C3;
#pragma unroll
                for (int rr = 0; rr < 2; rr++) {
                    const int m = mbase + rr * 8;
                    const int b = m >> 10, nr = m & 1023;
                    const size_t di = ((size_t)((b << 2) + h) * Nn + nr) * HDn + d;
                    *(__half2*)&dst[di] =
                        __floats2half2_rn(acc[mt][nt][rr * 2], acc[mt][nt][rr * 2 + 1]);
                }
            } else {
                float* C = (float*)Cv;
                const float b0 = bias[n], b1 = bias[n + 1];
                const size_t i0 = (size_t)mbase * Nd + n;
                const size_t i1 = (size_t)(mbase + 8) * Nd + n;
                *(float2*)&C[i0] = make_float2(acc[mt][nt][0] + b0 + resid[i0],
                                               acc[mt][nt][1] + b1 + resid[i0 + 1]);
                *(float2*)&C[i1] = make_float2(acc[mt][nt][2] + b0 + resid[i1],
                                               acc[mt][nt][3] + b1 + resid[i1 + 1]);
            }
        }
    }

    if (MODE == 3) {
        // quad-reduce (sum over lc4), then two-phase deterministic cross-warp reduce
        float pr[MT][2];
#pragma unroll
        for (int mt = 0; mt < MT; mt++)
#pragma unroll
            for (int sr = 0; sr < 2; sr++) {
                float p = part[mt][sr];
                p += __shfl_xor_sync(0xffffffffu, p, 1);
                p += __shfl_xor_sync(0xffffffffu, p, 2);
                pr[mt][sr] = p;
            }
        __syncthreads();                       // smem stages no longer needed
        float* sred = (float*)smh;             // [BM]
        if (wn == 0 && lc4 == 0) {
#pragma unroll
            for (int mt = 0; mt < MT; mt++)
#pragma unroll
                for (int sr = 0; sr < 2; sr++)
                    sred[wm * WTM + mt * 16 + sr * 8 + lr4] = pr[mt][sr];
        }
        __syncthreads();
        if (wn == 1 && lc4 == 0) {
#pragma unroll
            for (int mt = 0; mt < MT; mt++)
#pragma unroll
                for (int sr = 0; sr < 2; sr++) {
                    const int rl = wm * WTM + mt * 16 + sr * 8 + lr4;
                    kbp[(size_t)blockIdx.x * Md + m0 + rl] = sred[rl] + pr[mt][sr];
                }
        }
    }
}

// ---------------- kb[r] = -0.5 * (kbp[0][r] + kbp[1][r] + kbp[2][r]) ----------------
__global__ __launch_bounds__(256) void kb_reduce_kernel(
    const float* __restrict__ kbp, float* __restrict__ kb)
{
    const int r = blockIdx.x * 256 + threadIdx.x;
    if (r >= BHn * Nn) return;
    kb[r] = -0.5f * (kbp[r] + kbp[BHn * Nn + r] + kbp[2 * BHn * Nn + r]);
}

// ---------------- fp16 flash attention (3-stage): S = q . KM2 + kb ----------------
constexpr int KSs = 200;        // K/V smem stride (halfs)
constexpr int KVST = 64 * KSs;  // halfs per stage
constexpr int ATT_SMEM = 3 * 2 * KVST * 2 + 3 * 64 * 4;   // 154368 B

__global__ __launch_bounds__(256, 1) void attn_tc_kernel(
    const __half* __restrict__ Qg, const __half* __restrict__ KM,
    const __half* __restrict__ Vg, const float* __restrict__ kbias,
    __half* __restrict__ y)
{
    extern __shared__ __align__(16) __half smha[];
    __half* ks_base = smha;                       // 3 stages (KM2 tiles)
    __half* vs_base = smha + 3 * KVST;            // 3 stages
    float* kbt_base = (float*)(smha + 6 * KVST);  // 3 x 64

    const int bh = blockIdx.x, qt = blockIdx.y;   // qt: 128-row tile
    const int b = bh >> 2, h = bh & 3;
    const int t = threadIdx.x;
    const int wid = t >> 5, lane = t & 31;
    const int lr4 = lane >> 2, lc4 = lane & 3;
    const int g8 = lane >> 3, l8 = lane & 7;
    const int r0 = wid * 16;

    auto prefetch = [&](int kt, int st) {
        const __half* kg = KM + ((size_t)bh * Nn + kt * 64) * HDn;
        const __half* vg = Vg + ((size_t)bh * Nn + kt * 64) * HDn;
        __half* ksb = ks_base + st * KVST;
        __half* vsb = vs_base + st * KVST;
#pragma unroll
        for (int i = 0; i < 6; i++) {
            const int ch = t + i * 256;
            const int r = ch / 24, c = ch % 24;
            cp_async16(&ksb[r * KSs + c * 8], kg + r * HDn + c * 8);
            cp_async16(&vsb[r * KSs + c * 8], vg + r * HDn + c * 8);
        }
        if (t < 16) cp_async16(&kbt_base[st * 64 + t * 4],
                               kbias + (size_t)bh * Nn + kt * 64 + t * 4);
    };

    prefetch(0, 0); cp_commit();
    prefetch(1, 1); cp_commit();

    uint32_t qa[12][4];
    {
        const __half* qb = Qg + ((size_t)bh * Nn + qt * 128) * HDn;
#pragma unroll
        for (int k16 = 0; k16 < 12; k16++) {
            const int kk = k16 * 16;
            qa[k16][0] = *(const uint32_t*)&qb[(r0 + lr4)     * HDn + kk + 2 * lc4];
            qa[k16][1] = *(const uint32_t*)&qb[(r0 + lr4 + 8) * HDn + kk + 2 * lc4];
            qa[k16][2] = *(const uint32_t*)&qb[(r0 + lr4)     * HDn + kk + 8 + 2 * lc4];
            qa[k16][3] = *(const uint32_t*)&qb[(r0 + lr4 + 8) * HDn + kk + 8 + 2 * lc4];
        }
    }

    float O[24][4];
#pragma unroll
    for (int nt = 0; nt < 24; nt++)
#pragma unroll
        for (int q = 0; q < 4; q++) O[nt][q] = 0.f;
    float mr0 = -1e30f, mr1 = -1e30f, l0 = 0.f, l1 = 0.f;

    for (int kt = 0; kt < Nn / 64; kt++) {
        cp_wait<1>();
        __syncthreads();
        if (kt + 2 < Nn / 64) prefetch(kt + 2, (kt + 2) % 3);
        cp_commit();

        const int st = kt % 3;
        const uint32_t ks_u = (uint32_t)__cvta_generic_to_shared(ks_base + st * KVST);
        const uint32_t vs_u = (uint32_t)__cvta_generic_to_shared(vs_base + st * KVST);
        const float* kbt = kbt_base + st * 64;

        float s[8][4];
#pragma unroll
        for (int nt = 0; nt < 8; nt++)
#pragma unroll
            for (int q = 0; q < 4; q++) s[nt][q] = 0.f;
#pragma unroll
        for (int k16 = 0; k16 < 12; k16++) {
            const int kk = k16 * 16;
            uint32_t bf[8][2];
#pragma unroll
            for (int p = 0; p < 4; p++) {
                const int row = p * 16 + (g8 >> 1) * 8 + l8;
                const int col = kk + (g8 & 1) * 8;
                ldsm4(bf[2 * p][0], bf[2 * p][1], bf[2 * p + 1][0], bf[2 * p + 1][1],
                      ks_u + (row * KSs + col) * 2);
            }
#pragma unroll
            for (int nt = 0; nt < 8; nt++)
                mma16h(s[nt], qa[k16][0], qa[k16][1], qa[k16][2], qa[k16][3],
                       bf[nt][0], bf[nt][1]);
        }

        float pm0 = -1e30f, pm1 = -1e30f;
#pragma unroll
        for (int nt = 0; nt < 8; nt++) {
            const int col = nt * 8 + 2 * lc4;
            const float kb0 = kbt[col], kb1 = kbt[col + 1];
            s[nt][0] += kb0; s[nt][1] += kb1;
            s[nt][2] += kb0; s[nt][3] += kb1;
            pm0 = fmaxf(pm0, fmaxf(s[nt][0], s[nt][1]));
            pm1 = fmaxf(pm1, fmaxf(s[nt][2], s[nt][3]));
        }
        pm0 = fmaxf(pm0, __shfl_xor_sync(0xffffffffu, pm0, 1));
        pm0 = fmaxf(pm0, __shfl_xor_sync(0xffffffffu, pm0, 2));
        pm1 = fmaxf(pm1, __shfl_xor_sync(0xffffffffu, pm1, 1));
        pm1 = fmaxf(pm1, __shfl_xor_sync(0xffffffffu, pm1, 2));
        const float mn0 = fmaxf(mr0, pm0), mn1 = fmaxf(mr1, pm1);
        const float cor0 = __expf(mr0 - mn0), cor1 = __expf(mr1 - mn1);
        mr0 = mn0; mr1 = mn1;

        uint32_t pa[4][4];
        float q0 = 0.f, q1 = 0.f;
#pragma unroll
        for (int j = 0; j < 4; j++) {
#pragma unroll
            for (int hh = 0; hh < 2; hh++) {
                const int nt = 2 * j + hh;
                const float e0 = __expf(s[nt][0] - mn0);
                const float e1 = __expf(s[nt][1] - mn0);
                const float e2 = __expf(s[nt][2] - mn1);
                const float e3 = __expf(s[nt][3] - mn1);
                q0 += e0 + e1; q1 += e2 + e3;
                pa[j][2 * hh]     = h2u(__floats2half2_rn(e0, e1));
                pa[j][2 * hh + 1] = h2u(__floats2half2_rn(e2, e3));
            }
        }
        q0 += __shfl_xor_sync(0xffffffffu, q0, 1);
        q0 += __shfl_xor_sync(0xffffffffu, q0, 2);
        q1 += __shfl_xor_sync(0xffffffffu, q1, 1);
        q1 += __shfl_xor_sync(0xffffffffu, q1, 2);
        l0 = l0 * cor0 + q0;
        l1 = l1 * cor1 + q1;
#pragma unroll
        for (int nt = 0; nt < 24; nt++) {
            O[nt][0] *= cor0; O[nt][1] *= cor0;
            O[nt][2] *= cor1; O[nt][3] *= cor1;
        }

#pragma unroll
        for (int j = 0; j < 4; j++) {
            const int kk = j * 16;
#pragma unroll
            for (int p = 0; p < 12; p++) {
                const int rowv = kk + (g8 & 1) * 8 + l8;
                const int colv = p * 16 + (g8 >> 1) * 8;
                uint32_t b0A, b1A, b0B, b1B;
                ldsm4t(b0A, b1A, b0B, b1B, vs_u + (rowv * KSs + colv) * 2);
                mma16h(O[2 * p],     pa[j][0], pa[j][1], pa[j][2], pa[j][3], b0A, b1A);
                mma16h(O[2 * p + 1], pa[j][0], pa[j][1], pa[j][2], pa[j][3], b0B, b1B);
            }
        }
    }

    const float i0v = 1.0f / l0, i1v = 1.0f / l1;
    const int nrow0 = qt * 128 + r0 + lr4;
    __half* y0 = y + (size_t)(b * Nn + nrow0) * Cdim + h * HDn;
    __half* y1 = y0 + 8 * Cdim;
#pragma unroll
    for (int nt = 0; nt < 24; nt++) {
        const int col = nt * 8 + 2 * lc4;
        *(__half2*)&y0[col] = __floats2half2_rn(O[nt][0] * i0v, O[nt][1] * i0v);
        *(__half2*)&y1[col] = __floats2half2_rn(O[nt][2] * i1v, O[nt][3] * i1v);
    }
}

// ---------------- fused LN2 + RBF + fc + residual -> out (2 rows / warp-iter) --------
constexpr int RBF_SMEM_BYTES = (2 * CEN * Cdim + 2 * CEN) * 4;  // 123040 B

__global__ __launch_bounds__(256) void rbf_final_kernel(
    const float* __restrict__ x1, const float* __restrict__ n2w,
    const float* __restrict__ n2b, const float* __restrict__ centers,
    const float* __restrict__ beta, const float* __restrict__ fcw,
    float* __restrict__ out)
{
    extern __shared__ __align__(16) float rsm[];
    float* cs   = rsm;                       // [CEN][Cdim] centers
    float* fwT  = rsm + CEN * Cdim;          // [CEN][Cdim] fc_w transposed
    float* cn   = fwT + CEN * Cdim;          // [CEN]
    float* bt   = cn + CEN;                  // [CEN]
    const int t = threadIdx.x;
    for (int i = t; i < CEN * Cdim; i += 256) {
        cs[i] = centers[i];
        const int j = i / Cdim, c = i % Cdim;
        fwT[i] = fcw[c * CEN + j];
    }
    __syncthreads();
    if (t < CEN) {
        float s = 0.f;
        for (int k = 0; k < Cdim; k++) s += cs[t * Cdim + k] * cs[t * Cdim + k];
        cn[t] = s;
        bt[t] = beta[t];
    }
    __syncthreads();
    const int wid = t >> 5, lane = t & 31;
    const float4* w4 = (const float4*)n2w;
    const float4* b4 = (const float4*)n2b;

    for (int rr = 0; rr < 4; rr++) {
        const int row0 = blockIdx.x * 64 + wid * 8 + rr * 2;
        const float4* xr0 = (const float4*)(x1 + (size_t)row0 * Cdim);
        const float4* xr1 = (const float4*)(x1 + (size_t)(row0 + 1) * Cdim);

        float hv0[24], hv1[24];
        float a0, a1;
        {   // row0 LN
            float4 v[6];
            float s = 0.f, s2 = 0.f;
#pragma unroll
            for (int i = 0; i < 6; i++) {
                v[i] = xr0[lane + i * 32];
                s  += v[i].x + v[i].y + v[i].z + v[i].w;
                s2 += v[i].x * v[i].x + v[i].y * v[i].y + v[i].z * v[i].z + v[i].w * v[i].w;
            }
            s = warpsum32(s); s2 = warpsum32(s2);
            const float mu = s * (1.0f / Cdim);
            const float rs = rsqrtf(s2 * (1.0f / Cdim) - mu * mu + EPSv);
            float a = 0.f;
#pragma unroll
            for (int i = 0; i < 6; i++) {
                const int idx = lane + i * 32;
                const float4 wv = w4[idx], bv = b4[idx];
                hv0[4*i+0] = (v[i].x - mu) * rs * wv.x + bv.x;
                hv0[4*i+1] = (v[i].y - mu) * rs * wv.y + bv.y;
                hv0[4*i+2] = (v[i].z - mu) * rs * wv.z + bv.z;
                hv0[4*i+3] = (v[i].w - mu) * rs * wv.w + bv.w;
                a += hv0[4*i]*hv0[4*i] + hv0[4*i+1]*hv0[4*i+1]
                   + hv0[4*i+2]*hv0[4*i+2] + hv0[4*i+3]*hv0[4*i+3];
            }
            a0 = warpsum32(a);
        }
        {   // row1 LN
            float4 v[6];
            float s = 0.f, s2 = 0.f;
#pragma unroll
            for (int i = 0; i < 6; i++) {
                v[i] = xr1[lane + i * 32];
                s  += v[i].x + v[i].y + v[i].z + v[i].w;
                s2 += v[i].x * v[i].x + v[i].y * v[i].y + v[i].z * v[i].z + v[i].w * v[i].w;
            }
            s = warpsum32(s); s2 = warpsum32(s2);
            const float mu = s * (1.0f / Cdim);
            const float rs = rsqrtf(s2 * (1.0f / Cdim) - mu * mu + EPSv);
            float a = 0.f;
#pragma unroll
            for (int i = 0; i < 6; i++) {
                const int idx = lane + i * 32;
                const float4 wv = w4[idx], bv = b4[idx];
                hv1[4*i+0] = (v[i].x - mu) * rs * wv.x + bv.x;
                hv1[4*i+1] = (v[i].y - mu) * rs * wv.y + bv.y;
                hv1[4*i+2] = (v[i].z - mu) * rs * wv.z + bv.z;
                hv1[4*i+3] = (v[i].w - mu) * rs * wv.w + bv.w;
                a += hv1[4*i]*hv1[4*i] + hv1[4*i+1]*hv1[4*i+1]
                   + hv1[4*i+2]*hv1[4*i+2] + hv1[4*i+3]*hv1[4*i+3];
            }
            a1 = warpsum32(a);
        }

        // rbf values for both rows, sharing each center read
        float rj0[CEN], rj1[CEN];
#pragma unroll
        for (int j = 0; j < CEN; j++) {
            const float4* cj = (const float4*)(cs + j * Cdim);
            float d0 = 0.f, d1 = 0.f;
#pragma unroll
            for (int i = 0; i < 6; i++) {
                const float4 cv = cj[lane + i * 32];
                d0 += hv0[4*i]*cv.x + hv0[4*i+1]*cv.y + hv0[4*i+2]*cv.z + hv0[4*i+3]*cv.w;
                d1 += hv1[4*i]*cv.x + hv1[4*i+1]*cv.y + hv1[4*i+2]*cv.z + hv1[4*i+3]*cv.w;
            }
            d0 = warpsum32(d0); d1 = warpsum32(d1);
            rj0[j] = __expf(-bt[j] * (a0 - 2.0f * d0 + cn[j]));
            rj1[j] = __expf(-bt[j] * (a1 - 2.0f * d1 + cn[j]));
        }

        // out = x1 + rbf @ fc_w^T  (shared fwT reads for both rows)
        float4* o0row = (float4*)(out + (size_t)row0 * Cdim);
        float4* o1row = (float4*)(out + (size_t)(row0 + 1) * Cdim);
#pragma unroll
        for (int i = 0; i < 6; i++) {
            const int idx = lane + i * 32;
            float4 o0 = xr0[idx];
            float4 o1 = xr1[idx];
#pragma unroll
            for (int j = 0; j < CEN; j++) {
                const float4 fv = *(const float4*)&fwT[j * Cdim + 4 * idx];
                o0.x += rj0[j] * fv.x; o0.y += rj0[j] * fv.y;
                o0.z += rj0[j] * fv.z; o0.w += rj0[j] * fv.w;
                o1.x += rj1[j] * fv.x; o1.y += rj1[j] * fv.y;
                o1.z += rj1[j] * fv.z; o1.w += rj1[j] * fv.w;
            }
            o0row[idx] = o0;
            o1row[idx] = o1;
        }
    }
}

// ---------------- launcher ----------------
extern "C" void kernel_launch(void* const* d_in, const int* in_sizes, int n_in,
                              void* d_out, int out_size)
{
    (void)in_sizes; (void)n_in; (void)out_size;
    const float* x     = (const float*)d_in[0];
    const float* n1w   = (const float*)d_in[1];
    const float* n1b   = (const float*)d_in[2];
    const float* qkvw  = (const float*)d_in[3];
    const float* Mmat  = (const float*)d_in[4];
    const float* scale = (const float*)d_in[5];
    const float* projw = (const float*)d_in[6];
    const float* projb = (const float*)d_in[7];
    const float* n2w   = (const float*)d_in[8];
    const float* n2b   = (const float*)d_in[9];
    const float* cent  = (const float*)d_in[10];
    const float* beta  = (const float*)d_in[11];
    const float* fcw   = (const float*)d_in[12];
    float* out = (float*)d_out;

    __half *hP, *qwP, *pwP, *QgP, *KgP, *VgP, *KMP, *MhP, *yP;
    float *kbpP, *kbP, *x1P;
    cudaGetSymbolAddress((void**)&hP,   g_h);
    cudaGetSymbolAddress((void**)&qwP,  g_qkvwr);
    cudaGetSymbolAddress((void**)&pwP,  g_projwr);
    cudaGetSymbolAddress((void**)&QgP,  g_Qg);
    cudaGetSymbolAddress((void**)&KgP,  g_Kg);
    cudaGetSymbolAddress((void**)&VgP,  g_Vg);
    cudaGetSymbolAddress((void**)&KMP,  g_KM);
    cudaGetSymbolAddress((void**)&MhP,  g_Mh);
    cudaGetSymbolAddress((void**)&kbpP, g_kbp);
    cudaGetSymbolAddress((void**)&kbP,  g_kb);
    cudaGetSymbolAddress((void**)&yP,   g_y);
    cudaGetSymbolAddress((void**)&x1P,  g_x1);

    constexpr int GS128 = 3 * (128 + 128) * 64 * 2;   // 98304 B
    constexpr int GS64  = 3 * (128 + 64) * 64 * 2;    // 73728 B
    cudaFuncSetAttribute(gemm_h<128, 1>, cudaFuncAttributeMaxDynamicSharedMemorySize, GS128);
    cudaFuncSetAttribute(gemm_h<128, 2>, cudaFuncAttributeMaxDynamicSharedMemorySize, GS128);
    cudaFuncSetAttribute(gemm_h<64, 3>,  cudaFuncAttributeMaxDynamicSharedMemorySize, GS64);
    cudaFuncSetAttribute(attn_tc_kernel, cudaFuncAttributeMaxDynamicSharedMemorySize, ATT_SMEM);
    cudaFuncSetAttribute(rbf_final_kernel, cudaFuncAttributeMaxDynamicSharedMemorySize, RBF_SMEM_BYTES);

    // streams/events for prep overlap (created once; reused across calls)
    static cudaStream_t sA = nullptr, sB = nullptr;
    static cudaEvent_t  eF = nullptr, eA = nullptr, eB = nullptr;
    if (!sA) {
        cudaStreamCreateWithFlags(&sA, cudaStreamNonBlocking);
        cudaStreamCreateWithFlags(&sB, cudaStreamNonBlocking);
        cudaEventCreateWithFlags(&eF, cudaEventDisableTiming);
        cudaEventCreateWithFlags(&eA, cudaEventDisableTiming);
        cudaEventCreateWithFlags(&eB, cudaEventDisableTiming);
    }

    // fork prep work onto side streams
    cudaEventRecord(eF, 0);
    cudaStreamWaitEvent(sA, eF, 0);
    cudaStreamWaitEvent(sB, eF, 0);
    half_copy4_kernel<<<512, 256, 0, sA>>>((const float4*)qkvw, qwP, 3 * Cdim * Cdim / 4);
    cudaEventRecord(eA, sA);
    half_copy4_kernel<<<256, 256, 0, sB>>>((const float4*)projw, pwP, Cdim * Cdim / 4);
    scale_m_kernel<<<(HDn * HDn + 255) / 256, 256, 0, sB>>>(Mmat, scale, MhP);
    cudaEventRecord(eB, sB);

    // 1) LN1 (half out) — overlaps the weight conversions
    ln1_kernel<<<Sn / 8, 256>>>(x, n1w, n1b, hP);
    // join qkv weights
    cudaStreamWaitEvent(0, eA, 0);
    // 2) qkv GEMM fused with gather -> Qg/Kg/Vg (half)
    gemm_h<128, 1><<<dim3(3 * Cdim / 128, Sn / 128), 256, GS128>>>(
        hP, qwP, QgP, KgP, VgP, Sn, 3 * Cdim, Cdim, nullptr, nullptr, nullptr);
    // join Mh (+proj weights, conservative)
    cudaStreamWaitEvent(0, eB, 0);
    // 3) KM2 = K @ (2*scale*M)^T with fused kbias partials
    gemm_h<64, 3><<<dim3(HDn / 64, BHn * Nn / 128), 256, GS64>>>(
        KgP, MhP, KMP, nullptr, nullptr, BHn * Nn, HDn, HDn, nullptr, nullptr, kbpP);
    // 4) kb = -0.5 * sum(partials)
    kb_reduce_kernel<<<(BHn * Nn + 255) / 256, 256>>>(kbpP, kbP);
    // 5) fp16 flash attention (q . KM2 + kb) -> y (half)
    attn_tc_kernel<<<dim3(BHn, Nn / 128), 256, ATT_SMEM>>>(QgP, KMP, VgP, kbP, yP);
    // 6) x1 = x + y @ proj_w^T + proj_b (fp32 out)
    gemm_h<128, 2><<<dim3(Cdim / 128, Sn / 128), 256, GS128>>>(
        yP, pwP, x1P, nullptr, nullptr, Sn, Cdim, Cdim, projb, x, nullptr);
    // 7) fused LN2 + RBF + fc + residual -> out
    rbf_final_kernel<<<Sn / 64, 256, RBF_SMEM_BYTES>>>(x1P, n2w, n2b, cent, beta, fcw, out);
}